// round 1
// baseline (speedup 1.0000x reference)
#include <cuda_runtime.h>
#include <math.h>

// ---------------- problem constants ----------------
#define BB   16
#define TTRG 64
#define TT   64
#define SS   49
#define DD   512
#define DFF  2048
#define HH   8
// tokens
#define NTOK_X    (BB*TTRG)          // 1024
#define NTOK_VFT  (BB*TT*SS)         // 50176
#define NTOK_SOUT (BB*TT*TTRG)       // 65536

// ---------------- scratch (device globals, no allocation) ----------------
__device__ float g_cur [NTOK_X*DD];
__device__ float g_ln  [NTOK_X*DD];
__device__ float g_q   [NTOK_X*DD];
__device__ float g_ks  [2048*DD];
__device__ float g_vs  [2048*DD];
__device__ float g_attn[NTOK_X*DD];
__device__ float g_ts  [NTOK_X*DD];
__device__ float g_st  [NTOK_X*DD];
__device__ float g_ffh [NTOK_X*DFF];
__device__ float g_big0[NTOK_SOUT*DD];
__device__ float g_big1[NTOK_SOUT*DD];
__device__ float g_big2[NTOK_SOUT*DD];
__device__ float g_big3[NTOK_SOUT*DD];
__device__ int   g_map_perm[NTOK_VFT];
__device__ int   g_map_pt  [NTOK_VFT];
__device__ int   g_map_ps  [NTOK_SOUT];
__device__ int   g_res_t   [NTOK_VFT];
__device__ int   g_res_s   [NTOK_SOUT];

// ---------------- map builders ----------------
// m = (a*Bd + b)*Cd + c  ->  src = (a*Cd + c)*Bd + b
__global__ void build_swap(int* map, int A, int Bd, int Cd) {
    int m = blockIdx.x*256 + threadIdx.x;
    int tot = A*Bd*Cd;
    if (m < tot) {
        int c = m % Cd;
        int b = (m / Cd) % Bd;
        int a = m / (Cd*Bd);
        map[m] = (a*Cd + c)*Bd + b;
    }
}
// map[m] = (m/p)*q + m%q
__global__ void build_res(int* map, int tot, int p, int q) {
    int m = blockIdx.x*256 + threadIdx.x;
    if (m < tot) map[m] = (m/p)*q + (m % q);
}

// ---------------- layernorm (D=512 fixed) ----------------
__global__ __launch_bounds__(128) void ln_kernel(const float* __restrict__ in,
                                                 const float* __restrict__ gamma,
                                                 const float* __restrict__ beta,
                                                 float* __restrict__ out) {
    int row = blockIdx.x;
    int tid = threadIdx.x;
    const float4* p = reinterpret_cast<const float4*>(in + (long)row*DD);
    float4 v = p[tid];
    float s = v.x + v.y + v.z + v.w;
    float q = v.x*v.x + v.y*v.y + v.z*v.z + v.w*v.w;
    #pragma unroll
    for (int o = 16; o; o >>= 1) {
        s += __shfl_xor_sync(0xffffffffu, s, o);
        q += __shfl_xor_sync(0xffffffffu, q, o);
    }
    __shared__ float ssum[4], ssq[4];
    int warp = tid >> 5, lane = tid & 31;
    if (lane == 0) { ssum[warp] = s; ssq[warp] = q; }
    __syncthreads();
    __shared__ float smean, sinv;
    if (tid == 0) {
        float S = ssum[0]+ssum[1]+ssum[2]+ssum[3];
        float Q = ssq[0]+ssq[1]+ssq[2]+ssq[3];
        float mean = S * (1.0f/DD);
        float var  = Q * (1.0f/DD) - mean*mean;
        float sd   = sqrtf(fmaxf(var, 0.0f));
        smean = mean;
        sinv  = 1.0f / (sd + 1e-6f);
    }
    __syncthreads();
    float mean = smean, inv = sinv;
    float4 gv = reinterpret_cast<const float4*>(gamma)[tid];
    float4 bv = reinterpret_cast<const float4*>(beta)[tid];
    float4 o;
    o.x = gv.x*(v.x-mean)*inv + bv.x;
    o.y = gv.y*(v.y-mean)*inv + bv.y;
    o.z = gv.z*(v.z-mean)*inv + bv.z;
    o.w = gv.w*(v.w-mean)*inv + bv.w;
    reinterpret_cast<float4*>(out + (long)row*DD)[tid] = o;
}

// ---------------- tiled SGEMM: C[M,N] = A[M,K] @ W[K,N] (+bias)(+relu)(+residual) ----------------
// amap: optional row gather for A. rmap: optional row map for residual R (stride N).
__global__ __launch_bounds__(256) void sgemm_kernel(
    const float* __restrict__ A, const int* __restrict__ amap,
    const float* __restrict__ W, const float* __restrict__ bias,
    const float* __restrict__ R, const int* __restrict__ rmap,
    float* __restrict__ C, int M, int N, int K, int relu)
{
    __shared__ float As[16][68];
    __shared__ float Ws[16][64];
    __shared__ int rowm[64];
    int tid = threadIdx.x;
    int m0 = blockIdx.y << 6, n0 = blockIdx.x << 6;
    if (tid < 64) rowm[tid] = amap ? amap[m0 + tid] : (m0 + tid);
    __syncthreads();
    int ty = tid >> 4, tx = tid & 15;
    float acc[16];
    #pragma unroll
    for (int u = 0; u < 16; u++) acc[u] = 0.0f;

    for (int k0 = 0; k0 < K; k0 += 16) {
        #pragma unroll
        for (int r = 0; r < 4; r++) {
            int idx = tid + (r << 8);
            int i  = idx >> 4, kk = idx & 15;
            As[kk][i] = A[rowm[i]*K + k0 + kk];
            int kk2 = idx >> 6, j = idx & 63;
            Ws[kk2][j] = W[(k0 + kk2)*N + n0 + j];
        }
        __syncthreads();
        #pragma unroll
        for (int kk = 0; kk < 16; kk++) {
            float4 b = *reinterpret_cast<const float4*>(&Ws[kk][tx << 2]);
            float a0 = As[kk][(ty<<2)+0];
            float a1 = As[kk][(ty<<2)+1];
            float a2 = As[kk][(ty<<2)+2];
            float a3 = As[kk][(ty<<2)+3];
            acc[ 0] += a0*b.x; acc[ 1] += a0*b.y; acc[ 2] += a0*b.z; acc[ 3] += a0*b.w;
            acc[ 4] += a1*b.x; acc[ 5] += a1*b.y; acc[ 6] += a1*b.z; acc[ 7] += a1*b.w;
            acc[ 8] += a2*b.x; acc[ 9] += a2*b.y; acc[10] += a2*b.z; acc[11] += a2*b.w;
            acc[12] += a3*b.x; acc[13] += a3*b.y; acc[14] += a3*b.z; acc[15] += a3*b.w;
        }
        __syncthreads();
    }
    #pragma unroll
    for (int r = 0; r < 4; r++) {
        int m = m0 + (ty<<2) + r;
        int rbase = 0;
        if (R) rbase = (rmap ? rmap[m] : m) * N;
        #pragma unroll
        for (int c = 0; c < 4; c++) {
            int n = n0 + (tx<<2) + c;
            float v = acc[r*4 + c];
            if (bias) v += bias[n];
            if (relu) v = fmaxf(v, 0.0f);
            if (R)    v += R[rbase + n];
            C[m*N + n] = v;
        }
    }
}

// ---------------- batched multihead attention (dk=64) ----------------
// grid: (NB, H). Q: token-major rows; q row = (batch/q_group)*Lq + i.
// K/V rows: batch*Lk + j. O row: batch*Lq + i. scale = 1/8.
// mask_mode: 0 none, 1 full [NB, Lq, Lk], 2 row [(batch/mask_div), Lk]
__global__ __launch_bounds__(256) void attn_kernel(
    const float* __restrict__ Q, const float* __restrict__ Kg,
    const float* __restrict__ Vg, float* __restrict__ O,
    int Lq, int Lk, int q_group,
    const int* __restrict__ mask, int mask_mode, int mask_div)
{
    extern __shared__ float sm[];
    float* sQ  = sm;                  // Lq*64
    float* sKV = sm + Lq*64;          // 32*65
    float* sS  = sKV + 32*65;         // Lq*(Lk+1)
    int batch = blockIdx.x, h = blockIdx.y;
    int tid = threadIdx.x;
    int qbase = (batch / q_group) * Lq;
    int LkP = Lk + 1;

    for (int idx = tid; idx < Lq*64; idx += 256) {
        int i = idx >> 6, d = idx & 63;
        sQ[idx] = Q[(qbase + i)*DD + h*64 + d];
    }
    // scores
    for (int jt = 0; jt < Lk; jt += 32) {
        __syncthreads();
        for (int idx = tid; idx < 32*64; idx += 256) {
            int j = idx >> 6, d = idx & 63;
            int jj = jt + j;
            sKV[j*65 + d] = (jj < Lk) ? Kg[(batch*Lk + jj)*DD + h*64 + d] : 0.0f;
        }
        __syncthreads();
        for (int idx = tid; idx < Lq*32; idx += 256) {
            int i = idx >> 5, j = idx & 31;
            int jj = jt + j;
            if (jj < Lk) {
                float s = 0.0f;
                #pragma unroll
                for (int d = 0; d < 64; d++) s += sQ[i*64 + d] * sKV[j*65 + d];
                s *= 0.125f;
                if (mask_mode == 1) {
                    if (mask[(batch*Lq + i)*Lk + jj] == 0) s = -1e9f;
                } else if (mask_mode == 2) {
                    if (mask[(batch/mask_div)*Lk + jj] == 0) s = -1e9f;
                }
                sS[i*LkP + jj] = s;
            }
        }
    }
    __syncthreads();
    // softmax (one warp per row)
    int warp = tid >> 5, lane = tid & 31;
    for (int i = warp; i < Lq; i += 8) {
        float m = -3.4e38f;
        for (int j = lane; j < Lk; j += 32) m = fmaxf(m, sS[i*LkP + j]);
        #pragma unroll
        for (int o = 16; o; o >>= 1) m = fmaxf(m, __shfl_xor_sync(0xffffffffu, m, o));
        float sum = 0.0f;
        for (int j = lane; j < Lk; j += 32) {
            float e = __expf(sS[i*LkP + j] - m);
            sS[i*LkP + j] = e;
            sum += e;
        }
        #pragma unroll
        for (int o = 16; o; o >>= 1) sum += __shfl_xor_sync(0xffffffffu, sum, o);
        float inv = 1.0f / sum;
        for (int j = lane; j < Lk; j += 32) sS[i*LkP + j] *= inv;
    }
    // O = A @ V
    if (Lq == 1) {
        float acc = 0.0f;
        int d = tid;
        for (int jt = 0; jt < Lk; jt += 32) {
            __syncthreads();
            for (int idx = tid; idx < 32*64; idx += 256) {
                int j = idx >> 6, dd = idx & 63;
                int jj = jt + j;
                sKV[j*65 + dd] = (jj < Lk) ? Vg[(batch*Lk + jj)*DD + h*64 + dd] : 0.0f;
            }
            __syncthreads();
            if (d < 64) {
                int lim = min(32, Lk - jt);
                for (int j = 0; j < lim; j++) acc += sS[jt + j] * sKV[j*65 + d];
            }
        }
        if (d < 64) O[batch*DD + h*64 + d] = acc;
    } else {
        int i = tid >> 2, dg = tid & 3;
        float acc[16];
        #pragma unroll
        for (int u = 0; u < 16; u++) acc[u] = 0.0f;
        for (int jt = 0; jt < Lk; jt += 32) {
            __syncthreads();
            for (int idx = tid; idx < 32*64; idx += 256) {
                int j = idx >> 6, dd = idx & 63;
                int jj = jt + j;
                sKV[j*65 + dd] = (jj < Lk) ? Vg[(batch*Lk + jj)*DD + h*64 + dd] : 0.0f;
            }
            __syncthreads();
            if (i < Lq) {
                int lim = min(32, Lk - jt);
                for (int j = 0; j < lim; j++) {
                    float a = sS[i*LkP + jt + j];
                    #pragma unroll
                    for (int u = 0; u < 16; u++) acc[u] += a * sKV[j*65 + dg*16 + u];
                }
            }
        }
        if (i < Lq) {
            int d0 = dg*16;
            #pragma unroll
            for (int u = 0; u < 16; u++)
                O[(batch*Lq + i)*DD + h*64 + d0 + u] = acc[u];
        }
    }
}

// ---------------- elementwise add ----------------
__global__ void add_kernel(const float* __restrict__ a, const float* __restrict__ b,
                           float* __restrict__ c, int n) {
    int i = blockIdx.x*256 + threadIdx.x;
    if (i < n) c[i] = a[i] + b[i];
}

// ---------------- host orchestration ----------------
static float* sym_f(const void* s) { void* p = nullptr; cudaGetSymbolAddress(&p, s); return (float*)p; }
static int*   sym_i(const void* s) { void* p = nullptr; cudaGetSymbolAddress(&p, s); return (int*)p; }

extern "C" void kernel_launch(void* const* d_in, const int* in_sizes, int n_in,
                              void* d_out, int out_size) {
    const float* x    = (const float*)d_in[0];
    const float* vft  = (const float*)d_in[1];
    const float* his  = (const float*)d_in[2];
    const float* cap  = (const float*)d_in[3];
    const float* qry  = (const float*)d_in[4];
    const int* trg_m  = (const int*)d_in[5];
    const int* his_m  = (const int*)d_in[6];
    const int* cap_m  = (const int*)d_in[7];
    const int* qry_m  = (const int*)d_in[8];
    const int* tmp_m  = (const int*)d_in[9];
    const float* attw = (const float*)d_in[10];
    const float* attb = (const float*)d_in[11];
    const float* ffw1 = (const float*)d_in[12];
    const float* ffb1 = (const float*)d_in[13];
    const float* ffw2 = (const float*)d_in[14];
    const float* ffb2 = (const float*)d_in[15];
    const float* lng  = (const float*)d_in[16];
    const float* lnb  = (const float*)d_in[17];
    float* out = (float*)d_out;

    float* cur   = sym_f(g_cur);
    float* lnbuf = sym_f(g_ln);
    float* qb    = sym_f(g_q);
    float* ks    = sym_f(g_ks);
    float* vs    = sym_f(g_vs);
    float* ab    = sym_f(g_attn);
    float* ts    = sym_f(g_ts);
    float* st    = sym_f(g_st);
    float* ffh   = sym_f(g_ffh);
    float* big0  = sym_f(g_big0);
    float* big1  = sym_f(g_big1);
    float* big2  = sym_f(g_big2);
    float* big3  = sym_f(g_big3);
    int* map_perm = sym_i(g_map_perm);
    int* map_pt   = sym_i(g_map_pt);
    int* map_ps   = sym_i(g_map_ps);
    int* res_t    = sym_i(g_res_t);
    int* res_s    = sym_i(g_res_s);

    cudaFuncSetAttribute((const void*)attn_kernel,
                         cudaFuncAttributeMaxDynamicSharedMemorySize, 64*1024);

    #define AW(i,j) (attw + ((i)*4+(j))*DD*DD)
    #define ABI(i,j) (attb + ((i)*4+(j))*DD)

    auto gemm = [](const float* A, const int* amap, const float* W, const float* bias,
                   const float* R, const int* rmap, float* C, int M, int N, int K, int relu) {
        dim3 grid(N/64, M/64);
        sgemm_kernel<<<grid, 256>>>(A, amap, W, bias, R, rmap, C, M, N, K, relu);
    };
    auto attn = [](const float* Q, const float* K, const float* V, float* O,
                   int NB, int Lq, int Lk, int qg, const int* mask, int mode, int mdiv) {
        size_t sh = (size_t)(Lq*64 + 32*65 + Lq*(Lk+1)) * sizeof(float);
        attn_kernel<<<dim3(NB, HH), 256, sh>>>(Q, K, V, O, Lq, Lk, qg, mask, mode, mdiv);
    };
    auto ln = [&](const float* in, int li, float* o, int rows) {
        ln_kernel<<<rows, 128>>>(in, lng + li*DD, lnb + li*DD, o);
    };

    // ---- build index maps ----
    build_swap<<<(NTOK_VFT+255)/256, 256>>>(map_perm, BB, SS, TT);    // (b,s,t) <- vft(b,t,s)
    build_swap<<<(NTOK_VFT+255)/256, 256>>>(map_pt,   BB, TTRG, SS);  // (b,t,s) <- t_out(b,s,t)
    build_swap<<<(NTOK_SOUT+255)/256, 256>>>(map_ps,  BB, TTRG, TT);  // (b,t,tau) <- s_out(b,tau,t)
    build_res <<<(NTOK_VFT+255)/256, 256>>>(res_t, NTOK_VFT, SS*TT, TTRG);
    build_res <<<(NTOK_SOUT+255)/256, 256>>>(res_s, NTOK_SOUT, TT*TTRG, TTRG);

    // ---- mha0: self-attention (causal) ----
    ln(x, 0, lnbuf, NTOK_X);
    gemm(lnbuf, nullptr, AW(0,0), ABI(0,0), nullptr, nullptr, qb, NTOK_X, DD, DD, 0);
    gemm(lnbuf, nullptr, AW(0,1), ABI(0,1), nullptr, nullptr, ks, NTOK_X, DD, DD, 0);
    gemm(lnbuf, nullptr, AW(0,2), ABI(0,2), nullptr, nullptr, vs, NTOK_X, DD, DD, 0);
    attn(qb, ks, vs, ab, BB, TTRG, TTRG, 1, trg_m, 1, 1);
    gemm(ab, nullptr, AW(0,3), ABI(0,3), x, nullptr, cur, NTOK_X, DD, DD, 0);

    // ---- mha1..3: cross-attention (his / cap / query) ----
    {
        const float* kvsrc[3] = { his, cap, qry };
        const int    kvrows[3] = { BB*128, BB*64, BB*32 };
        const int    Lks[3]    = { 128, 64, 32 };
        const int*   masks[3]  = { his_m, cap_m, qry_m };
        for (int a = 0; a < 3; a++) {
            int wi = a + 1;
            ln(cur, wi, lnbuf, NTOK_X);
            gemm(lnbuf, nullptr, AW(wi,0), ABI(wi,0), nullptr, nullptr, qb, NTOK_X, DD, DD, 0);
            gemm(kvsrc[a], nullptr, AW(wi,1), ABI(wi,1), nullptr, nullptr, ks, kvrows[a], DD, DD, 0);
            gemm(kvsrc[a], nullptr, AW(wi,2), ABI(wi,2), nullptr, nullptr, vs, kvrows[a], DD, DD, 0);
            attn(qb, ks, vs, ab, BB, TTRG, Lks[a], 1, masks[a], 2, 1);
            gemm(ab, nullptr, AW(wi,3), ABI(wi,3), cur, nullptr, cur, NTOK_X, DD, DD, 0);
        }
    }
    // cur == mm from here on (must stay intact until after mha7 out-proj)

    // ---- temporal2spatial: mha4 ----
    ln(cur, 4, lnbuf, NTOK_X);
    gemm(lnbuf, nullptr, AW(4,0), ABI(4,0), nullptr, nullptr, qb, NTOK_X, DD, DD, 0);
    gemm(vft, map_perm, AW(4,1), ABI(4,1), nullptr, nullptr, big0, NTOK_VFT, DD, DD, 0);
    gemm(vft, map_perm, AW(4,2), ABI(4,2), nullptr, nullptr, big1, NTOK_VFT, DD, DD, 0);
    attn(qb, big0, big1, big2, BB*SS, TTRG, TT, SS, tmp_m, 2, SS);
    gemm(big2, nullptr, AW(4,3), ABI(4,3), cur, res_t, big3, NTOK_VFT, DD, DD, 0); // t_out

    // ---- mha5: attend over S, single query ----
    ln(cur, 5, lnbuf, NTOK_X);
    gemm(lnbuf, nullptr, AW(5,0), ABI(5,0), nullptr, nullptr, qb, NTOK_X, DD, DD, 0);
    gemm(big3, map_pt, AW(5,1), ABI(5,1), nullptr, nullptr, big0, NTOK_VFT, DD, DD, 0);
    gemm(big3, map_pt, AW(5,2), ABI(5,2), nullptr, nullptr, big1, NTOK_VFT, DD, DD, 0);
    attn(qb, big0, big1, ab, NTOK_X, 1, SS, 1, nullptr, 0, 1);
    gemm(ab, nullptr, AW(5,3), ABI(5,3), cur, nullptr, ts, NTOK_X, DD, DD, 0);
    // ffn0
    ln(ts, 6, lnbuf, NTOK_X);
    gemm(lnbuf, nullptr, ffw1 + 0*DD*DFF, ffb1 + 0*DFF, nullptr, nullptr, ffh, NTOK_X, DFF, DD, 1);
    gemm(ffh, nullptr, ffw2 + 0*DFF*DD, ffb2 + 0*DD, ts, nullptr, ts, NTOK_X, DD, DFF, 0);

    // ---- spatial2temporal: mha6 ----
    ln(cur, 7, lnbuf, NTOK_X);
    gemm(lnbuf, nullptr, AW(6,0), ABI(6,0), nullptr, nullptr, qb, NTOK_X, DD, DD, 0);
    gemm(vft, nullptr, AW(6,1), ABI(6,1), nullptr, nullptr, big0, NTOK_VFT, DD, DD, 0);
    gemm(vft, nullptr, AW(6,2), ABI(6,2), nullptr, nullptr, big1, NTOK_VFT, DD, DD, 0);
    attn(qb, big0, big1, big2, BB*TT, TTRG, SS, TT, nullptr, 0, 1);
    gemm(big2, nullptr, AW(6,3), ABI(6,3), cur, res_s, big3, NTOK_SOUT, DD, DD, 0); // s_out

    // ---- mha7: attend over T, single query ----
    ln(cur, 8, lnbuf, NTOK_X);
    gemm(lnbuf, nullptr, AW(7,0), ABI(7,0), nullptr, nullptr, qb, NTOK_X, DD, DD, 0);
    gemm(big3, map_ps, AW(7,1), ABI(7,1), nullptr, nullptr, big0, NTOK_SOUT, DD, DD, 0);
    gemm(big3, map_ps, AW(7,2), ABI(7,2), nullptr, nullptr, big1, NTOK_SOUT, DD, DD, 0);
    attn(qb, big0, big1, ab, NTOK_X, 1, TT, 1, tmp_m, 2, TTRG);
    gemm(ab, nullptr, AW(7,3), ABI(7,3), cur, nullptr, st, NTOK_X, DD, DD, 0);
    // ffn1
    ln(st, 9, lnbuf, NTOK_X);
    gemm(lnbuf, nullptr, ffw1 + 1*DD*DFF, ffb1 + 1*DFF, nullptr, nullptr, ffh, NTOK_X, DFF, DD, 1);
    gemm(ffh, nullptr, ffw2 + 1*DFF*DD, ffb2 + 1*DD, st, nullptr, st, NTOK_X, DD, DFF, 0);

    // ---- combine + ffn2 -> out ----
    add_kernel<<<(NTOK_X*DD + 255)/256, 256>>>(ts, st, cur, NTOK_X*DD);
    ln(cur, 10, lnbuf, NTOK_X);
    gemm(lnbuf, nullptr, ffw1 + 2*DD*DFF, ffb1 + 2*DFF, nullptr, nullptr, ffh, NTOK_X, DFF, DD, 1);
    gemm(ffh, nullptr, ffw2 + 2*DFF*DD, ffb2 + 2*DD, cur, nullptr, out, NTOK_X, DD, DFF, 0);

    #undef AW
    #undef ABI
}

// round 2
// speedup vs baseline: 1.1382x; 1.1382x over previous
#include <cuda_runtime.h>
#include <math.h>

// ---------------- problem constants ----------------
#define BB   16
#define TTRG 64
#define TT   64
#define SS   49
#define DD   512
#define DFF  2048
#define HH   8
#define NTOK_X    (BB*TTRG)          // 1024
#define NTOK_VFT  (BB*TT*SS)         // 50176
#define NTOK_SOUT (BB*TT*TTRG)       // 65536

// ---------------- scratch ----------------
__device__ float g_cur [NTOK_X*DD];
__device__ float g_ln  [NTOK_X*DD];
__device__ float g_q   [NTOK_X*DD];
__device__ float g_ks  [2048*DD];
__device__ float g_vs  [2048*DD];
__device__ float g_attn[NTOK_X*DD];
__device__ float g_ts  [NTOK_X*DD];
__device__ float g_st  [NTOK_X*DD];
__device__ float g_ffh [NTOK_X*DFF];
__device__ float g_big0[NTOK_SOUT*DD];
__device__ float g_big1[NTOK_SOUT*DD];
__device__ float g_big2[NTOK_SOUT*DD];
__device__ float g_big3[NTOK_SOUT*DD];
__device__ int   g_map_perm[NTOK_VFT];
__device__ int   g_map_pt  [NTOK_VFT];
__device__ int   g_map_ps  [NTOK_SOUT];
__device__ int   g_res_t   [NTOK_VFT];
__device__ int   g_res_s   [NTOK_SOUT];

// ---------------- map builders ----------------
__global__ void build_swap(int* map, int A, int Bd, int Cd) {
    int m = blockIdx.x*256 + threadIdx.x;
    int tot = A*Bd*Cd;
    if (m < tot) {
        int c = m % Cd;
        int b = (m / Cd) % Bd;
        int a = m / (Cd*Bd);
        map[m] = (a*Cd + c)*Bd + b;
    }
}
__global__ void build_res(int* map, int tot, int p, int q) {
    int m = blockIdx.x*256 + threadIdx.x;
    if (m < tot) map[m] = (m/p)*q + (m % q);
}

// ---------------- layernorm (D=512) ----------------
__global__ __launch_bounds__(128) void ln_kernel(const float* __restrict__ in,
                                                 const float* __restrict__ gamma,
                                                 const float* __restrict__ beta,
                                                 float* __restrict__ out) {
    int row = blockIdx.x;
    int tid = threadIdx.x;
    const float4* p = reinterpret_cast<const float4*>(in + (long)row*DD);
    float4 v = p[tid];
    float s = v.x + v.y + v.z + v.w;
    float q = v.x*v.x + v.y*v.y + v.z*v.z + v.w*v.w;
    #pragma unroll
    for (int o = 16; o; o >>= 1) {
        s += __shfl_xor_sync(0xffffffffu, s, o);
        q += __shfl_xor_sync(0xffffffffu, q, o);
    }
    __shared__ float ssum[4], ssq[4];
    int warp = tid >> 5, lane = tid & 31;
    if (lane == 0) { ssum[warp] = s; ssq[warp] = q; }
    __syncthreads();
    __shared__ float smean, sinv;
    if (tid == 0) {
        float S = ssum[0]+ssum[1]+ssum[2]+ssum[3];
        float Q = ssq[0]+ssq[1]+ssq[2]+ssq[3];
        float mean = S * (1.0f/DD);
        float var  = Q * (1.0f/DD) - mean*mean;
        float sd   = sqrtf(fmaxf(var, 0.0f));
        smean = mean;
        sinv  = 1.0f / (sd + 1e-6f);
    }
    __syncthreads();
    float mean = smean, inv = sinv;
    float4 gv = reinterpret_cast<const float4*>(gamma)[tid];
    float4 bv = reinterpret_cast<const float4*>(beta)[tid];
    float4 o;
    o.x = gv.x*(v.x-mean)*inv + bv.x;
    o.y = gv.y*(v.y-mean)*inv + bv.y;
    o.z = gv.z*(v.z-mean)*inv + bv.z;
    o.w = gv.w*(v.w-mean)*inv + bv.w;
    reinterpret_cast<float4*>(out + (long)row*DD)[tid] = o;
}

// ---------------- small SGEMM (64x64 tile) for M<=2048 ----------------
__global__ __launch_bounds__(256) void sgemm_kernel(
    const float* __restrict__ A, const int* __restrict__ amap,
    const float* __restrict__ W, const float* __restrict__ bias,
    const float* __restrict__ R, const int* __restrict__ rmap,
    float* __restrict__ C, int M, int N, int K, int relu)
{
    __shared__ float As[16][68];
    __shared__ float Ws[16][64];
    __shared__ int rowm[64];
    int tid = threadIdx.x;
    int m0 = blockIdx.y << 6, n0 = blockIdx.x << 6;
    if (tid < 64) rowm[tid] = amap ? amap[m0 + tid] : (m0 + tid);
    __syncthreads();
    int ty = tid >> 4, tx = tid & 15;
    float acc[16];
    #pragma unroll
    for (int u = 0; u < 16; u++) acc[u] = 0.0f;

    for (int k0 = 0; k0 < K; k0 += 16) {
        #pragma unroll
        for (int r = 0; r < 4; r++) {
            int idx = tid + (r << 8);
            int i  = idx >> 4, kk = idx & 15;
            As[kk][i] = A[rowm[i]*K + k0 + kk];
            int kk2 = idx >> 6, j = idx & 63;
            Ws[kk2][j] = W[(k0 + kk2)*N + n0 + j];
        }
        __syncthreads();
        #pragma unroll
        for (int kk = 0; kk < 16; kk++) {
            float4 b = *reinterpret_cast<const float4*>(&Ws[kk][tx << 2]);
            float a0 = As[kk][(ty<<2)+0];
            float a1 = As[kk][(ty<<2)+1];
            float a2 = As[kk][(ty<<2)+2];
            float a3 = As[kk][(ty<<2)+3];
            acc[ 0] += a0*b.x; acc[ 1] += a0*b.y; acc[ 2] += a0*b.z; acc[ 3] += a0*b.w;
            acc[ 4] += a1*b.x; acc[ 5] += a1*b.y; acc[ 6] += a1*b.z; acc[ 7] += a1*b.w;
            acc[ 8] += a2*b.x; acc[ 9] += a2*b.y; acc[10] += a2*b.z; acc[11] += a2*b.w;
            acc[12] += a3*b.x; acc[13] += a3*b.y; acc[14] += a3*b.z; acc[15] += a3*b.w;
        }
        __syncthreads();
    }
    #pragma unroll
    for (int r = 0; r < 4; r++) {
        int m = m0 + (ty<<2) + r;
        int rbase = 0;
        if (R) rbase = (rmap ? rmap[m] : m) * N;
        #pragma unroll
        for (int c = 0; c < 4; c++) {
            int n = n0 + (tx<<2) + c;
            float v = acc[r*4 + c];
            if (bias) v += bias[n];
            if (relu) v = fmaxf(v, 0.0f);
            if (R)    v += R[rbase + n];
            C[m*N + n] = v;
        }
    }
}

// ---------------- big SGEMM (128x128 tile, k=8, double-buffered) ----------------
// Requires M%128==0, N%128==0, K%8==0.
__global__ __launch_bounds__(256) void sgemm128_kernel(
    const float* __restrict__ A, const int* __restrict__ amap,
    const float* __restrict__ W, const float* __restrict__ bias,
    const float* __restrict__ R, const int* __restrict__ rmap,
    float* __restrict__ C, int M, int N, int K, int relu)
{
    __shared__ float As[2][8][128];
    __shared__ float Bs[2][8][128];
    __shared__ int rowm[128];
    int tid = threadIdx.x;
    int m0 = blockIdx.y << 7, n0 = blockIdx.x << 7;
    if (tid < 128) rowm[tid] = amap ? amap[m0 + tid] : (m0 + tid);
    __syncthreads();

    int ty = tid >> 4, tx = tid & 15;    // 16x16 thread grid, 8x8 microtile
    // A load: row = tid>>1, k-quad = tid&1 (k offset 0 or 4)
    int arow = tid >> 1, akq = (tid & 1) << 2;
    const float* aptr = A + (long)rowm[arow]*K + akq;
    // B load: kk = tid>>5, col4 = (tid&31)*4
    int bkk = tid >> 5, bc4 = (tid & 31) << 2;
    const float* bptr = W + (long)bkk*N + n0 + bc4;

    float acc[8][8];
    #pragma unroll
    for (int i = 0; i < 8; i++)
        #pragma unroll
        for (int j = 0; j < 8; j++) acc[i][j] = 0.0f;

    // preload tile 0
    float4 pa = *reinterpret_cast<const float4*>(aptr);
    float4 pb = *reinterpret_cast<const float4*>(bptr);
    As[0][akq+0][arow] = pa.x;
    As[0][akq+1][arow] = pa.y;
    As[0][akq+2][arow] = pa.z;
    As[0][akq+3][arow] = pa.w;
    *reinterpret_cast<float4*>(&Bs[0][bkk][bc4]) = pb;
    __syncthreads();

    int buf = 0;
    for (int k0 = 0; k0 < K; k0 += 8) {
        bool has_next = (k0 + 8) < K;
        if (has_next) {
            pa = *reinterpret_cast<const float4*>(aptr + k0 + 8);
            pb = *reinterpret_cast<const float4*>(bptr + (long)(k0 + 8)*N);
        }
        #pragma unroll
        for (int kk = 0; kk < 8; kk++) {
            float4 a0 = *reinterpret_cast<const float4*>(&As[buf][kk][ty<<3]);
            float4 a1 = *reinterpret_cast<const float4*>(&As[buf][kk][(ty<<3)+4]);
            float4 b0 = *reinterpret_cast<const float4*>(&Bs[buf][kk][tx<<3]);
            float4 b1 = *reinterpret_cast<const float4*>(&Bs[buf][kk][(tx<<3)+4]);
            float av[8] = {a0.x,a0.y,a0.z,a0.w,a1.x,a1.y,a1.z,a1.w};
            float bv[8] = {b0.x,b0.y,b0.z,b0.w,b1.x,b1.y,b1.z,b1.w};
            #pragma unroll
            for (int i = 0; i < 8; i++)
                #pragma unroll
                for (int j = 0; j < 8; j++)
                    acc[i][j] += av[i]*bv[j];
        }
        if (has_next) {
            int nb = buf ^ 1;
            As[nb][akq+0][arow] = pa.x;
            As[nb][akq+1][arow] = pa.y;
            As[nb][akq+2][arow] = pa.z;
            As[nb][akq+3][arow] = pa.w;
            *reinterpret_cast<float4*>(&Bs[nb][bkk][bc4]) = pb;
        }
        __syncthreads();
        buf ^= 1;
    }

    // epilogue
    float4 bb0, bb1;
    if (bias) {
        bb0 = *reinterpret_cast<const float4*>(bias + n0 + (tx<<3));
        bb1 = *reinterpret_cast<const float4*>(bias + n0 + (tx<<3) + 4);
    }
    #pragma unroll
    for (int i = 0; i < 8; i++) {
        int m = m0 + (ty<<3) + i;
        long cb = (long)m*N + n0 + (tx<<3);
        float4 v0 = make_float4(acc[i][0], acc[i][1], acc[i][2], acc[i][3]);
        float4 v1 = make_float4(acc[i][4], acc[i][5], acc[i][6], acc[i][7]);
        if (bias) {
            v0.x += bb0.x; v0.y += bb0.y; v0.z += bb0.z; v0.w += bb0.w;
            v1.x += bb1.x; v1.y += bb1.y; v1.z += bb1.z; v1.w += bb1.w;
        }
        if (relu) {
            v0.x = fmaxf(v0.x,0.f); v0.y = fmaxf(v0.y,0.f); v0.z = fmaxf(v0.z,0.f); v0.w = fmaxf(v0.w,0.f);
            v1.x = fmaxf(v1.x,0.f); v1.y = fmaxf(v1.y,0.f); v1.z = fmaxf(v1.z,0.f); v1.w = fmaxf(v1.w,0.f);
        }
        if (R) {
            long rb = (long)(rmap ? rmap[m] : m)*N + n0 + (tx<<3);
            float4 r0 = *reinterpret_cast<const float4*>(R + rb);
            float4 r1 = *reinterpret_cast<const float4*>(R + rb + 4);
            v0.x += r0.x; v0.y += r0.y; v0.z += r0.z; v0.w += r0.w;
            v1.x += r1.x; v1.y += r1.y; v1.z += r1.z; v1.w += r1.w;
        }
        *reinterpret_cast<float4*>(C + cb)     = v0;
        *reinterpret_cast<float4*>(C + cb + 4) = v1;
    }
}

// ---------------- batched multihead attention (dk=64) ----------------
#define KVP 68   // padded K/V smem stride (float4-aligned, conflict-friendly)
__global__ __launch_bounds__(256) void attn_kernel(
    const float* __restrict__ Q, const float* __restrict__ Kg,
    const float* __restrict__ Vg, float* __restrict__ O,
    int Lq, int Lk, int q_group,
    const int* __restrict__ mask, int mask_mode, int mask_div)
{
    extern __shared__ float sm[];
    float* sQ  = sm;                  // Lq*64
    float* sKV = sm + Lq*64;          // 32*KVP
    float* sS  = sKV + 32*KVP;        // Lq*(Lk+1)
    int batch = blockIdx.x, h = blockIdx.y;
    int tid = threadIdx.x;
    int qbase = (batch / q_group) * Lq;
    int LkP = Lk + 1;

    for (int idx = tid; idx < Lq*64; idx += 256) {
        int i = idx >> 6, d = idx & 63;
        sQ[idx] = Q[(qbase + i)*DD + h*64 + d];
    }
    // scores
    for (int jt = 0; jt < Lk; jt += 32) {
        __syncthreads();
        for (int idx = tid; idx < 32*64; idx += 256) {
            int j = idx >> 6, d = idx & 63;
            int jj = jt + j;
            sKV[j*KVP + d] = (jj < Lk) ? Kg[(batch*Lk + jj)*DD + h*64 + d] : 0.0f;
        }
        __syncthreads();
        for (int idx = tid; idx < Lq*32; idx += 256) {
            int i = idx >> 5, j = idx & 31;
            int jj = jt + j;
            if (jj < Lk) {
                const float4* q4 = reinterpret_cast<const float4*>(sQ + i*64);
                const float4* k4 = reinterpret_cast<const float4*>(sKV + j*KVP);
                float s = 0.0f;
                #pragma unroll
                for (int d = 0; d < 16; d++) {
                    float4 a = q4[d], b = k4[d];
                    s += a.x*b.x + a.y*b.y + a.z*b.z + a.w*b.w;
                }
                s *= 0.125f;
                if (mask_mode == 1) {
                    if (mask[(batch*Lq + i)*Lk + jj] == 0) s = -1e9f;
                } else if (mask_mode == 2) {
                    if (mask[(batch/mask_div)*Lk + jj] == 0) s = -1e9f;
                }
                sS[i*LkP + jj] = s;
            }
        }
    }
    __syncthreads();
    // softmax
    int warp = tid >> 5, lane = tid & 31;
    for (int i = warp; i < Lq; i += 8) {
        float m = -3.4e38f;
        for (int j = lane; j < Lk; j += 32) m = fmaxf(m, sS[i*LkP + j]);
        #pragma unroll
        for (int o = 16; o; o >>= 1) m = fmaxf(m, __shfl_xor_sync(0xffffffffu, m, o));
        float sum = 0.0f;
        for (int j = lane; j < Lk; j += 32) {
            float e = __expf(sS[i*LkP + j] - m);
            sS[i*LkP + j] = e;
            sum += e;
        }
        #pragma unroll
        for (int o = 16; o; o >>= 1) sum += __shfl_xor_sync(0xffffffffu, sum, o);
        float inv = 1.0f / sum;
        for (int j = lane; j < Lk; j += 32) sS[i*LkP + j] *= inv;
    }
    // O = A @ V
    if (Lq == 1) {
        float acc = 0.0f;
        int d = tid;
        for (int jt = 0; jt < Lk; jt += 32) {
            __syncthreads();
            for (int idx = tid; idx < 32*64; idx += 256) {
                int j = idx >> 6, dd = idx & 63;
                int jj = jt + j;
                sKV[j*KVP + dd] = (jj < Lk) ? Vg[(batch*Lk + jj)*DD + h*64 + dd] : 0.0f;
            }
            __syncthreads();
            if (d < 64) {
                int lim = min(32, Lk - jt);
                for (int j = 0; j < lim; j++) acc += sS[jt + j] * sKV[j*KVP + d];
            }
        }
        if (d < 64) O[batch*DD + h*64 + d] = acc;
    } else {
        int i = tid >> 2, dg = tid & 3;
        float acc[16];
        #pragma unroll
        for (int u = 0; u < 16; u++) acc[u] = 0.0f;
        for (int jt = 0; jt < Lk; jt += 32) {
            __syncthreads();
            for (int idx = tid; idx < 32*64; idx += 256) {
                int j = idx >> 6, dd = idx & 63;
                int jj = jt + j;
                sKV[j*KVP + dd] = (jj < Lk) ? Vg[(batch*Lk + jj)*DD + h*64 + dd] : 0.0f;
            }
            __syncthreads();
            if (i < Lq) {
                int lim = min(32, Lk - jt);
                for (int j = 0; j < lim; j++) {
                    float a = sS[i*LkP + jt + j];
                    const float4* v4 = reinterpret_cast<const float4*>(sKV + j*KVP + dg*16);
                    #pragma unroll
                    for (int u4 = 0; u4 < 4; u4++) {
                        float4 b = v4[u4];
                        acc[u4*4+0] += a*b.x;
                        acc[u4*4+1] += a*b.y;
                        acc[u4*4+2] += a*b.z;
                        acc[u4*4+3] += a*b.w;
                    }
                }
            }
        }
        if (i < Lq) {
            int d0 = dg*16;
            float* ob = O + (long)(batch*Lq + i)*DD + h*64 + d0;
            #pragma unroll
            for (int u4 = 0; u4 < 4; u4++) {
                float4 v = make_float4(acc[u4*4+0], acc[u4*4+1], acc[u4*4+2], acc[u4*4+3]);
                *reinterpret_cast<float4*>(ob + u4*4) = v;
            }
        }
    }
}

// ---------------- elementwise add ----------------
__global__ void add_kernel(const float* __restrict__ a, const float* __restrict__ b,
                           float* __restrict__ c, int n) {
    int i = blockIdx.x*256 + threadIdx.x;
    if (i < n) c[i] = a[i] + b[i];
}

// ---------------- host ----------------
static float* sym_f(const void* s) { void* p = nullptr; cudaGetSymbolAddress(&p, s); return (float*)p; }
static int*   sym_i(const void* s) { void* p = nullptr; cudaGetSymbolAddress(&p, s); return (int*)p; }

extern "C" void kernel_launch(void* const* d_in, const int* in_sizes, int n_in,
                              void* d_out, int out_size) {
    const float* x    = (const float*)d_in[0];
    const float* vft  = (const float*)d_in[1];
    const float* his  = (const float*)d_in[2];
    const float* cap  = (const float*)d_in[3];
    const float* qry  = (const float*)d_in[4];
    const int* trg_m  = (const int*)d_in[5];
    const int* his_m  = (const int*)d_in[6];
    const int* cap_m  = (const int*)d_in[7];
    const int* qry_m  = (const int*)d_in[8];
    const int* tmp_m  = (const int*)d_in[9];
    const float* attw = (const float*)d_in[10];
    const float* attb = (const float*)d_in[11];
    const float* ffw1 = (const float*)d_in[12];
    const float* ffb1 = (const float*)d_in[13];
    const float* ffw2 = (const float*)d_in[14];
    const float* ffb2 = (const float*)d_in[15];
    const float* lng  = (const float*)d_in[16];
    const float* lnb  = (const float*)d_in[17];
    float* out = (float*)d_out;

    float* cur   = sym_f(g_cur);
    float* lnbuf = sym_f(g_ln);
    float* qb    = sym_f(g_q);
    float* ks    = sym_f(g_ks);
    float* vs    = sym_f(g_vs);
    float* ab    = sym_f(g_attn);
    float* ts    = sym_f(g_ts);
    float* st    = sym_f(g_st);
    float* ffh   = sym_f(g_ffh);
    float* big0  = sym_f(g_big0);
    float* big1  = sym_f(g_big1);
    float* big2  = sym_f(g_big2);
    float* big3  = sym_f(g_big3);
    int* map_perm = sym_i(g_map_perm);
    int* map_pt   = sym_i(g_map_pt);
    int* map_ps   = sym_i(g_map_ps);
    int* res_t    = sym_i(g_res_t);
    int* res_s    = sym_i(g_res_s);

    cudaFuncSetAttribute((const void*)attn_kernel,
                         cudaFuncAttributeMaxDynamicSharedMemorySize, 64*1024);

    #define AW(i,j) (attw + ((i)*4+(j))*DD*DD)
    #define ABI(i,j) (attb + ((i)*4+(j))*DD)

    auto gemm = [](const float* A, const int* amap, const float* W, const float* bias,
                   const float* R, const int* rmap, float* C, int M, int N, int K, int relu) {
        if (M >= 4096) {
            dim3 grid(N/128, M/128);
            sgemm128_kernel<<<grid, 256>>>(A, amap, W, bias, R, rmap, C, M, N, K, relu);
        } else {
            dim3 grid(N/64, M/64);
            sgemm_kernel<<<grid, 256>>>(A, amap, W, bias, R, rmap, C, M, N, K, relu);
        }
    };
    auto attn = [](const float* Q, const float* K, const float* V, float* O,
                   int NB, int Lq, int Lk, int qg, const int* mask, int mode, int mdiv) {
        size_t sh = (size_t)(Lq*64 + 32*KVP + Lq*(Lk+1)) * sizeof(float);
        attn_kernel<<<dim3(NB, HH), 256, sh>>>(Q, K, V, O, Lq, Lk, qg, mask, mode, mdiv);
    };
    auto ln = [&](const float* in, int li, float* o, int rows) {
        ln_kernel<<<rows, 128>>>(in, lng + li*DD, lnb + li*DD, o);
    };

    // maps
    build_swap<<<(NTOK_VFT+255)/256, 256>>>(map_perm, BB, SS, TT);
    build_swap<<<(NTOK_VFT+255)/256, 256>>>(map_pt,   BB, TTRG, SS);
    build_swap<<<(NTOK_SOUT+255)/256, 256>>>(map_ps,  BB, TTRG, TT);
    build_res <<<(NTOK_VFT+255)/256, 256>>>(res_t, NTOK_VFT, SS*TT, TTRG);
    build_res <<<(NTOK_SOUT+255)/256, 256>>>(res_s, NTOK_SOUT, TT*TTRG, TTRG);

    // ---- mha0: causal self-attention ----
    ln(x, 0, lnbuf, NTOK_X);
    gemm(lnbuf, nullptr, AW(0,0), ABI(0,0), nullptr, nullptr, qb, NTOK_X, DD, DD, 0);
    gemm(lnbuf, nullptr, AW(0,1), ABI(0,1), nullptr, nullptr, ks, NTOK_X, DD, DD, 0);
    gemm(lnbuf, nullptr, AW(0,2), ABI(0,2), nullptr, nullptr, vs, NTOK_X, DD, DD, 0);
    attn(qb, ks, vs, ab, BB, TTRG, TTRG, 1, trg_m, 1, 1);
    gemm(ab, nullptr, AW(0,3), ABI(0,3), x, nullptr, cur, NTOK_X, DD, DD, 0);

    // ---- mha1..3 ----
    {
        const float* kvsrc[3] = { his, cap, qry };
        const int    kvrows[3] = { BB*128, BB*64, BB*32 };
        const int    Lks[3]    = { 128, 64, 32 };
        const int*   masks[3]  = { his_m, cap_m, qry_m };
        for (int a = 0; a < 3; a++) {
            int wi = a + 1;
            ln(cur, wi, lnbuf, NTOK_X);
            gemm(lnbuf, nullptr, AW(wi,0), ABI(wi,0), nullptr, nullptr, qb, NTOK_X, DD, DD, 0);
            gemm(kvsrc[a], nullptr, AW(wi,1), ABI(wi,1), nullptr, nullptr, ks, kvrows[a], DD, DD, 0);
            gemm(kvsrc[a], nullptr, AW(wi,2), ABI(wi,2), nullptr, nullptr, vs, kvrows[a], DD, DD, 0);
            attn(qb, ks, vs, ab, BB, TTRG, Lks[a], 1, masks[a], 2, 1);
            gemm(ab, nullptr, AW(wi,3), ABI(wi,3), cur, nullptr, cur, NTOK_X, DD, DD, 0);
        }
    }

    // ---- temporal2spatial: mha4 ----
    ln(cur, 4, lnbuf, NTOK_X);
    gemm(lnbuf, nullptr, AW(4,0), ABI(4,0), nullptr, nullptr, qb, NTOK_X, DD, DD, 0);
    gemm(vft, map_perm, AW(4,1), ABI(4,1), nullptr, nullptr, big0, NTOK_VFT, DD, DD, 0);
    gemm(vft, map_perm, AW(4,2), ABI(4,2), nullptr, nullptr, big1, NTOK_VFT, DD, DD, 0);
    attn(qb, big0, big1, big2, BB*SS, TTRG, TT, SS, tmp_m, 2, SS);
    gemm(big2, nullptr, AW(4,3), ABI(4,3), cur, res_t, big3, NTOK_VFT, DD, DD, 0);

    // ---- mha5 ----
    ln(cur, 5, lnbuf, NTOK_X);
    gemm(lnbuf, nullptr, AW(5,0), ABI(5,0), nullptr, nullptr, qb, NTOK_X, DD, DD, 0);
    gemm(big3, map_pt, AW(5,1), ABI(5,1), nullptr, nullptr, big0, NTOK_VFT, DD, DD, 0);
    gemm(big3, map_pt, AW(5,2), ABI(5,2), nullptr, nullptr, big1, NTOK_VFT, DD, DD, 0);
    attn(qb, big0, big1, ab, NTOK_X, 1, SS, 1, nullptr, 0, 1);
    gemm(ab, nullptr, AW(5,3), ABI(5,3), cur, nullptr, ts, NTOK_X, DD, DD, 0);
    // ffn0
    ln(ts, 6, lnbuf, NTOK_X);
    gemm(lnbuf, nullptr, ffw1 + 0*DD*DFF, ffb1 + 0*DFF, nullptr, nullptr, ffh, NTOK_X, DFF, DD, 1);
    gemm(ffh, nullptr, ffw2 + 0*DFF*DD, ffb2 + 0*DD, ts, nullptr, ts, NTOK_X, DD, DFF, 0);

    // ---- spatial2temporal: mha6 ----
    ln(cur, 7, lnbuf, NTOK_X);
    gemm(lnbuf, nullptr, AW(6,0), ABI(6,0), nullptr, nullptr, qb, NTOK_X, DD, DD, 0);
    gemm(vft, nullptr, AW(6,1), ABI(6,1), nullptr, nullptr, big0, NTOK_VFT, DD, DD, 0);
    gemm(vft, nullptr, AW(6,2), ABI(6,2), nullptr, nullptr, big1, NTOK_VFT, DD, DD, 0);
    attn(qb, big0, big1, big2, BB*TT, TTRG, SS, TT, nullptr, 0, 1);
    gemm(big2, nullptr, AW(6,3), ABI(6,3), cur, res_s, big3, NTOK_SOUT, DD, DD, 0);

    // ---- mha7 ----
    ln(cur, 8, lnbuf, NTOK_X);
    gemm(lnbuf, nullptr, AW(7,0), ABI(7,0), nullptr, nullptr, qb, NTOK_X, DD, DD, 0);
    gemm(big3, map_ps, AW(7,1), ABI(7,1), nullptr, nullptr, big0, NTOK_SOUT, DD, DD, 0);
    gemm(big3, map_ps, AW(7,2), ABI(7,2), nullptr, nullptr, big1, NTOK_SOUT, DD, DD, 0);
    attn(qb, big0, big1, ab, NTOK_X, 1, TT, 1, tmp_m, 2, TTRG);
    gemm(ab, nullptr, AW(7,3), ABI(7,3), cur, nullptr, st, NTOK_X, DD, DD, 0);
    // ffn1
    ln(st, 9, lnbuf, NTOK_X);
    gemm(lnbuf, nullptr, ffw1 + 1*DD*DFF, ffb1 + 1*DFF, nullptr, nullptr, ffh, NTOK_X, DFF, DD, 1);
    gemm(ffh, nullptr, ffw2 + 1*DFF*DD, ffb2 + 1*DD, st, nullptr, st, NTOK_X, DD, DFF, 0);

    // ---- combine + ffn2 ----
    add_kernel<<<(NTOK_X*DD + 255)/256, 256>>>(ts, st, cur, NTOK_X*DD);
    ln(cur, 10, lnbuf, NTOK_X);
    gemm(lnbuf, nullptr, ffw1 + 2*DD*DFF, ffb1 + 2*DFF, nullptr, nullptr, ffh, NTOK_X, DFF, DD, 1);
    gemm(ffh, nullptr, ffw2 + 2*DFF*DD, ffb2 + 2*DD, cur, nullptr, out, NTOK_X, DD, DFF, 0);

    #undef AW
    #undef ABI
}

// round 4
// speedup vs baseline: 1.9672x; 1.7283x over previous
#include <cuda_runtime.h>
#include <math.h>
#include <stdint.h>

// ---------------- problem constants ----------------
#define BB   16
#define TTRG 64
#define TT   64
#define SS   49
#define DD   512
#define DFF  2048
#define HH   8
#define NTOK_X    (BB*TTRG)          // 1024
#define NTOK_VFT  (BB*TT*SS)         // 50176
#define NTOK_SOUT (BB*TT*TTRG)       // 65536

// ---------------- scratch ----------------
__device__ float g_cur [NTOK_X*DD];
__device__ float g_ln  [NTOK_X*DD];
__device__ float g_q   [NTOK_X*DD];
__device__ float g_ks  [2048*DD];
__device__ float g_vs  [2048*DD];
__device__ float g_attn[NTOK_X*DD];
__device__ float g_ts  [NTOK_X*DD];
__device__ float g_st  [NTOK_X*DD];
__device__ float g_ffh [NTOK_X*DFF];
__device__ float g_big0[NTOK_SOUT*DD];
__device__ float g_big1[NTOK_SOUT*DD];
__device__ float g_big2[NTOK_SOUT*DD];
__device__ float g_big3[NTOK_SOUT*DD];
__device__ int   g_map_perm[NTOK_VFT];
__device__ int   g_map_pt  [NTOK_VFT];
__device__ int   g_map_ps  [NTOK_SOUT];
__device__ int   g_res_t   [NTOK_VFT];
__device__ int   g_res_s   [NTOK_SOUT];

// ---------------- map builders ----------------
__global__ void build_swap(int* map, int A, int Bd, int Cd) {
    int m = blockIdx.x*256 + threadIdx.x;
    int tot = A*Bd*Cd;
    if (m < tot) {
        int c = m % Cd;
        int b = (m / Cd) % Bd;
        int a = m / (Cd*Bd);
        map[m] = (a*Cd + c)*Bd + b;
    }
}
__global__ void build_res(int* map, int tot, int p, int q) {
    int m = blockIdx.x*256 + threadIdx.x;
    if (m < tot) map[m] = (m/p)*q + (m % q);
}

// ---------------- layernorm (D=512) ----------------
__global__ __launch_bounds__(128) void ln_kernel(const float* __restrict__ in,
                                                 const float* __restrict__ gamma,
                                                 const float* __restrict__ beta,
                                                 float* __restrict__ out) {
    int row = blockIdx.x;
    int tid = threadIdx.x;
    const float4* p = reinterpret_cast<const float4*>(in + (long)row*DD);
    float4 v = p[tid];
    float s = v.x + v.y + v.z + v.w;
    float q = v.x*v.x + v.y*v.y + v.z*v.z + v.w*v.w;
    #pragma unroll
    for (int o = 16; o; o >>= 1) {
        s += __shfl_xor_sync(0xffffffffu, s, o);
        q += __shfl_xor_sync(0xffffffffu, q, o);
    }
    __shared__ float ssum[4], ssq[4];
    int warp = tid >> 5, lane = tid & 31;
    if (lane == 0) { ssum[warp] = s; ssq[warp] = q; }
    __syncthreads();
    __shared__ float smean, sinv;
    if (tid == 0) {
        float S = ssum[0]+ssum[1]+ssum[2]+ssum[3];
        float Q = ssq[0]+ssq[1]+ssq[2]+ssq[3];
        float mean = S * (1.0f/DD);
        float var  = Q * (1.0f/DD) - mean*mean;
        float sd   = sqrtf(fmaxf(var, 0.0f));
        smean = mean;
        sinv  = 1.0f / (sd + 1e-6f);
    }
    __syncthreads();
    float mean = smean, inv = sinv;
    float4 gv = reinterpret_cast<const float4*>(gamma)[tid];
    float4 bv = reinterpret_cast<const float4*>(beta)[tid];
    float4 o;
    o.x = gv.x*(v.x-mean)*inv + bv.x;
    o.y = gv.y*(v.y-mean)*inv + bv.y;
    o.z = gv.z*(v.z-mean)*inv + bv.z;
    o.w = gv.w*(v.w-mean)*inv + bv.w;
    reinterpret_cast<float4*>(out + (long)row*DD)[tid] = o;
}

// ---------------- small SGEMM (64x64 tile) for modest M ----------------
__global__ __launch_bounds__(256) void sgemm_kernel(
    const float* __restrict__ A, const int* __restrict__ amap,
    const float* __restrict__ W, const float* __restrict__ bias,
    const float* __restrict__ R, const int* __restrict__ rmap,
    float* __restrict__ C, int M, int N, int K, int relu)
{
    __shared__ float As[16][68];
    __shared__ float Ws[16][64];
    __shared__ int rowm[64];
    int tid = threadIdx.x;
    int m0 = blockIdx.y << 6, n0 = blockIdx.x << 6;
    if (tid < 64) rowm[tid] = amap ? amap[m0 + tid] : (m0 + tid);
    __syncthreads();
    int ty = tid >> 4, tx = tid & 15;
    float acc[16];
    #pragma unroll
    for (int u = 0; u < 16; u++) acc[u] = 0.0f;

    for (int k0 = 0; k0 < K; k0 += 16) {
        #pragma unroll
        for (int r = 0; r < 4; r++) {
            int idx = tid + (r << 8);
            int i  = idx >> 4, kk = idx & 15;
            As[kk][i] = A[rowm[i]*K + k0 + kk];
            int kk2 = idx >> 6, j = idx & 63;
            Ws[kk2][j] = W[(k0 + kk2)*N + n0 + j];
        }
        __syncthreads();
        #pragma unroll
        for (int kk = 0; kk < 16; kk++) {
            float4 b = *reinterpret_cast<const float4*>(&Ws[kk][tx << 2]);
            float a0 = As[kk][(ty<<2)+0];
            float a1 = As[kk][(ty<<2)+1];
            float a2 = As[kk][(ty<<2)+2];
            float a3 = As[kk][(ty<<2)+3];
            acc[ 0] += a0*b.x; acc[ 1] += a0*b.y; acc[ 2] += a0*b.z; acc[ 3] += a0*b.w;
            acc[ 4] += a1*b.x; acc[ 5] += a1*b.y; acc[ 6] += a1*b.z; acc[ 7] += a1*b.w;
            acc[ 8] += a2*b.x; acc[ 9] += a2*b.y; acc[10] += a2*b.z; acc[11] += a2*b.w;
            acc[12] += a3*b.x; acc[13] += a3*b.y; acc[14] += a3*b.z; acc[15] += a3*b.w;
        }
        __syncthreads();
    }
    #pragma unroll
    for (int r = 0; r < 4; r++) {
        int m = m0 + (ty<<2) + r;
        int rbase = 0;
        if (R) rbase = (rmap ? rmap[m] : m) * N;
        #pragma unroll
        for (int c = 0; c < 4; c++) {
            int n = n0 + (tx<<2) + c;
            float v = acc[r*4 + c];
            if (bias) v += bias[n];
            if (relu) v = fmaxf(v, 0.0f);
            if (R)    v += R[rbase + n];
            C[m*N + n] = v;
        }
    }
}

// ---------------- tf32 tensor-core GEMM (128x128 tile, Kc=16, double-buffered) ----
// Requires M%128==0, N%128==0, K%16==0.
__device__ __forceinline__ float tf32r(float x) {
    uint32_t u;
    asm("cvt.rna.tf32.f32 %0, %1;" : "=r"(u) : "f"(x));
    return __uint_as_float(u);
}
__device__ __forceinline__ void mma_tf32(float* c, const uint32_t* a, const uint32_t* b) {
    asm volatile("mma.sync.aligned.m16n8k8.row.col.f32.tf32.tf32.f32 "
        "{%0,%1,%2,%3}, {%4,%5,%6,%7}, {%8,%9}, {%0,%1,%2,%3};"
        : "+f"(c[0]), "+f"(c[1]), "+f"(c[2]), "+f"(c[3])
        : "r"(a[0]), "r"(a[1]), "r"(a[2]), "r"(a[3]), "r"(b[0]), "r"(b[1]));
}

#define TCP 136  // smem stride pad: multiple of 4 (float4-aligned) and 136%32==8 -> conflict-free fragment reads

__global__ __launch_bounds__(256, 2) void sgemm_tc_kernel(
    const float* __restrict__ A, const int* __restrict__ amap,
    const float* __restrict__ W, const float* __restrict__ bias,
    const float* __restrict__ R, const int* __restrict__ rmap,
    float* __restrict__ C, int M, int N, int K, int relu)
{
    __shared__ float As[2][16][TCP];
    __shared__ float Bs[2][16][TCP];
    __shared__ int rowm[128];
    int tid = threadIdx.x;
    int m0 = blockIdx.y << 7, n0 = blockIdx.x << 7;
    if (tid < 128) rowm[tid] = amap ? amap[m0 + tid] : (m0 + tid);
    __syncthreads();

    int wid = tid >> 5, lane = tid & 31;
    int warp_m = wid >> 2, warp_n = wid & 3;   // 2 x 4 warps -> 64 x 32 per warp
    int gr = lane >> 2, gc = lane & 3;

    // global load assignments
    int arow = tid >> 1, ak = (tid & 1) << 3;              // 8 k-floats each
    const float* aptr = A + (long)rowm[arow]*K + ak;
    int bk = tid >> 5, bn = (lane) << 2;                   // two k-rows (bk, bk+8)
    const float* bptr = W + (long)bk*N + n0 + bn;

    float acc[4][4][4];
    #pragma unroll
    for (int i = 0; i < 4; i++)
        #pragma unroll
        for (int j = 0; j < 4; j++)
            #pragma unroll
            for (int u = 0; u < 4; u++) acc[i][j][u] = 0.0f;

    // preload chunk 0
    float4 a0 = *reinterpret_cast<const float4*>(aptr);
    float4 a1 = *reinterpret_cast<const float4*>(aptr + 4);
    float4 b0 = *reinterpret_cast<const float4*>(bptr);
    float4 b1 = *reinterpret_cast<const float4*>(bptr + (long)8*N);
    {
        As[0][ak+0][arow] = tf32r(a0.x); As[0][ak+1][arow] = tf32r(a0.y);
        As[0][ak+2][arow] = tf32r(a0.z); As[0][ak+3][arow] = tf32r(a0.w);
        As[0][ak+4][arow] = tf32r(a1.x); As[0][ak+5][arow] = tf32r(a1.y);
        As[0][ak+6][arow] = tf32r(a1.z); As[0][ak+7][arow] = tf32r(a1.w);
        float4 c0 = make_float4(tf32r(b0.x), tf32r(b0.y), tf32r(b0.z), tf32r(b0.w));
        float4 c1 = make_float4(tf32r(b1.x), tf32r(b1.y), tf32r(b1.z), tf32r(b1.w));
        *reinterpret_cast<float4*>(&Bs[0][bk][bn])   = c0;
        *reinterpret_cast<float4*>(&Bs[0][bk+8][bn]) = c1;
    }
    __syncthreads();

    int buf = 0;
    for (int k0 = 0; k0 < K; k0 += 16) {
        bool has_next = (k0 + 16) < K;
        if (has_next) {
            a0 = *reinterpret_cast<const float4*>(aptr + k0 + 16);
            a1 = *reinterpret_cast<const float4*>(aptr + k0 + 20);
            b0 = *reinterpret_cast<const float4*>(bptr + (long)(k0 + 16)*N);
            b1 = *reinterpret_cast<const float4*>(bptr + (long)(k0 + 24)*N);
        }
        #pragma unroll
        for (int ks = 0; ks < 2; ks++) {
            int kb = ks << 3;
            uint32_t af[4][4], bf[4][2];
            #pragma unroll
            for (int mt = 0; mt < 4; mt++) {
                int mb = (warp_m << 6) + (mt << 4) + gr;
                af[mt][0] = __float_as_uint(As[buf][kb+gc  ][mb]);
                af[mt][1] = __float_as_uint(As[buf][kb+gc  ][mb+8]);
                af[mt][2] = __float_as_uint(As[buf][kb+gc+4][mb]);
                af[mt][3] = __float_as_uint(As[buf][kb+gc+4][mb+8]);
            }
            #pragma unroll
            for (int nt = 0; nt < 4; nt++) {
                int nb = (warp_n << 5) + (nt << 3) + gr;
                bf[nt][0] = __float_as_uint(Bs[buf][kb+gc  ][nb]);
                bf[nt][1] = __float_as_uint(Bs[buf][kb+gc+4][nb]);
            }
            #pragma unroll
            for (int mt = 0; mt < 4; mt++)
                #pragma unroll
                for (int nt = 0; nt < 4; nt++)
                    mma_tf32(acc[mt][nt], af[mt], bf[nt]);
        }
        if (has_next) {
            int nb2 = buf ^ 1;
            As[nb2][ak+0][arow] = tf32r(a0.x); As[nb2][ak+1][arow] = tf32r(a0.y);
            As[nb2][ak+2][arow] = tf32r(a0.z); As[nb2][ak+3][arow] = tf32r(a0.w);
            As[nb2][ak+4][arow] = tf32r(a1.x); As[nb2][ak+5][arow] = tf32r(a1.y);
            As[nb2][ak+6][arow] = tf32r(a1.z); As[nb2][ak+7][arow] = tf32r(a1.w);
            float4 c0 = make_float4(tf32r(b0.x), tf32r(b0.y), tf32r(b0.z), tf32r(b0.w));
            float4 c1 = make_float4(tf32r(b1.x), tf32r(b1.y), tf32r(b1.z), tf32r(b1.w));
            *reinterpret_cast<float4*>(&Bs[nb2][bk][bn])   = c0;
            *reinterpret_cast<float4*>(&Bs[nb2][bk+8][bn]) = c1;
        }
        __syncthreads();
        buf ^= 1;
    }

    // epilogue
    #pragma unroll
    for (int mt = 0; mt < 4; mt++) {
        #pragma unroll
        for (int half = 0; half < 2; half++) {
            int m = m0 + (warp_m << 6) + (mt << 4) + gr + (half << 3);
            long rbase = 0;
            if (R) rbase = (long)(rmap ? rmap[m] : m) * N;
            #pragma unroll
            for (int nt = 0; nt < 4; nt++) {
                int n = n0 + (warp_n << 5) + (nt << 3) + (gc << 1);
                float v0 = acc[mt][nt][half*2 + 0];
                float v1 = acc[mt][nt][half*2 + 1];
                if (bias) { v0 += bias[n]; v1 += bias[n+1]; }
                if (relu) { v0 = fmaxf(v0, 0.0f); v1 = fmaxf(v1, 0.0f); }
                if (R) {
                    float2 rv = *reinterpret_cast<const float2*>(R + rbase + n);
                    v0 += rv.x; v1 += rv.y;
                }
                *reinterpret_cast<float2*>(C + (long)m*N + n) = make_float2(v0, v1);
            }
        }
    }
}

// ---------------- batched multihead attention (dk=64) ----------------
#define KVP 68
__global__ __launch_bounds__(256) void attn_kernel(
    const float* __restrict__ Q, const float* __restrict__ Kg,
    const float* __restrict__ Vg, float* __restrict__ O,
    int Lq, int Lk, int q_group,
    const int* __restrict__ mask, int mask_mode, int mask_div)
{
    extern __shared__ float sm[];
    float* sQ  = sm;
    float* sKV = sm + Lq*64;
    float* sS  = sKV + 32*KVP;
    int batch = blockIdx.x, h = blockIdx.y;
    int tid = threadIdx.x;
    int qbase = (batch / q_group) * Lq;
    int LkP = Lk + 1;

    for (int idx = tid; idx < Lq*64; idx += 256) {
        int i = idx >> 6, d = idx & 63;
        sQ[idx] = Q[(qbase + i)*DD + h*64 + d];
    }
    for (int jt = 0; jt < Lk; jt += 32) {
        __syncthreads();
        for (int idx = tid; idx < 32*64; idx += 256) {
            int j = idx >> 6, d = idx & 63;
            int jj = jt + j;
            sKV[j*KVP + d] = (jj < Lk) ? Kg[(batch*Lk + jj)*DD + h*64 + d] : 0.0f;
        }
        __syncthreads();
        for (int idx = tid; idx < Lq*32; idx += 256) {
            int i = idx >> 5, j = idx & 31;
            int jj = jt + j;
            if (jj < Lk) {
                const float4* q4 = reinterpret_cast<const float4*>(sQ + i*64);
                const float4* k4 = reinterpret_cast<const float4*>(sKV + j*KVP);
                float s = 0.0f;
                #pragma unroll
                for (int d = 0; d < 16; d++) {
                    float4 a = q4[d], b = k4[d];
                    s += a.x*b.x + a.y*b.y + a.z*b.z + a.w*b.w;
                }
                s *= 0.125f;
                if (mask_mode == 1) {
                    if (mask[(batch*Lq + i)*Lk + jj] == 0) s = -1e9f;
                } else if (mask_mode == 2) {
                    if (mask[(batch/mask_div)*Lk + jj] == 0) s = -1e9f;
                }
                sS[i*LkP + jj] = s;
            }
        }
    }
    __syncthreads();
    int warp = tid >> 5, lane = tid & 31;
    for (int i = warp; i < Lq; i += 8) {
        float m = -3.4e38f;
        for (int j = lane; j < Lk; j += 32) m = fmaxf(m, sS[i*LkP + j]);
        #pragma unroll
        for (int o = 16; o; o >>= 1) m = fmaxf(m, __shfl_xor_sync(0xffffffffu, m, o));
        float sum = 0.0f;
        for (int j = lane; j < Lk; j += 32) {
            float e = __expf(sS[i*LkP + j] - m);
            sS[i*LkP + j] = e;
            sum += e;
        }
        #pragma unroll
        for (int o = 16; o; o >>= 1) sum += __shfl_xor_sync(0xffffffffu, sum, o);
        float inv = 1.0f / sum;
        for (int j = lane; j < Lk; j += 32) sS[i*LkP + j] *= inv;
    }
    if (Lq == 1) {
        float acc = 0.0f;
        int d = tid;
        for (int jt = 0; jt < Lk; jt += 32) {
            __syncthreads();
            for (int idx = tid; idx < 32*64; idx += 256) {
                int j = idx >> 6, dd = idx & 63;
                int jj = jt + j;
                sKV[j*KVP + dd] = (jj < Lk) ? Vg[(batch*Lk + jj)*DD + h*64 + dd] : 0.0f;
            }
            __syncthreads();
            if (d < 64) {
                int lim = min(32, Lk - jt);
                for (int j = 0; j < lim; j++) acc += sS[jt + j] * sKV[j*KVP + d];
            }
        }
        if (d < 64) O[batch*DD + h*64 + d] = acc;
    } else {
        int i = tid >> 2, dg = tid & 3;
        float acc[16];
        #pragma unroll
        for (int u = 0; u < 16; u++) acc[u] = 0.0f;
        for (int jt = 0; jt < Lk; jt += 32) {
            __syncthreads();
            for (int idx = tid; idx < 32*64; idx += 256) {
                int j = idx >> 6, dd = idx & 63;
                int jj = jt + j;
                sKV[j*KVP + dd] = (jj < Lk) ? Vg[(batch*Lk + jj)*DD + h*64 + dd] : 0.0f;
            }
            __syncthreads();
            if (i < Lq) {
                int lim = min(32, Lk - jt);
                for (int j = 0; j < lim; j++) {
                    float a = sS[i*LkP + jt + j];
                    const float4* v4 = reinterpret_cast<const float4*>(sKV + j*KVP + dg*16);
                    #pragma unroll
                    for (int u4 = 0; u4 < 4; u4++) {
                        float4 b = v4[u4];
                        acc[u4*4+0] += a*b.x;
                        acc[u4*4+1] += a*b.y;
                        acc[u4*4+2] += a*b.z;
                        acc[u4*4+3] += a*b.w;
                    }
                }
            }
        }
        if (i < Lq) {
            int d0 = dg*16;
            float* ob = O + (long)(batch*Lq + i)*DD + h*64 + d0;
            #pragma unroll
            for (int u4 = 0; u4 < 4; u4++) {
                float4 v = make_float4(acc[u4*4+0], acc[u4*4+1], acc[u4*4+2], acc[u4*4+3]);
                *reinterpret_cast<float4*>(ob + u4*4) = v;
            }
        }
    }
}

// ---------------- elementwise add ----------------
__global__ void add_kernel(const float* __restrict__ a, const float* __restrict__ b,
                           float* __restrict__ c, int n) {
    int i = blockIdx.x*256 + threadIdx.x;
    if (i < n) c[i] = a[i] + b[i];
}

// ---------------- host ----------------
static float* sym_f(const void* s) { void* p = nullptr; cudaGetSymbolAddress(&p, s); return (float*)p; }
static int*   sym_i(const void* s) { void* p = nullptr; cudaGetSymbolAddress(&p, s); return (int*)p; }

extern "C" void kernel_launch(void* const* d_in, const int* in_sizes, int n_in,
                              void* d_out, int out_size) {
    const float* x    = (const float*)d_in[0];
    const float* vft  = (const float*)d_in[1];
    const float* his  = (const float*)d_in[2];
    const float* cap  = (const float*)d_in[3];
    const float* qry  = (const float*)d_in[4];
    const int* trg_m  = (const int*)d_in[5];
    const int* his_m  = (const int*)d_in[6];
    const int* cap_m  = (const int*)d_in[7];
    const int* qry_m  = (const int*)d_in[8];
    const int* tmp_m  = (const int*)d_in[9];
    const float* attw = (const float*)d_in[10];
    const float* attb = (const float*)d_in[11];
    const float* ffw1 = (const float*)d_in[12];
    const float* ffb1 = (const float*)d_in[13];
    const float* ffw2 = (const float*)d_in[14];
    const float* ffb2 = (const float*)d_in[15];
    const float* lng  = (const float*)d_in[16];
    const float* lnb  = (const float*)d_in[17];
    float* out = (float*)d_out;

    float* cur   = sym_f(g_cur);
    float* lnbuf = sym_f(g_ln);
    float* qb    = sym_f(g_q);
    float* ks    = sym_f(g_ks);
    float* vs    = sym_f(g_vs);
    float* ab    = sym_f(g_attn);
    float* ts    = sym_f(g_ts);
    float* st    = sym_f(g_st);
    float* ffh   = sym_f(g_ffh);
    float* big0  = sym_f(g_big0);
    float* big1  = sym_f(g_big1);
    float* big2  = sym_f(g_big2);
    float* big3  = sym_f(g_big3);
    int* map_perm = sym_i(g_map_perm);
    int* map_pt   = sym_i(g_map_pt);
    int* map_ps   = sym_i(g_map_ps);
    int* res_t    = sym_i(g_res_t);
    int* res_s    = sym_i(g_res_s);

    cudaFuncSetAttribute((const void*)attn_kernel,
                         cudaFuncAttributeMaxDynamicSharedMemorySize, 64*1024);

    #define AW(i,j) (attw + ((i)*4+(j))*DD*DD)
    #define ABI(i,j) (attb + ((i)*4+(j))*DD)

    auto gemm = [](const float* A, const int* amap, const float* W, const float* bias,
                   const float* R, const int* rmap, float* C, int M, int N, int K, int relu) {
        if (M >= 4096) {
            dim3 grid(N/128, M/128);
            sgemm_tc_kernel<<<grid, 256>>>(A, amap, W, bias, R, rmap, C, M, N, K, relu);
        } else {
            dim3 grid(N/64, M/64);
            sgemm_kernel<<<grid, 256>>>(A, amap, W, bias, R, rmap, C, M, N, K, relu);
        }
    };
    auto attn = [](const float* Q, const float* K, const float* V, float* O,
                   int NB, int Lq, int Lk, int qg, const int* mask, int mode, int mdiv) {
        size_t sh = (size_t)(Lq*64 + 32*KVP + Lq*(Lk+1)) * sizeof(float);
        attn_kernel<<<dim3(NB, HH), 256, sh>>>(Q, K, V, O, Lq, Lk, qg, mask, mode, mdiv);
    };
    auto ln = [&](const float* in, int li, float* o, int rows) {
        ln_kernel<<<rows, 128>>>(in, lng + li*DD, lnb + li*DD, o);
    };

    // maps
    build_swap<<<(NTOK_VFT+255)/256, 256>>>(map_perm, BB, SS, TT);
    build_swap<<<(NTOK_VFT+255)/256, 256>>>(map_pt,   BB, TTRG, SS);
    build_swap<<<(NTOK_SOUT+255)/256, 256>>>(map_ps,  BB, TTRG, TT);
    build_res <<<(NTOK_VFT+255)/256, 256>>>(res_t, NTOK_VFT, SS*TT, TTRG);
    build_res <<<(NTOK_SOUT+255)/256, 256>>>(res_s, NTOK_SOUT, TT*TTRG, TTRG);

    // ---- mha0: causal self-attention ----
    ln(x, 0, lnbuf, NTOK_X);
    gemm(lnbuf, nullptr, AW(0,0), ABI(0,0), nullptr, nullptr, qb, NTOK_X, DD, DD, 0);
    gemm(lnbuf, nullptr, AW(0,1), ABI(0,1), nullptr, nullptr, ks, NTOK_X, DD, DD, 0);
    gemm(lnbuf, nullptr, AW(0,2), ABI(0,2), nullptr, nullptr, vs, NTOK_X, DD, DD, 0);
    attn(qb, ks, vs, ab, BB, TTRG, TTRG, 1, trg_m, 1, 1);
    gemm(ab, nullptr, AW(0,3), ABI(0,3), x, nullptr, cur, NTOK_X, DD, DD, 0);

    // ---- mha1..3 ----
    {
        const float* kvsrc[3] = { his, cap, qry };
        const int    kvrows[3] = { BB*128, BB*64, BB*32 };
        const int    Lks[3]    = { 128, 64, 32 };
        const int*   masks[3]  = { his_m, cap_m, qry_m };
        for (int a = 0; a < 3; a++) {
            int wi = a + 1;
            ln(cur, wi, lnbuf, NTOK_X);
            gemm(lnbuf, nullptr, AW(wi,0), ABI(wi,0), nullptr, nullptr, qb, NTOK_X, DD, DD, 0);
            gemm(kvsrc[a], nullptr, AW(wi,1), ABI(wi,1), nullptr, nullptr, ks, kvrows[a], DD, DD, 0);
            gemm(kvsrc[a], nullptr, AW(wi,2), ABI(wi,2), nullptr, nullptr, vs, kvrows[a], DD, DD, 0);
            attn(qb, ks, vs, ab, BB, TTRG, Lks[a], 1, masks[a], 2, 1);
            gemm(ab, nullptr, AW(wi,3), ABI(wi,3), cur, nullptr, cur, NTOK_X, DD, DD, 0);
        }
    }

    // ---- temporal2spatial: mha4 ----
    ln(cur, 4, lnbuf, NTOK_X);
    gemm(lnbuf, nullptr, AW(4,0), ABI(4,0), nullptr, nullptr, qb, NTOK_X, DD, DD, 0);
    gemm(vft, map_perm, AW(4,1), ABI(4,1), nullptr, nullptr, big0, NTOK_VFT, DD, DD, 0);
    gemm(vft, map_perm, AW(4,2), ABI(4,2), nullptr, nullptr, big1, NTOK_VFT, DD, DD, 0);
    attn(qb, big0, big1, big2, BB*SS, TTRG, TT, SS, tmp_m, 2, SS);
    gemm(big2, nullptr, AW(4,3), ABI(4,3), cur, res_t, big3, NTOK_VFT, DD, DD, 0);

    // ---- mha5 ----
    ln(cur, 5, lnbuf, NTOK_X);
    gemm(lnbuf, nullptr, AW(5,0), ABI(5,0), nullptr, nullptr, qb, NTOK_X, DD, DD, 0);
    gemm(big3, map_pt, AW(5,1), ABI(5,1), nullptr, nullptr, big0, NTOK_VFT, DD, DD, 0);
    gemm(big3, map_pt, AW(5,2), ABI(5,2), nullptr, nullptr, big1, NTOK_VFT, DD, DD, 0);
    attn(qb, big0, big1, ab, NTOK_X, 1, SS, 1, nullptr, 0, 1);
    gemm(ab, nullptr, AW(5,3), ABI(5,3), cur, nullptr, ts, NTOK_X, DD, DD, 0);
    // ffn0
    ln(ts, 6, lnbuf, NTOK_X);
    gemm(lnbuf, nullptr, ffw1 + 0*DD*DFF, ffb1 + 0*DFF, nullptr, nullptr, ffh, NTOK_X, DFF, DD, 1);
    gemm(ffh, nullptr, ffw2 + 0*DFF*DD, ffb2 + 0*DD, ts, nullptr, ts, NTOK_X, DD, DFF, 0);

    // ---- spatial2temporal: mha6 ----
    ln(cur, 7, lnbuf, NTOK_X);
    gemm(lnbuf, nullptr, AW(6,0), ABI(6,0), nullptr, nullptr, qb, NTOK_X, DD, DD, 0);
    gemm(vft, nullptr, AW(6,1), ABI(6,1), nullptr, nullptr, big0, NTOK_VFT, DD, DD, 0);
    gemm(vft, nullptr, AW(6,2), ABI(6,2), nullptr, nullptr, big1, NTOK_VFT, DD, DD, 0);
    attn(qb, big0, big1, big2, BB*TT, TTRG, SS, TT, nullptr, 0, 1);
    gemm(big2, nullptr, AW(6,3), ABI(6,3), cur, res_s, big3, NTOK_SOUT, DD, DD, 0);

    // ---- mha7 ----
    ln(cur, 8, lnbuf, NTOK_X);
    gemm(lnbuf, nullptr, AW(7,0), ABI(7,0), nullptr, nullptr, qb, NTOK_X, DD, DD, 0);
    gemm(big3, map_ps, AW(7,1), ABI(7,1), nullptr, nullptr, big0, NTOK_SOUT, DD, DD, 0);
    gemm(big3, map_ps, AW(7,2), ABI(7,2), nullptr, nullptr, big1, NTOK_SOUT, DD, DD, 0);
    attn(qb, big0, big1, ab, NTOK_X, 1, TT, 1, tmp_m, 2, TTRG);
    gemm(ab, nullptr, AW(7,3), ABI(7,3), cur, nullptr, st, NTOK_X, DD, DD, 0);
    // ffn1
    ln(st, 9, lnbuf, NTOK_X);
    gemm(lnbuf, nullptr, ffw1 + 1*DD*DFF, ffb1 + 1*DFF, nullptr, nullptr, ffh, NTOK_X, DFF, DD, 1);
    gemm(ffh, nullptr, ffw2 + 1*DFF*DD, ffb2 + 1*DD, st, nullptr, st, NTOK_X, DD, DFF, 0);

    // ---- combine + ffn2 ----
    add_kernel<<<(NTOK_X*DD + 255)/256, 256>>>(ts, st, cur, NTOK_X*DD);
    ln(cur, 10, lnbuf, NTOK_X);
    gemm(lnbuf, nullptr, ffw1 + 2*DD*DFF, ffb1 + 2*DFF, nullptr, nullptr, ffh, NTOK_X, DFF, DD, 1);
    gemm(ffh, nullptr, ffw2 + 2*DFF*DD, ffb2 + 2*DD, cur, nullptr, out, NTOK_X, DD, DFF, 0);

    #undef AW
    #undef ABI
}

// round 5
// speedup vs baseline: 2.9531x; 1.5012x over previous
#include <cuda_runtime.h>
#include <math.h>
#include <stdint.h>

// ---------------- problem constants ----------------
#define BB   16
#define TTRG 64
#define TT   64
#define SS   49
#define DD   512
#define DFF  2048
#define HH   8
#define NTOK_X    (BB*TTRG)          // 1024
#define NTOK_VFT  (BB*TT*SS)         // 50176
#define NTOK_SOUT (BB*TT*TTRG)       // 65536

// ---------------- scratch ----------------
__device__ float g_cur [NTOK_X*DD];
__device__ float g_ln  [NTOK_X*DD];
__device__ float g_q   [NTOK_X*DD];
__device__ float g_ks  [2048*DD];
__device__ float g_vs  [2048*DD];
__device__ float g_attn[NTOK_X*DD];
__device__ float g_ts  [NTOK_X*DD];
__device__ float g_st  [NTOK_X*DD];
__device__ float g_ffh [NTOK_X*DFF];
__device__ float g_big0[NTOK_SOUT*DD];
__device__ float g_big1[NTOK_SOUT*DD];
__device__ float g_big2[NTOK_SOUT*DD];
__device__ float g_big3[NTOK_SOUT*DD];
__device__ int   g_map_perm[NTOK_VFT];
__device__ int   g_map_pt  [NTOK_VFT];
__device__ int   g_map_ps  [NTOK_SOUT];
__device__ int   g_res_t   [NTOK_VFT];
__device__ int   g_res_s   [NTOK_SOUT];

// ---------------- map builders ----------------
__global__ void build_swap(int* map, int A, int Bd, int Cd) {
    int m = blockIdx.x*256 + threadIdx.x;
    int tot = A*Bd*Cd;
    if (m < tot) {
        int c = m % Cd;
        int b = (m / Cd) % Bd;
        int a = m / (Cd*Bd);
        map[m] = (a*Cd + c)*Bd + b;
    }
}
__global__ void build_res(int* map, int tot, int p, int q) {
    int m = blockIdx.x*256 + threadIdx.x;
    if (m < tot) map[m] = (m/p)*q + (m % q);
}

// ---------------- layernorm (D=512) ----------------
__global__ __launch_bounds__(128) void ln_kernel(const float* __restrict__ in,
                                                 const float* __restrict__ gamma,
                                                 const float* __restrict__ beta,
                                                 float* __restrict__ out) {
    int row = blockIdx.x;
    int tid = threadIdx.x;
    const float4* p = reinterpret_cast<const float4*>(in + (long)row*DD);
    float4 v = p[tid];
    float s = v.x + v.y + v.z + v.w;
    float q = v.x*v.x + v.y*v.y + v.z*v.z + v.w*v.w;
    #pragma unroll
    for (int o = 16; o; o >>= 1) {
        s += __shfl_xor_sync(0xffffffffu, s, o);
        q += __shfl_xor_sync(0xffffffffu, q, o);
    }
    __shared__ float ssum[4], ssq[4];
    int warp = tid >> 5, lane = tid & 31;
    if (lane == 0) { ssum[warp] = s; ssq[warp] = q; }
    __syncthreads();
    __shared__ float smean, sinv;
    if (tid == 0) {
        float S = ssum[0]+ssum[1]+ssum[2]+ssum[3];
        float Q = ssq[0]+ssq[1]+ssq[2]+ssq[3];
        float mean = S * (1.0f/DD);
        float var  = Q * (1.0f/DD) - mean*mean;
        float sd   = sqrtf(fmaxf(var, 0.0f));
        smean = mean;
        sinv  = 1.0f / (sd + 1e-6f);
    }
    __syncthreads();
    float mean = smean, inv = sinv;
    float4 gv = reinterpret_cast<const float4*>(gamma)[tid];
    float4 bv = reinterpret_cast<const float4*>(beta)[tid];
    float4 o;
    o.x = gv.x*(v.x-mean)*inv + bv.x;
    o.y = gv.y*(v.y-mean)*inv + bv.y;
    o.z = gv.z*(v.z-mean)*inv + bv.z;
    o.w = gv.w*(v.w-mean)*inv + bv.w;
    reinterpret_cast<float4*>(out + (long)row*DD)[tid] = o;
}

// ---------------- tf32 helpers ----------------
__device__ __forceinline__ float tf32r(float x) {
    uint32_t u;
    asm("cvt.rna.tf32.f32 %0, %1;" : "=r"(u) : "f"(x));
    return __uint_as_float(u);
}
__device__ __forceinline__ void mma_tf32(float* c, const uint32_t* a, const uint32_t* b) {
    asm volatile("mma.sync.aligned.m16n8k8.row.col.f32.tf32.tf32.f32 "
        "{%0,%1,%2,%3}, {%4,%5,%6,%7}, {%8,%9}, {%0,%1,%2,%3};"
        : "+f"(c[0]), "+f"(c[1]), "+f"(c[2]), "+f"(c[3])
        : "r"(a[0]), "r"(a[1]), "r"(a[2]), "r"(a[3]), "r"(b[0]), "r"(b[1]));
}

// ---------------- tf32 tensor-core GEMM (128x128 tile, Kc=16, double-buffered) ----
// Requires M%128==0, N%128==0, K%16==0.
#define TCP 136  // smem stride pad: float4-aligned, 136%32==8 -> conflict-free fragment reads

__global__ __launch_bounds__(256, 2) void sgemm_tc_kernel(
    const float* __restrict__ A, const int* __restrict__ amap,
    const float* __restrict__ W, const float* __restrict__ bias,
    const float* __restrict__ R, const int* __restrict__ rmap,
    float* __restrict__ C, int M, int N, int K, int relu)
{
    __shared__ float As[2][16][TCP];
    __shared__ float Bs[2][16][TCP];
    __shared__ int rowm[128];
    int tid = threadIdx.x;
    int m0 = blockIdx.y << 7, n0 = blockIdx.x << 7;
    if (tid < 128) rowm[tid] = amap ? amap[m0 + tid] : (m0 + tid);
    __syncthreads();

    int wid = tid >> 5, lane = tid & 31;
    int warp_m = wid >> 2, warp_n = wid & 3;   // 2 x 4 warps -> 64 x 32 per warp
    int gr = lane >> 2, gc = lane & 3;

    int arow = tid >> 1, ak = (tid & 1) << 3;
    const float* aptr = A + (long)rowm[arow]*K + ak;
    int bk = tid >> 5, bn = (lane) << 2;
    const float* bptr = W + (long)bk*N + n0 + bn;

    float acc[4][4][4];
    #pragma unroll
    for (int i = 0; i < 4; i++)
        #pragma unroll
        for (int j = 0; j < 4; j++)
            #pragma unroll
            for (int u = 0; u < 4; u++) acc[i][j][u] = 0.0f;

    float4 a0 = *reinterpret_cast<const float4*>(aptr);
    float4 a1 = *reinterpret_cast<const float4*>(aptr + 4);
    float4 b0 = *reinterpret_cast<const float4*>(bptr);
    float4 b1 = *reinterpret_cast<const float4*>(bptr + (long)8*N);
    {
        As[0][ak+0][arow] = tf32r(a0.x); As[0][ak+1][arow] = tf32r(a0.y);
        As[0][ak+2][arow] = tf32r(a0.z); As[0][ak+3][arow] = tf32r(a0.w);
        As[0][ak+4][arow] = tf32r(a1.x); As[0][ak+5][arow] = tf32r(a1.y);
        As[0][ak+6][arow] = tf32r(a1.z); As[0][ak+7][arow] = tf32r(a1.w);
        float4 c0 = make_float4(tf32r(b0.x), tf32r(b0.y), tf32r(b0.z), tf32r(b0.w));
        float4 c1 = make_float4(tf32r(b1.x), tf32r(b1.y), tf32r(b1.z), tf32r(b1.w));
        *reinterpret_cast<float4*>(&Bs[0][bk][bn])   = c0;
        *reinterpret_cast<float4*>(&Bs[0][bk+8][bn]) = c1;
    }
    __syncthreads();

    int buf = 0;
    for (int k0 = 0; k0 < K; k0 += 16) {
        bool has_next = (k0 + 16) < K;
        if (has_next) {
            a0 = *reinterpret_cast<const float4*>(aptr + k0 + 16);
            a1 = *reinterpret_cast<const float4*>(aptr + k0 + 20);
            b0 = *reinterpret_cast<const float4*>(bptr + (long)(k0 + 16)*N);
            b1 = *reinterpret_cast<const float4*>(bptr + (long)(k0 + 24)*N);
        }
        #pragma unroll
        for (int ks = 0; ks < 2; ks++) {
            int kb = ks << 3;
            uint32_t af[4][4], bf[4][2];
            #pragma unroll
            for (int mt = 0; mt < 4; mt++) {
                int mb = (warp_m << 6) + (mt << 4) + gr;
                af[mt][0] = __float_as_uint(As[buf][kb+gc  ][mb]);
                af[mt][1] = __float_as_uint(As[buf][kb+gc  ][mb+8]);
                af[mt][2] = __float_as_uint(As[buf][kb+gc+4][mb]);
                af[mt][3] = __float_as_uint(As[buf][kb+gc+4][mb+8]);
            }
            #pragma unroll
            for (int nt = 0; nt < 4; nt++) {
                int nb = (warp_n << 5) + (nt << 3) + gr;
                bf[nt][0] = __float_as_uint(Bs[buf][kb+gc  ][nb]);
                bf[nt][1] = __float_as_uint(Bs[buf][kb+gc+4][nb]);
            }
            #pragma unroll
            for (int mt = 0; mt < 4; mt++)
                #pragma unroll
                for (int nt = 0; nt < 4; nt++)
                    mma_tf32(acc[mt][nt], af[mt], bf[nt]);
        }
        if (has_next) {
            int nb2 = buf ^ 1;
            As[nb2][ak+0][arow] = tf32r(a0.x); As[nb2][ak+1][arow] = tf32r(a0.y);
            As[nb2][ak+2][arow] = tf32r(a0.z); As[nb2][ak+3][arow] = tf32r(a0.w);
            As[nb2][ak+4][arow] = tf32r(a1.x); As[nb2][ak+5][arow] = tf32r(a1.y);
            As[nb2][ak+6][arow] = tf32r(a1.z); As[nb2][ak+7][arow] = tf32r(a1.w);
            float4 c0 = make_float4(tf32r(b0.x), tf32r(b0.y), tf32r(b0.z), tf32r(b0.w));
            float4 c1 = make_float4(tf32r(b1.x), tf32r(b1.y), tf32r(b1.z), tf32r(b1.w));
            *reinterpret_cast<float4*>(&Bs[nb2][bk][bn])   = c0;
            *reinterpret_cast<float4*>(&Bs[nb2][bk+8][bn]) = c1;
        }
        __syncthreads();
        buf ^= 1;
    }

    #pragma unroll
    for (int mt = 0; mt < 4; mt++) {
        #pragma unroll
        for (int half = 0; half < 2; half++) {
            int m = m0 + (warp_m << 6) + (mt << 4) + gr + (half << 3);
            long rbase = 0;
            if (R) rbase = (long)(rmap ? rmap[m] : m) * N;
            #pragma unroll
            for (int nt = 0; nt < 4; nt++) {
                int n = n0 + (warp_n << 5) + (nt << 3) + (gc << 1);
                float v0 = acc[mt][nt][half*2 + 0];
                float v1 = acc[mt][nt][half*2 + 1];
                if (bias) { v0 += bias[n]; v1 += bias[n+1]; }
                if (relu) { v0 = fmaxf(v0, 0.0f); v1 = fmaxf(v1, 0.0f); }
                if (R) {
                    float2 rv = *reinterpret_cast<const float2*>(R + rbase + n);
                    v0 += rv.x; v1 += rv.y;
                }
                *reinterpret_cast<float2*>(C + (long)m*N + n) = make_float2(v0, v1);
            }
        }
    }
}

// ---------------- tensor-core attention, Lq=64, dk=64 ----------------
// grid (NB, H), 256 threads. LkPad = Lk rounded up to multiple of 32 (<=128).
// sQ[64][68], sKV[LkPad][68], sS[64][LkPad+4]
__global__ __launch_bounds__(256) void attn_tc_kernel(
    const float* __restrict__ Q, const float* __restrict__ Kg,
    const float* __restrict__ Vg, float* __restrict__ O,
    int Lk, int LkPad, int q_group,
    const int* __restrict__ mask, int mask_mode, int mask_div)
{
    extern __shared__ float sm[];
    float* sQ  = sm;                    // 64*68
    float* sKV = sm + 64*68;            // LkPad*68
    float* sS  = sKV + LkPad*68;        // 64*(LkPad+4)
    int batch = blockIdx.x, h = blockIdx.y;
    int tid = threadIdx.x;
    int qbase = (batch / q_group) * 64;
    int sp = LkPad + 4;

    int wid = tid >> 5, lane = tid & 31;
    int warp_m = wid >> 2, warp_n = wid & 3;
    int gr = lane >> 2, gc = lane & 3;
    int nw  = LkPad >> 2;   // per-warp score-col width
    int ntn = LkPad >> 5;   // score n-tiles per warp (1..4)

    // load Q, K (tf32)
    for (int idx = tid; idx < 64*64; idx += 256) {
        int i = idx >> 6, d = idx & 63;
        sQ[i*68 + d] = tf32r(Q[(qbase + i)*DD + h*64 + d]);
    }
    for (int idx = tid; idx < LkPad*64; idx += 256) {
        int j = idx >> 6, d = idx & 63;
        sKV[j*68 + d] = (j < Lk) ? tf32r(Kg[(long)(batch*Lk + j)*DD + h*64 + d]) : 0.0f;
    }
    __syncthreads();

    // scores: S[64][LkPad] = Q @ K^T
    {
        float acc[2][4][4];
        #pragma unroll
        for (int mt = 0; mt < 2; mt++)
            #pragma unroll
            for (int nt = 0; nt < 4; nt++)
                #pragma unroll
                for (int u = 0; u < 4; u++) acc[mt][nt][u] = 0.0f;

        for (int kb = 0; kb < 64; kb += 8) {
            uint32_t af[2][4];
            #pragma unroll
            for (int mt = 0; mt < 2; mt++) {
                int mr = warp_m*32 + mt*16 + gr;
                af[mt][0] = __float_as_uint(sQ[mr*68 + kb+gc]);
                af[mt][1] = __float_as_uint(sQ[(mr+8)*68 + kb+gc]);
                af[mt][2] = __float_as_uint(sQ[mr*68 + kb+gc+4]);
                af[mt][3] = __float_as_uint(sQ[(mr+8)*68 + kb+gc+4]);
            }
            for (int nt = 0; nt < ntn; nt++) {
                int nc = warp_n*nw + nt*8 + gr;
                uint32_t bf[2];
                bf[0] = __float_as_uint(sKV[nc*68 + kb+gc]);
                bf[1] = __float_as_uint(sKV[nc*68 + kb+gc+4]);
                mma_tf32(acc[0][nt], af[0], bf);
                mma_tf32(acc[1][nt], af[1], bf);
            }
        }
        #pragma unroll
        for (int mt = 0; mt < 2; mt++)
            for (int nt = 0; nt < ntn; nt++) {
                int row = warp_m*32 + mt*16 + gr;
                int col = warp_n*nw + nt*8 + (gc << 1);
                sS[row*sp + col]       = acc[mt][nt][0]*0.125f;
                sS[row*sp + col + 1]   = acc[mt][nt][1]*0.125f;
                sS[(row+8)*sp + col]   = acc[mt][nt][2]*0.125f;
                sS[(row+8)*sp + col+1] = acc[mt][nt][3]*0.125f;
            }
    }
    __syncthreads();

    // softmax rows (warp per row), mask, tf32-round probs, zero padding
    for (int i = wid; i < 64; i += 8) {
        float mx = -3.4e38f;
        for (int j = lane; j < Lk; j += 32) {
            float v = sS[i*sp + j];
            bool dead = false;
            if (mask_mode == 1) dead = (mask[(long)(batch*64 + i)*Lk + j] == 0);
            else if (mask_mode == 2) dead = (mask[(batch/mask_div)*Lk + j] == 0);
            if (dead) { v = -1e9f; sS[i*sp + j] = v; }
            mx = fmaxf(mx, v);
        }
        #pragma unroll
        for (int o = 16; o; o >>= 1) mx = fmaxf(mx, __shfl_xor_sync(0xffffffffu, mx, o));
        float sum = 0.0f;
        for (int j = lane; j < Lk; j += 32) {
            float e = __expf(sS[i*sp + j] - mx);
            sS[i*sp + j] = e;
            sum += e;
        }
        #pragma unroll
        for (int o = 16; o; o >>= 1) sum += __shfl_xor_sync(0xffffffffu, sum, o);
        float inv = 1.0f / sum;
        for (int j = lane; j < Lk; j += 32) sS[i*sp + j] = tf32r(sS[i*sp + j] * inv);
        for (int j = Lk + lane; j < LkPad; j += 32) sS[i*sp + j] = 0.0f;
    }

    // load V into sKV (overwrite K)
    for (int idx = tid; idx < LkPad*64; idx += 256) {
        int j = idx >> 6, d = idx & 63;
        sKV[j*68 + d] = (j < Lk) ? tf32r(Vg[(long)(batch*Lk + j)*DD + h*64 + d]) : 0.0f;
    }
    __syncthreads();

    // O = P @ V  (M=64, N=64, K=LkPad)
    {
        float acc[2][2][4];
        #pragma unroll
        for (int mt = 0; mt < 2; mt++)
            #pragma unroll
            for (int nt = 0; nt < 2; nt++)
                #pragma unroll
                for (int u = 0; u < 4; u++) acc[mt][nt][u] = 0.0f;

        for (int kb = 0; kb < LkPad; kb += 8) {
            uint32_t af[2][4];
            #pragma unroll
            for (int mt = 0; mt < 2; mt++) {
                int mr = warp_m*32 + mt*16 + gr;
                af[mt][0] = __float_as_uint(sS[mr*sp + kb+gc]);
                af[mt][1] = __float_as_uint(sS[(mr+8)*sp + kb+gc]);
                af[mt][2] = __float_as_uint(sS[mr*sp + kb+gc+4]);
                af[mt][3] = __float_as_uint(sS[(mr+8)*sp + kb+gc+4]);
            }
            #pragma unroll
            for (int nt = 0; nt < 2; nt++) {
                int nc = warp_n*16 + nt*8 + gr;
                uint32_t bf[2];
                bf[0] = __float_as_uint(sKV[(kb+gc)*68 + nc]);
                bf[1] = __float_as_uint(sKV[(kb+gc+4)*68 + nc]);
                mma_tf32(acc[0][nt], af[0], bf);
                mma_tf32(acc[1][nt], af[1], bf);
            }
        }
        #pragma unroll
        for (int mt = 0; mt < 2; mt++)
            #pragma unroll
            for (int nt = 0; nt < 2; nt++) {
                int i = warp_m*32 + mt*16 + gr;
                int d = warp_n*16 + nt*8 + (gc << 1);
                long base = (long)(batch*64 + i)*DD + h*64 + d;
                *reinterpret_cast<float2*>(O + base) =
                    make_float2(acc[mt][nt][0], acc[mt][nt][1]);
                *reinterpret_cast<float2*>(O + base + 8*DD) =
                    make_float2(acc[mt][nt][2], acc[mt][nt][3]);
            }
    }
}

// ---------------- fp32 attention for Lq=1 (mha5/mha7) ----------------
#define KVP 68
__global__ __launch_bounds__(256) void attn1_kernel(
    const float* __restrict__ Q, const float* __restrict__ Kg,
    const float* __restrict__ Vg, float* __restrict__ O,
    int Lk, const int* __restrict__ mask, int mask_mode, int mask_div)
{
    extern __shared__ float sm[];
    float* sQ  = sm;           // 64
    float* sKV = sm + 64;      // 32*KVP
    float* sS  = sKV + 32*KVP; // Lk
    int batch = blockIdx.x, h = blockIdx.y;
    int tid = threadIdx.x;

    if (tid < 64) sQ[tid] = Q[(long)batch*DD + h*64 + tid];
    for (int jt = 0; jt < Lk; jt += 32) {
        __syncthreads();
        for (int idx = tid; idx < 32*64; idx += 256) {
            int j = idx >> 6, d = idx & 63;
            int jj = jt + j;
            sKV[j*KVP + d] = (jj < Lk) ? Kg[(long)(batch*Lk + jj)*DD + h*64 + d] : 0.0f;
        }
        __syncthreads();
        if (tid < 32) {
            int jj = jt + tid;
            if (jj < Lk) {
                const float4* q4 = reinterpret_cast<const float4*>(sQ);
                const float4* k4 = reinterpret_cast<const float4*>(sKV + tid*KVP);
                float s = 0.0f;
                #pragma unroll
                for (int d = 0; d < 16; d++) {
                    float4 a = q4[d], b = k4[d];
                    s += a.x*b.x + a.y*b.y + a.z*b.z + a.w*b.w;
                }
                s *= 0.125f;
                if (mask_mode == 2 && mask[(batch/mask_div)*Lk + jj] == 0) s = -1e9f;
                sS[jj] = s;
            }
        }
    }
    __syncthreads();
    if (tid < 32) {
        float m = -3.4e38f;
        for (int j = tid; j < Lk; j += 32) m = fmaxf(m, sS[j]);
        #pragma unroll
        for (int o = 16; o; o >>= 1) m = fmaxf(m, __shfl_xor_sync(0xffffffffu, m, o));
        float sum = 0.0f;
        for (int j = tid; j < Lk; j += 32) {
            float e = __expf(sS[j] - m);
            sS[j] = e;
            sum += e;
        }
        #pragma unroll
        for (int o = 16; o; o >>= 1) sum += __shfl_xor_sync(0xffffffffu, sum, o);
        float inv = 1.0f / sum;
        for (int j = tid; j < Lk; j += 32) sS[j] *= inv;
    }
    float acc = 0.0f;
    for (int jt = 0; jt < Lk; jt += 32) {
        __syncthreads();
        for (int idx = tid; idx < 32*64; idx += 256) {
            int j = idx >> 6, dd = idx & 63;
            int jj = jt + j;
            sKV[j*KVP + dd] = (jj < Lk) ? Vg[(long)(batch*Lk + jj)*DD + h*64 + dd] : 0.0f;
        }
        __syncthreads();
        if (tid < 64) {
            int lim = min(32, Lk - jt);
            for (int j = 0; j < lim; j++) acc += sS[jt + j] * sKV[j*KVP + tid];
        }
    }
    if (tid < 64) O[(long)batch*DD + h*64 + tid] = acc;
}

// ---------------- elementwise add ----------------
__global__ void add_kernel(const float* __restrict__ a, const float* __restrict__ b,
                           float* __restrict__ c, int n) {
    int i = blockIdx.x*256 + threadIdx.x;
    if (i < n) c[i] = a[i] + b[i];
}

// ---------------- host ----------------
static float* sym_f(const void* s) { void* p = nullptr; cudaGetSymbolAddress(&p, s); return (float*)p; }
static int*   sym_i(const void* s) { void* p = nullptr; cudaGetSymbolAddress(&p, s); return (int*)p; }

extern "C" void kernel_launch(void* const* d_in, const int* in_sizes, int n_in,
                              void* d_out, int out_size) {
    const float* x    = (const float*)d_in[0];
    const float* vft  = (const float*)d_in[1];
    const float* his  = (const float*)d_in[2];
    const float* cap  = (const float*)d_in[3];
    const float* qry  = (const float*)d_in[4];
    const int* trg_m  = (const int*)d_in[5];
    const int* his_m  = (const int*)d_in[6];
    const int* cap_m  = (const int*)d_in[7];
    const int* qry_m  = (const int*)d_in[8];
    const int* tmp_m  = (const int*)d_in[9];
    const float* attw = (const float*)d_in[10];
    const float* attb = (const float*)d_in[11];
    const float* ffw1 = (const float*)d_in[12];
    const float* ffb1 = (const float*)d_in[13];
    const float* ffw2 = (const float*)d_in[14];
    const float* ffb2 = (const float*)d_in[15];
    const float* lng  = (const float*)d_in[16];
    const float* lnb  = (const float*)d_in[17];
    float* out = (float*)d_out;

    float* cur   = sym_f(g_cur);
    float* lnbuf = sym_f(g_ln);
    float* qb    = sym_f(g_q);
    float* ks    = sym_f(g_ks);
    float* vs    = sym_f(g_vs);
    float* ab    = sym_f(g_attn);
    float* ts    = sym_f(g_ts);
    float* st    = sym_f(g_st);
    float* ffh   = sym_f(g_ffh);
    float* big0  = sym_f(g_big0);
    float* big1  = sym_f(g_big1);
    float* big2  = sym_f(g_big2);
    float* big3  = sym_f(g_big3);
    int* map_perm = sym_i(g_map_perm);
    int* map_pt   = sym_i(g_map_pt);
    int* map_ps   = sym_i(g_map_ps);
    int* res_t    = sym_i(g_res_t);
    int* res_s    = sym_i(g_res_s);

    cudaFuncSetAttribute((const void*)attn_tc_kernel,
                         cudaFuncAttributeMaxDynamicSharedMemorySize, 120*1024);
    cudaFuncSetAttribute((const void*)attn1_kernel,
                         cudaFuncAttributeMaxDynamicSharedMemorySize, 32*1024);

    #define AW(i,j) (attw + ((i)*4+(j))*DD*DD)
    #define ABI(i,j) (attb + ((i)*4+(j))*DD)

    auto gemm = [](const float* A, const int* amap, const float* W, const float* bias,
                   const float* R, const int* rmap, float* C, int M, int N, int K, int relu) {
        dim3 grid(N/128, M/128);
        sgemm_tc_kernel<<<grid, 256>>>(A, amap, W, bias, R, rmap, C, M, N, K, relu);
    };
    auto attn = [](const float* Q, const float* K, const float* V, float* O,
                   int NB, int Lk, int qg, const int* mask, int mode, int mdiv) {
        int LkPad = (Lk + 31) & ~31;
        size_t sh = (size_t)(64*68 + LkPad*68 + 64*(LkPad+4)) * sizeof(float);
        attn_tc_kernel<<<dim3(NB, HH), 256, sh>>>(Q, K, V, O, Lk, LkPad, qg, mask, mode, mdiv);
    };
    auto attn1 = [](const float* Q, const float* K, const float* V, float* O,
                    int NB, int Lk, const int* mask, int mode, int mdiv) {
        size_t sh = (size_t)(64 + 32*KVP + Lk) * sizeof(float);
        attn1_kernel<<<dim3(NB, HH), 256, sh>>>(Q, K, V, O, Lk, mask, mode, mdiv);
    };
    auto ln = [&](const float* in, int li, float* o, int rows) {
        ln_kernel<<<rows, 128>>>(in, lng + li*DD, lnb + li*DD, o);
    };

    // maps
    build_swap<<<(NTOK_VFT+255)/256, 256>>>(map_perm, BB, SS, TT);
    build_swap<<<(NTOK_VFT+255)/256, 256>>>(map_pt,   BB, TTRG, SS);
    build_swap<<<(NTOK_SOUT+255)/256, 256>>>(map_ps,  BB, TTRG, TT);
    build_res <<<(NTOK_VFT+255)/256, 256>>>(res_t, NTOK_VFT, SS*TT, TTRG);
    build_res <<<(NTOK_SOUT+255)/256, 256>>>(res_s, NTOK_SOUT, TT*TTRG, TTRG);

    // ---- mha0: causal self-attention ----
    ln(x, 0, lnbuf, NTOK_X);
    gemm(lnbuf, nullptr, AW(0,0), ABI(0,0), nullptr, nullptr, qb, NTOK_X, DD, DD, 0);
    gemm(lnbuf, nullptr, AW(0,1), ABI(0,1), nullptr, nullptr, ks, NTOK_X, DD, DD, 0);
    gemm(lnbuf, nullptr, AW(0,2), ABI(0,2), nullptr, nullptr, vs, NTOK_X, DD, DD, 0);
    attn(qb, ks, vs, ab, BB, TTRG, 1, trg_m, 1, 1);
    gemm(ab, nullptr, AW(0,3), ABI(0,3), x, nullptr, cur, NTOK_X, DD, DD, 0);

    // ---- mha1..3 ----
    {
        const float* kvsrc[3] = { his, cap, qry };
        const int    kvrows[3] = { BB*128, BB*64, BB*32 };
        const int    Lks[3]    = { 128, 64, 32 };
        const int*   masks[3]  = { his_m, cap_m, qry_m };
        for (int a = 0; a < 3; a++) {
            int wi = a + 1;
            ln(cur, wi, lnbuf, NTOK_X);
            gemm(lnbuf, nullptr, AW(wi,0), ABI(wi,0), nullptr, nullptr, qb, NTOK_X, DD, DD, 0);
            gemm(kvsrc[a], nullptr, AW(wi,1), ABI(wi,1), nullptr, nullptr, ks, kvrows[a], DD, DD, 0);
            gemm(kvsrc[a], nullptr, AW(wi,2), ABI(wi,2), nullptr, nullptr, vs, kvrows[a], DD, DD, 0);
            attn(qb, ks, vs, ab, BB, Lks[a], 1, masks[a], 2, 1);
            gemm(ab, nullptr, AW(wi,3), ABI(wi,3), cur, nullptr, cur, NTOK_X, DD, DD, 0);
        }
    }

    // ---- temporal2spatial: mha4 ----
    ln(cur, 4, lnbuf, NTOK_X);
    gemm(lnbuf, nullptr, AW(4,0), ABI(4,0), nullptr, nullptr, qb, NTOK_X, DD, DD, 0);
    gemm(vft, map_perm, AW(4,1), ABI(4,1), nullptr, nullptr, big0, NTOK_VFT, DD, DD, 0);
    gemm(vft, map_perm, AW(4,2), ABI(4,2), nullptr, nullptr, big1, NTOK_VFT, DD, DD, 0);
    attn(qb, big0, big1, big2, BB*SS, TT, SS, tmp_m, 2, SS);
    gemm(big2, nullptr, AW(4,3), ABI(4,3), cur, res_t, big3, NTOK_VFT, DD, DD, 0);

    // ---- mha5 ----
    ln(cur, 5, lnbuf, NTOK_X);
    gemm(lnbuf, nullptr, AW(5,0), ABI(5,0), nullptr, nullptr, qb, NTOK_X, DD, DD, 0);
    gemm(big3, map_pt, AW(5,1), ABI(5,1), nullptr, nullptr, big0, NTOK_VFT, DD, DD, 0);
    gemm(big3, map_pt, AW(5,2), ABI(5,2), nullptr, nullptr, big1, NTOK_VFT, DD, DD, 0);
    attn1(qb, big0, big1, ab, NTOK_X, SS, nullptr, 0, 1);
    gemm(ab, nullptr, AW(5,3), ABI(5,3), cur, nullptr, ts, NTOK_X, DD, DD, 0);
    // ffn0
    ln(ts, 6, lnbuf, NTOK_X);
    gemm(lnbuf, nullptr, ffw1 + 0*DD*DFF, ffb1 + 0*DFF, nullptr, nullptr, ffh, NTOK_X, DFF, DD, 1);
    gemm(ffh, nullptr, ffw2 + 0*DFF*DD, ffb2 + 0*DD, ts, nullptr, ts, NTOK_X, DD, DFF, 0);

    // ---- spatial2temporal: mha6 ----
    ln(cur, 7, lnbuf, NTOK_X);
    gemm(lnbuf, nullptr, AW(6,0), ABI(6,0), nullptr, nullptr, qb, NTOK_X, DD, DD, 0);
    gemm(vft, nullptr, AW(6,1), ABI(6,1), nullptr, nullptr, big0, NTOK_VFT, DD, DD, 0);
    gemm(vft, nullptr, AW(6,2), ABI(6,2), nullptr, nullptr, big1, NTOK_VFT, DD, DD, 0);
    attn(qb, big0, big1, big2, BB*TT, SS, TT, nullptr, 0, 1);
    gemm(big2, nullptr, AW(6,3), ABI(6,3), cur, res_s, big3, NTOK_SOUT, DD, DD, 0);

    // ---- mha7 ----
    ln(cur, 8, lnbuf, NTOK_X);
    gemm(lnbuf, nullptr, AW(7,0), ABI(7,0), nullptr, nullptr, qb, NTOK_X, DD, DD, 0);
    gemm(big3, map_ps, AW(7,1), ABI(7,1), nullptr, nullptr, big0, NTOK_SOUT, DD, DD, 0);
    gemm(big3, map_ps, AW(7,2), ABI(7,2), nullptr, nullptr, big1, NTOK_SOUT, DD, DD, 0);
    attn1(qb, big0, big1, ab, NTOK_X, TT, tmp_m, 2, TTRG);
    gemm(ab, nullptr, AW(7,3), ABI(7,3), cur, nullptr, st, NTOK_X, DD, DD, 0);
    // ffn1
    ln(st, 9, lnbuf, NTOK_X);
    gemm(lnbuf, nullptr, ffw1 + 1*DD*DFF, ffb1 + 1*DFF, nullptr, nullptr, ffh, NTOK_X, DFF, DD, 1);
    gemm(ffh, nullptr, ffw2 + 1*DFF*DD, ffb2 + 1*DD, st, nullptr, st, NTOK_X, DD, DFF, 0);

    // ---- combine + ffn2 ----
    add_kernel<<<(NTOK_X*DD + 255)/256, 256>>>(ts, st, cur, NTOK_X*DD);
    ln(cur, 10, lnbuf, NTOK_X);
    gemm(lnbuf, nullptr, ffw1 + 2*DD*DFF, ffb1 + 2*DFF, nullptr, nullptr, ffh, NTOK_X, DFF, DD, 1);
    gemm(ffh, nullptr, ffw2 + 2*DFF*DD, ffb2 + 2*DD, cur, nullptr, out, NTOK_X, DD, DFF, 0);

    #undef AW
    #undef ABI
}

// round 6
// speedup vs baseline: 3.0476x; 1.0320x over previous
#include <cuda_runtime.h>
#include <math.h>
#include <stdint.h>

// ---------------- problem constants ----------------
#define BB   16
#define TTRG 64
#define TT   64
#define SS   49
#define DD   512
#define DFF  2048
#define HH   8
#define NTOK_X    (BB*TTRG)          // 1024
#define NTOK_VFT  (BB*TT*SS)         // 50176
#define NTOK_SOUT (BB*TT*TTRG)       // 65536

// ---------------- scratch ----------------
__device__ float g_cur [NTOK_X*DD];
__device__ float g_ln  [NTOK_X*DD];
__device__ float g_q   [NTOK_X*DD];
__device__ float g_ks  [2048*DD];
__device__ float g_vs  [2048*DD];
__device__ float g_attn[NTOK_X*DD];
__device__ float g_ts  [NTOK_X*DD];
__device__ float g_st  [NTOK_X*DD];
__device__ float g_ffh [NTOK_X*DFF];
__device__ float g_big0[NTOK_SOUT*DD];
__device__ float g_big1[NTOK_SOUT*DD];
__device__ float g_big2[NTOK_SOUT*DD];
__device__ float g_big3[NTOK_SOUT*DD];
__device__ float g_big4[NTOK_SOUT*DD];
__device__ float g_big5[NTOK_SOUT*DD];
__device__ int   g_map_perm[NTOK_VFT];
__device__ int   g_map_pt  [NTOK_VFT];
__device__ int   g_map_ps  [NTOK_SOUT];
__device__ int   g_res_t   [NTOK_VFT];
__device__ int   g_res_s   [NTOK_SOUT];

// ---------------- fused map builder (one launch, 5 jobs) ----------------
__device__ __forceinline__ int swap_map(int m, int Bd, int Cd) {
    int c = m % Cd;
    int b = (m / Cd) % Bd;
    int a = m / (Cd*Bd);
    return (a*Cd + c)*Bd + b;
}
__global__ void build_maps_kernel() {
    int m = blockIdx.x*256 + threadIdx.x;
    int job = blockIdx.y;
    if (job == 0)      { if (m < NTOK_VFT)  g_map_perm[m] = swap_map(m, SS, TT); }
    else if (job == 1) { if (m < NTOK_VFT)  g_map_pt[m]   = swap_map(m, TTRG, SS); }
    else if (job == 2) { if (m < NTOK_SOUT) g_map_ps[m]   = swap_map(m, TTRG, TT); }
    else if (job == 3) { if (m < NTOK_VFT)  g_res_t[m]    = (m/(SS*TT))*TTRG + (m % TTRG); }
    else               { if (m < NTOK_SOUT) g_res_s[m]    = (m/(TT*TTRG))*TTRG + (m % TTRG); }
}

// ---------------- layernorm (D=512) ----------------
__global__ __launch_bounds__(128) void ln_kernel(const float* __restrict__ in,
                                                 const float* __restrict__ gamma,
                                                 const float* __restrict__ beta,
                                                 float* __restrict__ out) {
    int row = blockIdx.x;
    int tid = threadIdx.x;
    const float4* p = reinterpret_cast<const float4*>(in + (long)row*DD);
    float4 v = p[tid];
    float s = v.x + v.y + v.z + v.w;
    float q = v.x*v.x + v.y*v.y + v.z*v.z + v.w*v.w;
    #pragma unroll
    for (int o = 16; o; o >>= 1) {
        s += __shfl_xor_sync(0xffffffffu, s, o);
        q += __shfl_xor_sync(0xffffffffu, q, o);
    }
    __shared__ float ssum[4], ssq[4];
    int warp = tid >> 5, lane = tid & 31;
    if (lane == 0) { ssum[warp] = s; ssq[warp] = q; }
    __syncthreads();
    __shared__ float smean, sinv;
    if (tid == 0) {
        float S = ssum[0]+ssum[1]+ssum[2]+ssum[3];
        float Q = ssq[0]+ssq[1]+ssq[2]+ssq[3];
        float mean = S * (1.0f/DD);
        float var  = Q * (1.0f/DD) - mean*mean;
        float sd   = sqrtf(fmaxf(var, 0.0f));
        smean = mean;
        sinv  = 1.0f / (sd + 1e-6f);
    }
    __syncthreads();
    float mean = smean, inv = sinv;
    float4 gv = reinterpret_cast<const float4*>(gamma)[tid];
    float4 bv = reinterpret_cast<const float4*>(beta)[tid];
    float4 o;
    o.x = gv.x*(v.x-mean)*inv + bv.x;
    o.y = gv.y*(v.y-mean)*inv + bv.y;
    o.z = gv.z*(v.z-mean)*inv + bv.z;
    o.w = gv.w*(v.w-mean)*inv + bv.w;
    reinterpret_cast<float4*>(out + (long)row*DD)[tid] = o;
}

// ---------------- tf32/cp.async helpers ----------------
__device__ __forceinline__ void mma_tf32(float* c, const uint32_t* a, const uint32_t* b) {
    asm volatile("mma.sync.aligned.m16n8k8.row.col.f32.tf32.tf32.f32 "
        "{%0,%1,%2,%3}, {%4,%5,%6,%7}, {%8,%9}, {%0,%1,%2,%3};"
        : "+f"(c[0]), "+f"(c[1]), "+f"(c[2]), "+f"(c[3])
        : "r"(a[0]), "r"(a[1]), "r"(a[2]), "r"(a[3]), "r"(b[0]), "r"(b[1]));
}
__device__ __forceinline__ void cp_async16(void* smem_ptr, const void* gptr) {
    uint32_t s = (uint32_t)__cvta_generic_to_shared(smem_ptr);
    asm volatile("cp.async.ca.shared.global [%0], [%1], 16;" :: "r"(s), "l"(gptr));
}
#define CP_COMMIT() asm volatile("cp.async.commit_group;")
#define CP_WAIT0()  asm volatile("cp.async.wait_group 0;")

// ---------------- tf32 tensor-core GEMM (128x128 tile, Kc=16, double-buffered) ----
// Requires M%128==0, N%128==0, K%16==0. fp32 operands truncated to tf32 by MMA HW.
#define TCP 136  // smem stride pad: float4-aligned, 136%32==8 -> conflict-free fragment reads

__global__ __launch_bounds__(256, 2) void sgemm_tc_kernel(
    const float* __restrict__ A, const int* __restrict__ amap,
    const float* __restrict__ W, const float* __restrict__ bias,
    const float* __restrict__ R, const int* __restrict__ rmap,
    float* __restrict__ C, int M, int N, int K, int relu)
{
    __shared__ float As[2][16][TCP];
    __shared__ float Bs[2][16][TCP];
    __shared__ int rowm[128];
    int tid = threadIdx.x;
    int m0 = blockIdx.y << 7, n0 = blockIdx.x << 7;
    if (tid < 128) rowm[tid] = amap ? amap[m0 + tid] : (m0 + tid);
    __syncthreads();

    int wid = tid >> 5, lane = tid & 31;
    int warp_m = wid >> 2, warp_n = wid & 3;   // 2 x 4 warps -> 64 x 32 per warp
    int gr = lane >> 2, gc = lane & 3;

    int arow = tid >> 1, ak = (tid & 1) << 3;
    const float* aptr = A + (long)rowm[arow]*K + ak;
    int bk = tid >> 5, bn = (lane) << 2;
    const float* bptr = W + (long)bk*N + n0 + bn;

    float acc[4][4][4];
    #pragma unroll
    for (int i = 0; i < 4; i++)
        #pragma unroll
        for (int j = 0; j < 4; j++)
            #pragma unroll
            for (int u = 0; u < 4; u++) acc[i][j][u] = 0.0f;

    // preload tile 0
    cp_async16(&Bs[0][bk][bn],   bptr);
    cp_async16(&Bs[0][bk+8][bn], bptr + (long)8*N);
    CP_COMMIT();
    float4 a0 = *reinterpret_cast<const float4*>(aptr);
    float4 a1 = *reinterpret_cast<const float4*>(aptr + 4);
    As[0][ak+0][arow] = a0.x; As[0][ak+1][arow] = a0.y;
    As[0][ak+2][arow] = a0.z; As[0][ak+3][arow] = a0.w;
    As[0][ak+4][arow] = a1.x; As[0][ak+5][arow] = a1.y;
    As[0][ak+6][arow] = a1.z; As[0][ak+7][arow] = a1.w;
    CP_WAIT0();
    __syncthreads();

    int buf = 0;
    for (int k0 = 0; k0 < K; k0 += 16) {
        bool has_next = (k0 + 16) < K;
        if (has_next) {
            a0 = *reinterpret_cast<const float4*>(aptr + k0 + 16);
            a1 = *reinterpret_cast<const float4*>(aptr + k0 + 20);
            cp_async16(&Bs[buf^1][bk][bn],   bptr + (long)(k0 + 16)*N);
            cp_async16(&Bs[buf^1][bk+8][bn], bptr + (long)(k0 + 24)*N);
            CP_COMMIT();
        }
        #pragma unroll
        for (int ks = 0; ks < 2; ks++) {
            int kb = ks << 3;
            uint32_t af[4][4], bf[4][2];
            #pragma unroll
            for (int mt = 0; mt < 4; mt++) {
                int mb = (warp_m << 6) + (mt << 4) + gr;
                af[mt][0] = __float_as_uint(As[buf][kb+gc  ][mb]);
                af[mt][1] = __float_as_uint(As[buf][kb+gc  ][mb+8]);
                af[mt][2] = __float_as_uint(As[buf][kb+gc+4][mb]);
                af[mt][3] = __float_as_uint(As[buf][kb+gc+4][mb+8]);
            }
            #pragma unroll
            for (int nt = 0; nt < 4; nt++) {
                int nb = (warp_n << 5) + (nt << 3) + gr;
                bf[nt][0] = __float_as_uint(Bs[buf][kb+gc  ][nb]);
                bf[nt][1] = __float_as_uint(Bs[buf][kb+gc+4][nb]);
            }
            #pragma unroll
            for (int mt = 0; mt < 4; mt++)
                #pragma unroll
                for (int nt = 0; nt < 4; nt++)
                    mma_tf32(acc[mt][nt], af[mt], bf[nt]);
        }
        if (has_next) {
            int nb2 = buf ^ 1;
            As[nb2][ak+0][arow] = a0.x; As[nb2][ak+1][arow] = a0.y;
            As[nb2][ak+2][arow] = a0.z; As[nb2][ak+3][arow] = a0.w;
            As[nb2][ak+4][arow] = a1.x; As[nb2][ak+5][arow] = a1.y;
            As[nb2][ak+6][arow] = a1.z; As[nb2][ak+7][arow] = a1.w;
            CP_WAIT0();
        }
        __syncthreads();
        buf ^= 1;
    }

    #pragma unroll
    for (int mt = 0; mt < 4; mt++) {
        #pragma unroll
        for (int half = 0; half < 2; half++) {
            int m = m0 + (warp_m << 6) + (mt << 4) + gr + (half << 3);
            long rbase = 0;
            if (R) rbase = (long)(rmap ? rmap[m] : m) * N;
            #pragma unroll
            for (int nt = 0; nt < 4; nt++) {
                int n = n0 + (warp_n << 5) + (nt << 3) + (gc << 1);
                float v0 = acc[mt][nt][half*2 + 0];
                float v1 = acc[mt][nt][half*2 + 1];
                if (bias) { v0 += bias[n]; v1 += bias[n+1]; }
                if (relu) { v0 = fmaxf(v0, 0.0f); v1 = fmaxf(v1, 0.0f); }
                if (R) {
                    float2 rv = *reinterpret_cast<const float2*>(R + rbase + n);
                    v0 += rv.x; v1 += rv.y;
                }
                *reinterpret_cast<float2*>(C + (long)m*N + n) = make_float2(v0, v1);
            }
        }
    }
}

// ---------------- tensor-core attention, Lq=64, dk=64 ----------------
// grid (NB, H), 256 threads. LkPad = Lk rounded up to multiple of 32 (<=128).
// sQ[64][68], sKV[LkPad][68], sS[64][LkPad+4]
__global__ __launch_bounds__(256) void attn_tc_kernel(
    const float* __restrict__ Q, const float* __restrict__ Kg,
    const float* __restrict__ Vg, float* __restrict__ O,
    int Lk, int LkPad, int q_group,
    const int* __restrict__ mask, int mask_mode, int mask_div)
{
    extern __shared__ float sm[];
    float* sQ  = sm;                    // 64*68
    float* sKV = sm + 64*68;            // LkPad*68
    float* sS  = sKV + LkPad*68;        // 64*(LkPad+4)
    int batch = blockIdx.x, h = blockIdx.y;
    int tid = threadIdx.x;
    int qbase = (batch / q_group) * 64;
    int sp = LkPad + 4;

    int wid = tid >> 5, lane = tid & 31;
    int warp_m = wid >> 2, warp_n = wid & 3;
    int gr = lane >> 2, gc = lane & 3;
    int nw  = LkPad >> 2;
    int ntn = LkPad >> 5;

    // async-load Q, K (16B chunks)
    for (int c4 = tid; c4 < 64*16; c4 += 256) {
        int i = c4 >> 4, d = (c4 & 15) << 2;
        cp_async16(&sQ[i*68 + d], &Q[(long)(qbase + i)*DD + h*64 + d]);
    }
    for (int c4 = tid; c4 < Lk*16; c4 += 256) {
        int j = c4 >> 4, d = (c4 & 15) << 2;
        cp_async16(&sKV[j*68 + d], &Kg[(long)(batch*Lk + j)*DD + h*64 + d]);
    }
    CP_COMMIT();
    // zero K pad rows (regular stores)
    for (int idx = Lk*64 + tid; idx < LkPad*64; idx += 256) {
        int j = idx >> 6, d = idx & 63;
        sKV[j*68 + d] = 0.0f;
    }
    CP_WAIT0();
    __syncthreads();

    // scores: S[64][LkPad] = Q @ K^T
    {
        float acc[2][4][4];
        #pragma unroll
        for (int mt = 0; mt < 2; mt++)
            #pragma unroll
            for (int nt = 0; nt < 4; nt++)
                #pragma unroll
                for (int u = 0; u < 4; u++) acc[mt][nt][u] = 0.0f;

        for (int kb = 0; kb < 64; kb += 8) {
            uint32_t af[2][4];
            #pragma unroll
            for (int mt = 0; mt < 2; mt++) {
                int mr = warp_m*32 + mt*16 + gr;
                af[mt][0] = __float_as_uint(sQ[mr*68 + kb+gc]);
                af[mt][1] = __float_as_uint(sQ[(mr+8)*68 + kb+gc]);
                af[mt][2] = __float_as_uint(sQ[mr*68 + kb+gc+4]);
                af[mt][3] = __float_as_uint(sQ[(mr+8)*68 + kb+gc+4]);
            }
            for (int nt = 0; nt < ntn; nt++) {
                int nc = warp_n*nw + nt*8 + gr;
                uint32_t bf[2];
                bf[0] = __float_as_uint(sKV[nc*68 + kb+gc]);
                bf[1] = __float_as_uint(sKV[nc*68 + kb+gc+4]);
                mma_tf32(acc[0][nt], af[0], bf);
                mma_tf32(acc[1][nt], af[1], bf);
            }
        }
        #pragma unroll
        for (int mt = 0; mt < 2; mt++)
            for (int nt = 0; nt < ntn; nt++) {
                int row = warp_m*32 + mt*16 + gr;
                int col = warp_n*nw + nt*8 + (gc << 1);
                sS[row*sp + col]       = acc[mt][nt][0]*0.125f;
                sS[row*sp + col + 1]   = acc[mt][nt][1]*0.125f;
                sS[(row+8)*sp + col]   = acc[mt][nt][2]*0.125f;
                sS[(row+8)*sp + col+1] = acc[mt][nt][3]*0.125f;
            }
    }
    __syncthreads();

    // issue async V load NOW (overlaps with softmax; K in sKV no longer needed)
    for (int c4 = tid; c4 < Lk*16; c4 += 256) {
        int j = c4 >> 4, d = (c4 & 15) << 2;
        cp_async16(&sKV[j*68 + d], &Vg[(long)(batch*Lk + j)*DD + h*64 + d]);
    }
    CP_COMMIT();

    // softmax rows (warp per row), mask, zero padding
    for (int i = wid; i < 64; i += 8) {
        float mx = -3.4e38f;
        for (int j = lane; j < Lk; j += 32) {
            float v = sS[i*sp + j];
            bool dead = false;
            if (mask_mode == 1) dead = (mask[(long)(batch*64 + i)*Lk + j] == 0);
            else if (mask_mode == 2) dead = (mask[(batch/mask_div)*Lk + j] == 0);
            if (dead) { v = -1e9f; sS[i*sp + j] = v; }
            mx = fmaxf(mx, v);
        }
        #pragma unroll
        for (int o = 16; o; o >>= 1) mx = fmaxf(mx, __shfl_xor_sync(0xffffffffu, mx, o));
        float sum = 0.0f;
        for (int j = lane; j < Lk; j += 32) {
            float e = __expf(sS[i*sp + j] - mx);
            sS[i*sp + j] = e;
            sum += e;
        }
        #pragma unroll
        for (int o = 16; o; o >>= 1) sum += __shfl_xor_sync(0xffffffffu, sum, o);
        float inv = 1.0f / sum;
        for (int j = lane; j < Lk; j += 32) sS[i*sp + j] *= inv;
        for (int j = Lk + lane; j < LkPad; j += 32) sS[i*sp + j] = 0.0f;
    }
    CP_WAIT0();
    __syncthreads();

    // O = P @ V  (M=64, N=64, K=LkPad); V pad rows ignored since P pad cols are 0
    {
        float acc[2][2][4];
        #pragma unroll
        for (int mt = 0; mt < 2; mt++)
            #pragma unroll
            for (int nt = 0; nt < 2; nt++)
                #pragma unroll
                for (int u = 0; u < 4; u++) acc[mt][nt][u] = 0.0f;

        for (int kb = 0; kb < LkPad; kb += 8) {
            bool kload = (kb + 8 <= Lk) || (kb < Lk);  // rows >= Lk are stale; guard via P==0
            uint32_t af[2][4];
            #pragma unroll
            for (int mt = 0; mt < 2; mt++) {
                int mr = warp_m*32 + mt*16 + gr;
                af[mt][0] = __float_as_uint(sS[mr*sp + kb+gc]);
                af[mt][1] = __float_as_uint(sS[(mr+8)*sp + kb+gc]);
                af[mt][2] = __float_as_uint(sS[mr*sp + kb+gc+4]);
                af[mt][3] = __float_as_uint(sS[(mr+8)*sp + kb+gc+4]);
            }
            #pragma unroll
            for (int nt = 0; nt < 2; nt++) {
                int nc = warp_n*16 + nt*8 + gr;
                uint32_t bf[2];
                int k0r = kb+gc, k1r = kb+gc+4;
                bf[0] = (k0r < Lk) ? __float_as_uint(sKV[k0r*68 + nc]) : 0u;
                bf[1] = (k1r < Lk) ? __float_as_uint(sKV[k1r*68 + nc]) : 0u;
                mma_tf32(acc[0][nt], af[0], bf);
                mma_tf32(acc[1][nt], af[1], bf);
            }
            (void)kload;
        }
        #pragma unroll
        for (int mt = 0; mt < 2; mt++)
            #pragma unroll
            for (int nt = 0; nt < 2; nt++) {
                int i = warp_m*32 + mt*16 + gr;
                int d = warp_n*16 + nt*8 + (gc << 1);
                long base = (long)(batch*64 + i)*DD + h*64 + d;
                *reinterpret_cast<float2*>(O + base) =
                    make_float2(acc[mt][nt][0], acc[mt][nt][1]);
                *reinterpret_cast<float2*>(O + base + 8*DD) =
                    make_float2(acc[mt][nt][2], acc[mt][nt][3]);
            }
    }
}

// ---------------- fp32 attention for Lq=1 (mha5/mha7) ----------------
#define KVP 68
__global__ __launch_bounds__(256) void attn1_kernel(
    const float* __restrict__ Q, const float* __restrict__ Kg,
    const float* __restrict__ Vg, float* __restrict__ O,
    int Lk, const int* __restrict__ mask, int mask_mode, int mask_div)
{
    extern __shared__ float sm[];
    float* sQ  = sm;           // 64
    float* sKV = sm + 64;      // 32*KVP
    float* sS  = sKV + 32*KVP; // Lk
    int batch = blockIdx.x, h = blockIdx.y;
    int tid = threadIdx.x;

    if (tid < 64) sQ[tid] = Q[(long)batch*DD + h*64 + tid];
    for (int jt = 0; jt < Lk; jt += 32) {
        __syncthreads();
        for (int idx = tid; idx < 32*64; idx += 256) {
            int j = idx >> 6, d = idx & 63;
            int jj = jt + j;
            sKV[j*KVP + d] = (jj < Lk) ? Kg[(long)(batch*Lk + jj)*DD + h*64 + d] : 0.0f;
        }
        __syncthreads();
        if (tid < 32) {
            int jj = jt + tid;
            if (jj < Lk) {
                const float4* q4 = reinterpret_cast<const float4*>(sQ);
                const float4* k4 = reinterpret_cast<const float4*>(sKV + tid*KVP);
                float s = 0.0f;
                #pragma unroll
                for (int d = 0; d < 16; d++) {
                    float4 a = q4[d], b = k4[d];
                    s += a.x*b.x + a.y*b.y + a.z*b.z + a.w*b.w;
                }
                s *= 0.125f;
                if (mask_mode == 2 && mask[(batch/mask_div)*Lk + jj] == 0) s = -1e9f;
                sS[jj] = s;
            }
        }
    }
    __syncthreads();
    if (tid < 32) {
        float m = -3.4e38f;
        for (int j = tid; j < Lk; j += 32) m = fmaxf(m, sS[j]);
        #pragma unroll
        for (int o = 16; o; o >>= 1) m = fmaxf(m, __shfl_xor_sync(0xffffffffu, m, o));
        float sum = 0.0f;
        for (int j = tid; j < Lk; j += 32) {
            float e = __expf(sS[j] - m);
            sS[j] = e;
            sum += e;
        }
        #pragma unroll
        for (int o = 16; o; o >>= 1) sum += __shfl_xor_sync(0xffffffffu, sum, o);
        float inv = 1.0f / sum;
        for (int j = tid; j < Lk; j += 32) sS[j] *= inv;
    }
    float acc = 0.0f;
    for (int jt = 0; jt < Lk; jt += 32) {
        __syncthreads();
        for (int idx = tid; idx < 32*64; idx += 256) {
            int j = idx >> 6, dd = idx & 63;
            int jj = jt + j;
            sKV[j*KVP + dd] = (jj < Lk) ? Vg[(long)(batch*Lk + jj)*DD + h*64 + dd] : 0.0f;
        }
        __syncthreads();
        if (tid < 64) {
            int lim = min(32, Lk - jt);
            for (int j = 0; j < lim; j++) acc += sS[jt + j] * sKV[j*KVP + tid];
        }
    }
    if (tid < 64) O[(long)batch*DD + h*64 + tid] = acc;
}

// ---------------- elementwise add ----------------
__global__ void add_kernel(const float* __restrict__ a, const float* __restrict__ b,
                           float* __restrict__ c, int n) {
    int i = blockIdx.x*256 + threadIdx.x;
    if (i < n) c[i] = a[i] + b[i];
}

// ---------------- host ----------------
static float* sym_f(const void* s) { void* p = nullptr; cudaGetSymbolAddress(&p, s); return (float*)p; }
static int*   sym_i(const void* s) { void* p = nullptr; cudaGetSymbolAddress(&p, s); return (int*)p; }

extern "C" void kernel_launch(void* const* d_in, const int* in_sizes, int n_in,
                              void* d_out, int out_size) {
    const float* x    = (const float*)d_in[0];
    const float* vft  = (const float*)d_in[1];
    const float* his  = (const float*)d_in[2];
    const float* cap  = (const float*)d_in[3];
    const float* qry  = (const float*)d_in[4];
    const int* trg_m  = (const int*)d_in[5];
    const int* his_m  = (const int*)d_in[6];
    const int* cap_m  = (const int*)d_in[7];
    const int* qry_m  = (const int*)d_in[8];
    const int* tmp_m  = (const int*)d_in[9];
    const float* attw = (const float*)d_in[10];
    const float* attb = (const float*)d_in[11];
    const float* ffw1 = (const float*)d_in[12];
    const float* ffb1 = (const float*)d_in[13];
    const float* ffw2 = (const float*)d_in[14];
    const float* ffb2 = (const float*)d_in[15];
    const float* lng  = (const float*)d_in[16];
    const float* lnb  = (const float*)d_in[17];
    float* out = (float*)d_out;

    float* cur   = sym_f(g_cur);
    float* lnbuf = sym_f(g_ln);
    float* qb    = sym_f(g_q);
    float* ks    = sym_f(g_ks);
    float* vs    = sym_f(g_vs);
    float* ab    = sym_f(g_attn);
    float* ts    = sym_f(g_ts);
    float* st    = sym_f(g_st);
    float* ffh   = sym_f(g_ffh);
    float* big0  = sym_f(g_big0);
    float* big1  = sym_f(g_big1);
    float* big2  = sym_f(g_big2);
    float* big3  = sym_f(g_big3);
    float* big4  = sym_f(g_big4);
    float* big5  = sym_f(g_big5);
    int* map_perm = sym_i(g_map_perm);
    int* map_pt   = sym_i(g_map_pt);
    int* map_ps   = sym_i(g_map_ps);
    int* res_t    = sym_i(g_res_t);
    int* res_s    = sym_i(g_res_s);

    cudaFuncSetAttribute((const void*)attn_tc_kernel,
                         cudaFuncAttributeMaxDynamicSharedMemorySize, 120*1024);
    cudaFuncSetAttribute((const void*)attn1_kernel,
                         cudaFuncAttributeMaxDynamicSharedMemorySize, 32*1024);

    #define AW(i,j) (attw + ((i)*4+(j))*DD*DD)
    #define ABI(i,j) (attb + ((i)*4+(j))*DD)

    auto gemm = [](const float* A, const int* amap, const float* W, const float* bias,
                   const float* R, const int* rmap, float* C, int M, int N, int K, int relu) {
        dim3 grid(N/128, M/128);
        sgemm_tc_kernel<<<grid, 256>>>(A, amap, W, bias, R, rmap, C, M, N, K, relu);
    };
    auto attn = [](const float* Q, const float* K, const float* V, float* O,
                   int NB, int Lk, int qg, const int* mask, int mode, int mdiv) {
        int LkPad = (Lk + 31) & ~31;
        size_t sh = (size_t)(64*68 + LkPad*68 + 64*(LkPad+4)) * sizeof(float);
        attn_tc_kernel<<<dim3(NB, HH), 256, sh>>>(Q, K, V, O, Lk, LkPad, qg, mask, mode, mdiv);
    };
    auto attn1 = [](const float* Q, const float* K, const float* V, float* O,
                    int NB, int Lk, const int* mask, int mode, int mdiv) {
        size_t sh = (size_t)(64 + 32*KVP + Lk) * sizeof(float);
        attn1_kernel<<<dim3(NB, HH), 256, sh>>>(Q, K, V, O, Lk, mask, mode, mdiv);
    };
    auto ln = [&](const float* in, int li, float* o, int rows) {
        ln_kernel<<<rows, 128>>>(in, lng + li*DD, lnb + li*DD, o);
    };

    // launch 0: fused maps
    build_maps_kernel<<<dim3(256, 5), 256>>>();
    // launch 1: ln for mha0
    ln(x, 0, lnbuf, NTOK_X);
    // launches 2-5: the four independent big vft projections (launch 5 -> ncu capture)
    gemm(vft, map_perm, AW(4,1), ABI(4,1), nullptr, nullptr, big0, NTOK_VFT, DD, DD, 0); // mha4 K
    gemm(vft, map_perm, AW(4,2), ABI(4,2), nullptr, nullptr, big1, NTOK_VFT, DD, DD, 0); // mha4 V
    gemm(vft, nullptr,  AW(6,1), ABI(6,1), nullptr, nullptr, big4, NTOK_SOUT, DD, DD, 0); // mha6 K
    gemm(vft, nullptr,  AW(6,2), ABI(6,2), nullptr, nullptr, big5, NTOK_SOUT, DD, DD, 0); // mha6 V

    // ---- mha0: causal self-attention ----
    gemm(lnbuf, nullptr, AW(0,0), ABI(0,0), nullptr, nullptr, qb, NTOK_X, DD, DD, 0);
    gemm(lnbuf, nullptr, AW(0,1), ABI(0,1), nullptr, nullptr, ks, NTOK_X, DD, DD, 0);
    gemm(lnbuf, nullptr, AW(0,2), ABI(0,2), nullptr, nullptr, vs, NTOK_X, DD, DD, 0);
    attn(qb, ks, vs, ab, BB, TTRG, 1, trg_m, 1, 1);
    gemm(ab, nullptr, AW(0,3), ABI(0,3), x, nullptr, cur, NTOK_X, DD, DD, 0);

    // ---- mha1..3 ----
    {
        const float* kvsrc[3] = { his, cap, qry };
        const int    kvrows[3] = { BB*128, BB*64, BB*32 };
        const int    Lks[3]    = { 128, 64, 32 };
        const int*   masks[3]  = { his_m, cap_m, qry_m };
        for (int a = 0; a < 3; a++) {
            int wi = a + 1;
            ln(cur, wi, lnbuf, NTOK_X);
            gemm(lnbuf, nullptr, AW(wi,0), ABI(wi,0), nullptr, nullptr, qb, NTOK_X, DD, DD, 0);
            gemm(kvsrc[a], nullptr, AW(wi,1), ABI(wi,1), nullptr, nullptr, ks, kvrows[a], DD, DD, 0);
            gemm(kvsrc[a], nullptr, AW(wi,2), ABI(wi,2), nullptr, nullptr, vs, kvrows[a], DD, DD, 0);
            attn(qb, ks, vs, ab, BB, Lks[a], 1, masks[a], 2, 1);
            gemm(ab, nullptr, AW(wi,3), ABI(wi,3), cur, nullptr, cur, NTOK_X, DD, DD, 0);
        }
    }

    // ---- temporal2spatial: mha4 (K/V already in big0/big1) ----
    ln(cur, 4, lnbuf, NTOK_X);
    gemm(lnbuf, nullptr, AW(4,0), ABI(4,0), nullptr, nullptr, qb, NTOK_X, DD, DD, 0);
    attn(qb, big0, big1, big2, BB*SS, TT, SS, tmp_m, 2, SS);
    gemm(big2, nullptr, AW(4,3), ABI(4,3), cur, res_t, big3, NTOK_VFT, DD, DD, 0);

    // ---- mha5 ----
    ln(cur, 5, lnbuf, NTOK_X);
    gemm(lnbuf, nullptr, AW(5,0), ABI(5,0), nullptr, nullptr, qb, NTOK_X, DD, DD, 0);
    gemm(big3, map_pt, AW(5,1), ABI(5,1), nullptr, nullptr, big0, NTOK_VFT, DD, DD, 0);
    gemm(big3, map_pt, AW(5,2), ABI(5,2), nullptr, nullptr, big1, NTOK_VFT, DD, DD, 0);
    attn1(qb, big0, big1, ab, NTOK_X, SS, nullptr, 0, 1);
    gemm(ab, nullptr, AW(5,3), ABI(5,3), cur, nullptr, ts, NTOK_X, DD, DD, 0);
    // ffn0
    ln(ts, 6, lnbuf, NTOK_X);
    gemm(lnbuf, nullptr, ffw1 + 0*DD*DFF, ffb1 + 0*DFF, nullptr, nullptr, ffh, NTOK_X, DFF, DD, 1);
    gemm(ffh, nullptr, ffw2 + 0*DFF*DD, ffb2 + 0*DD, ts, nullptr, ts, NTOK_X, DD, DFF, 0);

    // ---- spatial2temporal: mha6 (K/V already in big4/big5) ----
    ln(cur, 7, lnbuf, NTOK_X);
    gemm(lnbuf, nullptr, AW(6,0), ABI(6,0), nullptr, nullptr, qb, NTOK_X, DD, DD, 0);
    attn(qb, big4, big5, big2, BB*TT, SS, TT, nullptr, 0, 1);
    gemm(big2, nullptr, AW(6,3), ABI(6,3), cur, res_s, big3, NTOK_SOUT, DD, DD, 0);

    // ---- mha7 ----
    ln(cur, 8, lnbuf, NTOK_X);
    gemm(lnbuf, nullptr, AW(7,0), ABI(7,0), nullptr, nullptr, qb, NTOK_X, DD, DD, 0);
    gemm(big3, map_ps, AW(7,1), ABI(7,1), nullptr, nullptr, big0, NTOK_SOUT, DD, DD, 0);
    gemm(big3, map_ps, AW(7,2), ABI(7,2), nullptr, nullptr, big1, NTOK_SOUT, DD, DD, 0);
    attn1(qb, big0, big1, ab, NTOK_X, TT, tmp_m, 2, TTRG);
    gemm(ab, nullptr, AW(7,3), ABI(7,3), cur, nullptr, st, NTOK_X, DD, DD, 0);
    // ffn1
    ln(st, 9, lnbuf, NTOK_X);
    gemm(lnbuf, nullptr, ffw1 + 1*DD*DFF, ffb1 + 1*DFF, nullptr, nullptr, ffh, NTOK_X, DFF, DD, 1);
    gemm(ffh, nullptr, ffw2 + 1*DFF*DD, ffb2 + 1*DD, st, nullptr, st, NTOK_X, DD, DFF, 0);

    // ---- combine + ffn2 ----
    add_kernel<<<(NTOK_X*DD + 255)/256, 256>>>(ts, st, cur, NTOK_X*DD);
    ln(cur, 10, lnbuf, NTOK_X);
    gemm(lnbuf, nullptr, ffw1 + 2*DD*DFF, ffb1 + 2*DFF, nullptr, nullptr, ffh, NTOK_X, DFF, DD, 1);
    gemm(ffh, nullptr, ffw2 + 2*DFF*DD, ffb2 + 2*DD, cur, nullptr, out, NTOK_X, DD, DFF, 0);

    #undef AW
    #undef ABI
}

// round 7
// speedup vs baseline: 3.3580x; 1.1018x over previous
#include <cuda_runtime.h>
#include <math.h>
#include <stdint.h>

// ---------------- problem constants ----------------
#define BB   16
#define TTRG 64
#define TT   64
#define SS   49
#define DD   512
#define DFF  2048
#define HH   8
#define NTOK_X    (BB*TTRG)          // 1024
#define NTOK_VFT  (BB*TT*SS)         // 50176
#define NTOK_SOUT (BB*TT*TTRG)       // 65536

// ---------------- scratch ----------------
__device__ float g_cur [NTOK_X*DD];
__device__ float g_ln  [NTOK_X*DD];
__device__ float g_q   [NTOK_X*DD];
__device__ float g_ks  [2048*DD];
__device__ float g_vs  [2048*DD];
__device__ float g_attn[NTOK_X*DD];
__device__ float g_ts  [NTOK_X*DD];
__device__ float g_st  [NTOK_X*DD];
__device__ float g_ffh [NTOK_X*DFF];
__device__ float g_big0[NTOK_SOUT*DD];
__device__ float g_big1[NTOK_SOUT*DD];
__device__ float g_big2[NTOK_SOUT*DD];
__device__ float g_big3[NTOK_SOUT*DD];
__device__ float g_big4[NTOK_SOUT*DD];
__device__ float g_big5[NTOK_SOUT*DD];
__device__ int   g_map_perm[NTOK_VFT];
__device__ int   g_map_pt  [NTOK_VFT];
__device__ int   g_map_ps  [NTOK_SOUT];
__device__ int   g_res_t   [NTOK_VFT];
__device__ int   g_res_s   [NTOK_SOUT];

// ---------------- fused map builder ----------------
__device__ __forceinline__ int swap_map(int m, int Bd, int Cd) {
    int c = m % Cd;
    int b = (m / Cd) % Bd;
    int a = m / (Cd*Bd);
    return (a*Cd + c)*Bd + b;
}
__global__ void build_maps_kernel() {
    int m = blockIdx.x*256 + threadIdx.x;
    int job = blockIdx.y;
    if (job == 0)      { if (m < NTOK_VFT)  g_map_perm[m] = swap_map(m, SS, TT); }
    else if (job == 1) { if (m < NTOK_VFT)  g_map_pt[m]   = swap_map(m, TTRG, SS); }
    else if (job == 2) { if (m < NTOK_SOUT) g_map_ps[m]   = swap_map(m, TTRG, TT); }
    else if (job == 3) { if (m < NTOK_VFT)  g_res_t[m]    = (m/(SS*TT))*TTRG + (m % TTRG); }
    else               { if (m < NTOK_SOUT) g_res_s[m]    = (m/(TT*TTRG))*TTRG + (m % TTRG); }
}

// ---------------- layernorm (D=512) ----------------
__global__ __launch_bounds__(128) void ln_kernel(const float* __restrict__ in,
                                                 const float* __restrict__ gamma,
                                                 const float* __restrict__ beta,
                                                 float* __restrict__ out) {
    int row = blockIdx.x;
    int tid = threadIdx.x;
    const float4* p = reinterpret_cast<const float4*>(in + (long)row*DD);
    float4 v = p[tid];
    float s = v.x + v.y + v.z + v.w;
    float q = v.x*v.x + v.y*v.y + v.z*v.z + v.w*v.w;
    #pragma unroll
    for (int o = 16; o; o >>= 1) {
        s += __shfl_xor_sync(0xffffffffu, s, o);
        q += __shfl_xor_sync(0xffffffffu, q, o);
    }
    __shared__ float ssum[4], ssq[4];
    int warp = tid >> 5, lane = tid & 31;
    if (lane == 0) { ssum[warp] = s; ssq[warp] = q; }
    __syncthreads();
    __shared__ float smean, sinv;
    if (tid == 0) {
        float S = ssum[0]+ssum[1]+ssum[2]+ssum[3];
        float Q = ssq[0]+ssq[1]+ssq[2]+ssq[3];
        float mean = S * (1.0f/DD);
        float var  = Q * (1.0f/DD) - mean*mean;
        float sd   = sqrtf(fmaxf(var, 0.0f));
        smean = mean;
        sinv  = 1.0f / (sd + 1e-6f);
    }
    __syncthreads();
    float mean = smean, inv = sinv;
    float4 gv = reinterpret_cast<const float4*>(gamma)[tid];
    float4 bv = reinterpret_cast<const float4*>(beta)[tid];
    float4 o;
    o.x = gv.x*(v.x-mean)*inv + bv.x;
    o.y = gv.y*(v.y-mean)*inv + bv.y;
    o.z = gv.z*(v.z-mean)*inv + bv.z;
    o.w = gv.w*(v.w-mean)*inv + bv.w;
    reinterpret_cast<float4*>(out + (long)row*DD)[tid] = o;
}

// ---------------- tf32/cp.async/ldmatrix helpers ----------------
__device__ __forceinline__ void mma_tf32(float* c, const uint32_t* a, const uint32_t* b) {
    asm volatile("mma.sync.aligned.m16n8k8.row.col.f32.tf32.tf32.f32 "
        "{%0,%1,%2,%3}, {%4,%5,%6,%7}, {%8,%9}, {%0,%1,%2,%3};"
        : "+f"(c[0]), "+f"(c[1]), "+f"(c[2]), "+f"(c[3])
        : "r"(a[0]), "r"(a[1]), "r"(a[2]), "r"(a[3]), "r"(b[0]), "r"(b[1]));
}
__device__ __forceinline__ void cp_async16(void* smem_ptr, const void* gptr) {
    uint32_t s = (uint32_t)__cvta_generic_to_shared(smem_ptr);
    asm volatile("cp.async.cg.shared.global [%0], [%1], 16;" :: "r"(s), "l"(gptr));
}
#define CP_COMMIT() asm volatile("cp.async.commit_group;")
#define CP_WAIT0()  asm volatile("cp.async.wait_group 0;")
__device__ __forceinline__ void ldsm_x4(uint32_t* r, const void* p) {
    uint32_t a = (uint32_t)__cvta_generic_to_shared(p);
    asm volatile("ldmatrix.sync.aligned.m8n8.x4.shared.b16 {%0,%1,%2,%3}, [%4];"
        : "=r"(r[0]), "=r"(r[1]), "=r"(r[2]), "=r"(r[3]) : "r"(a));
}

// ---------------- tf32 tensor-core GEMM (128x128 tile, Kc=16, double-buffered) ----
// A smem: row-major [128 m][20] (pad 20 -> LDSM rows on disjoint banks)
// B smem: k-major [16][136]
#define TCP 136
#define ASP 20

__global__ __launch_bounds__(256, 2) void sgemm_tc_kernel(
    const float* __restrict__ A, const int* __restrict__ amap,
    const float* __restrict__ W, const float* __restrict__ bias,
    const float* __restrict__ R, const int* __restrict__ rmap,
    float* __restrict__ C, int M, int N, int K, int relu)
{
    __shared__ float As[2][128][ASP];
    __shared__ float Bs[2][16][TCP];
    __shared__ int rowm[128];
    int tid = threadIdx.x;
    int m0 = blockIdx.y << 7, n0 = blockIdx.x << 7;
    if (tid < 128) rowm[tid] = amap ? amap[m0 + tid] : (m0 + tid);
    __syncthreads();

    int wid = tid >> 5, lane = tid & 31;
    int warp_m = wid >> 2, warp_n = wid & 3;   // 2 x 4 warps -> 64 x 32 per warp
    int gr = lane >> 2, gc = lane & 3;
    int lrow = lane & 15, lkq = (lane >> 4) << 2;   // ldmatrix addressing

    int arow = tid >> 1, ak = (tid & 1) << 3;
    const float* aptr = A + (long)rowm[arow]*K + ak;
    int bk = tid >> 5, bn = (lane) << 2;
    const float* bptr = W + (long)bk*N + n0 + bn;

    float acc[4][4][4];
    #pragma unroll
    for (int i = 0; i < 4; i++)
        #pragma unroll
        for (int j = 0; j < 4; j++)
            #pragma unroll
            for (int u = 0; u < 4; u++) acc[i][j][u] = 0.0f;

    // preload tile 0
    cp_async16(&As[0][arow][ak],     aptr);
    cp_async16(&As[0][arow][ak + 4], aptr + 4);
    cp_async16(&Bs[0][bk][bn],   bptr);
    cp_async16(&Bs[0][bk+8][bn], bptr + (long)8*N);
    CP_COMMIT();
    CP_WAIT0();
    __syncthreads();

    int buf = 0;
    for (int k0 = 0; k0 < K; k0 += 16) {
        bool has_next = (k0 + 16) < K;
        if (has_next) {
            cp_async16(&As[buf^1][arow][ak],     aptr + k0 + 16);
            cp_async16(&As[buf^1][arow][ak + 4], aptr + k0 + 20);
            cp_async16(&Bs[buf^1][bk][bn],   bptr + (long)(k0 + 16)*N);
            cp_async16(&Bs[buf^1][bk+8][bn], bptr + (long)(k0 + 24)*N);
            CP_COMMIT();
        }
        #pragma unroll
        for (int ks = 0; ks < 2; ks++) {
            int kb = ks << 3;
            uint32_t af[4][4], bf[4][2];
            #pragma unroll
            for (int mt = 0; mt < 4; mt++) {
                int mb = (warp_m << 6) + (mt << 4) + lrow;
                ldsm_x4(af[mt], &As[buf][mb][kb + lkq]);
            }
            #pragma unroll
            for (int nt = 0; nt < 4; nt++) {
                int nb = (warp_n << 5) + (nt << 3) + gr;
                bf[nt][0] = __float_as_uint(Bs[buf][kb+gc  ][nb]);
                bf[nt][1] = __float_as_uint(Bs[buf][kb+gc+4][nb]);
            }
            #pragma unroll
            for (int mt = 0; mt < 4; mt++)
                #pragma unroll
                for (int nt = 0; nt < 4; nt++)
                    mma_tf32(acc[mt][nt], af[mt], bf[nt]);
        }
        if (has_next) CP_WAIT0();
        __syncthreads();
        buf ^= 1;
    }

    #pragma unroll
    for (int mt = 0; mt < 4; mt++) {
        #pragma unroll
        for (int half = 0; half < 2; half++) {
            int m = m0 + (warp_m << 6) + (mt << 4) + gr + (half << 3);
            long rbase = 0;
            if (R) rbase = (long)(rmap ? rmap[m] : m) * N;
            #pragma unroll
            for (int nt = 0; nt < 4; nt++) {
                int n = n0 + (warp_n << 5) + (nt << 3) + (gc << 1);
                float v0 = acc[mt][nt][half*2 + 0];
                float v1 = acc[mt][nt][half*2 + 1];
                if (bias) { v0 += bias[n]; v1 += bias[n+1]; }
                if (relu) { v0 = fmaxf(v0, 0.0f); v1 = fmaxf(v1, 0.0f); }
                if (R) {
                    float2 rv = *reinterpret_cast<const float2*>(R + rbase + n);
                    v0 += rv.x; v1 += rv.y;
                }
                *reinterpret_cast<float2*>(C + (long)m*N + n) = make_float2(v0, v1);
            }
        }
    }
}

// ---------------- tensor-core attention, Lq=64, dk=64 ----------------
__global__ __launch_bounds__(256) void attn_tc_kernel(
    const float* __restrict__ Q, const float* __restrict__ Kg,
    const float* __restrict__ Vg, float* __restrict__ O,
    int Lk, int LkPad, int q_group,
    const int* __restrict__ mask, int mask_mode, int mask_div)
{
    extern __shared__ float sm[];
    float* sQ  = sm;                    // 64*68
    float* sKV = sm + 64*68;            // LkPad*68
    float* sS  = sKV + LkPad*68;        // 64*(LkPad+4)
    int batch = blockIdx.x, h = blockIdx.y;
    int tid = threadIdx.x;
    int qbase = (batch / q_group) * 64;
    int sp = LkPad + 4;

    int wid = tid >> 5, lane = tid & 31;
    int warp_m = wid >> 2, warp_n = wid & 3;
    int gr = lane >> 2, gc = lane & 3;
    int nw  = LkPad >> 2;
    int ntn = LkPad >> 5;

    for (int c4 = tid; c4 < 64*16; c4 += 256) {
        int i = c4 >> 4, d = (c4 & 15) << 2;
        cp_async16(&sQ[i*68 + d], &Q[(long)(qbase + i)*DD + h*64 + d]);
    }
    for (int c4 = tid; c4 < Lk*16; c4 += 256) {
        int j = c4 >> 4, d = (c4 & 15) << 2;
        cp_async16(&sKV[j*68 + d], &Kg[(long)(batch*Lk + j)*DD + h*64 + d]);
    }
    CP_COMMIT();
    for (int idx = Lk*64 + tid; idx < LkPad*64; idx += 256) {
        int j = idx >> 6, d = idx & 63;
        sKV[j*68 + d] = 0.0f;
    }
    CP_WAIT0();
    __syncthreads();

    // scores
    {
        float acc[2][4][4];
        #pragma unroll
        for (int mt = 0; mt < 2; mt++)
            #pragma unroll
            for (int nt = 0; nt < 4; nt++)
                #pragma unroll
                for (int u = 0; u < 4; u++) acc[mt][nt][u] = 0.0f;

        for (int kb = 0; kb < 64; kb += 8) {
            uint32_t af[2][4];
            #pragma unroll
            for (int mt = 0; mt < 2; mt++) {
                int mr = warp_m*32 + mt*16 + gr;
                af[mt][0] = __float_as_uint(sQ[mr*68 + kb+gc]);
                af[mt][1] = __float_as_uint(sQ[(mr+8)*68 + kb+gc]);
                af[mt][2] = __float_as_uint(sQ[mr*68 + kb+gc+4]);
                af[mt][3] = __float_as_uint(sQ[(mr+8)*68 + kb+gc+4]);
            }
            for (int nt = 0; nt < ntn; nt++) {
                int nc = warp_n*nw + nt*8 + gr;
                uint32_t bf[2];
                bf[0] = __float_as_uint(sKV[nc*68 + kb+gc]);
                bf[1] = __float_as_uint(sKV[nc*68 + kb+gc+4]);
                mma_tf32(acc[0][nt], af[0], bf);
                mma_tf32(acc[1][nt], af[1], bf);
            }
        }
        #pragma unroll
        for (int mt = 0; mt < 2; mt++)
            for (int nt = 0; nt < ntn; nt++) {
                int row = warp_m*32 + mt*16 + gr;
                int col = warp_n*nw + nt*8 + (gc << 1);
                sS[row*sp + col]       = acc[mt][nt][0]*0.125f;
                sS[row*sp + col + 1]   = acc[mt][nt][1]*0.125f;
                sS[(row+8)*sp + col]   = acc[mt][nt][2]*0.125f;
                sS[(row+8)*sp + col+1] = acc[mt][nt][3]*0.125f;
            }
    }
    __syncthreads();

    // async V load overlapped with softmax
    for (int c4 = tid; c4 < Lk*16; c4 += 256) {
        int j = c4 >> 4, d = (c4 & 15) << 2;
        cp_async16(&sKV[j*68 + d], &Vg[(long)(batch*Lk + j)*DD + h*64 + d]);
    }
    CP_COMMIT();

    for (int i = wid; i < 64; i += 8) {
        float mx = -3.4e38f;
        for (int j = lane; j < Lk; j += 32) {
            float v = sS[i*sp + j];
            bool dead = false;
            if (mask_mode == 1) dead = (mask[(long)(batch*64 + i)*Lk + j] == 0);
            else if (mask_mode == 2) dead = (mask[(batch/mask_div)*Lk + j] == 0);
            if (dead) { v = -1e9f; sS[i*sp + j] = v; }
            mx = fmaxf(mx, v);
        }
        #pragma unroll
        for (int o = 16; o; o >>= 1) mx = fmaxf(mx, __shfl_xor_sync(0xffffffffu, mx, o));
        float sum = 0.0f;
        for (int j = lane; j < Lk; j += 32) {
            float e = __expf(sS[i*sp + j] - mx);
            sS[i*sp + j] = e;
            sum += e;
        }
        #pragma unroll
        for (int o = 16; o; o >>= 1) sum += __shfl_xor_sync(0xffffffffu, sum, o);
        float inv = 1.0f / sum;
        for (int j = lane; j < Lk; j += 32) sS[i*sp + j] *= inv;
        for (int j = Lk + lane; j < LkPad; j += 32) sS[i*sp + j] = 0.0f;
    }
    CP_WAIT0();
    __syncthreads();

    // O = P @ V
    {
        float acc[2][2][4];
        #pragma unroll
        for (int mt = 0; mt < 2; mt++)
            #pragma unroll
            for (int nt = 0; nt < 2; nt++)
                #pragma unroll
                for (int u = 0; u < 4; u++) acc[mt][nt][u] = 0.0f;

        for (int kb = 0; kb < LkPad; kb += 8) {
            uint32_t af[2][4];
            #pragma unroll
            for (int mt = 0; mt < 2; mt++) {
                int mr = warp_m*32 + mt*16 + gr;
                af[mt][0] = __float_as_uint(sS[mr*sp + kb+gc]);
                af[mt][1] = __float_as_uint(sS[(mr+8)*sp + kb+gc]);
                af[mt][2] = __float_as_uint(sS[mr*sp + kb+gc+4]);
                af[mt][3] = __float_as_uint(sS[(mr+8)*sp + kb+gc+4]);
            }
            #pragma unroll
            for (int nt = 0; nt < 2; nt++) {
                int nc = warp_n*16 + nt*8 + gr;
                uint32_t bf[2];
                int k0r = kb+gc, k1r = kb+gc+4;
                bf[0] = (k0r < Lk) ? __float_as_uint(sKV[k0r*68 + nc]) : 0u;
                bf[1] = (k1r < Lk) ? __float_as_uint(sKV[k1r*68 + nc]) : 0u;
                mma_tf32(acc[0][nt], af[0], bf);
                mma_tf32(acc[1][nt], af[1], bf);
            }
        }
        #pragma unroll
        for (int mt = 0; mt < 2; mt++)
            #pragma unroll
            for (int nt = 0; nt < 2; nt++) {
                int i = warp_m*32 + mt*16 + gr;
                int d = warp_n*16 + nt*8 + (gc << 1);
                long base = (long)(batch*64 + i)*DD + h*64 + d;
                *reinterpret_cast<float2*>(O + base) =
                    make_float2(acc[mt][nt][0], acc[mt][nt][1]);
                *reinterpret_cast<float2*>(O + base + 8*DD) =
                    make_float2(acc[mt][nt][2], acc[mt][nt][3]);
            }
    }
}

// ---------------- fp32 attention for Lq=1 (mha5/mha7) ----------------
#define KVP 68
__global__ __launch_bounds__(256) void attn1_kernel(
    const float* __restrict__ Q, const float* __restrict__ Kg,
    const float* __restrict__ Vg, float* __restrict__ O,
    int Lk, const int* __restrict__ mask, int mask_mode, int mask_div)
{
    extern __shared__ float sm[];
    float* sQ  = sm;
    float* sKV = sm + 64;
    float* sS  = sKV + 32*KVP;
    int batch = blockIdx.x, h = blockIdx.y;
    int tid = threadIdx.x;

    if (tid < 64) sQ[tid] = Q[(long)batch*DD + h*64 + tid];
    for (int jt = 0; jt < Lk; jt += 32) {
        __syncthreads();
        for (int idx = tid; idx < 32*64; idx += 256) {
            int j = idx >> 6, d = idx & 63;
            int jj = jt + j;
            sKV[j*KVP + d] = (jj < Lk) ? Kg[(long)(batch*Lk + jj)*DD + h*64 + d] : 0.0f;
        }
        __syncthreads();
        if (tid < 32) {
            int jj = jt + tid;
            if (jj < Lk) {
                const float4* q4 = reinterpret_cast<const float4*>(sQ);
                const float4* k4 = reinterpret_cast<const float4*>(sKV + tid*KVP);
                float s = 0.0f;
                #pragma unroll
                for (int d = 0; d < 16; d++) {
                    float4 a = q4[d], b = k4[d];
                    s += a.x*b.x + a.y*b.y + a.z*b.z + a.w*b.w;
                }
                s *= 0.125f;
                if (mask_mode == 2 && mask[(batch/mask_div)*Lk + jj] == 0) s = -1e9f;
                sS[jj] = s;
            }
        }
    }
    __syncthreads();
    if (tid < 32) {
        float m = -3.4e38f;
        for (int j = tid; j < Lk; j += 32) m = fmaxf(m, sS[j]);
        #pragma unroll
        for (int o = 16; o; o >>= 1) m = fmaxf(m, __shfl_xor_sync(0xffffffffu, m, o));
        float sum = 0.0f;
        for (int j = tid; j < Lk; j += 32) {
            float e = __expf(sS[j] - m);
            sS[j] = e;
            sum += e;
        }
        #pragma unroll
        for (int o = 16; o; o >>= 1) sum += __shfl_xor_sync(0xffffffffu, sum, o);
        float inv = 1.0f / sum;
        for (int j = tid; j < Lk; j += 32) sS[j] *= inv;
    }
    float acc = 0.0f;
    for (int jt = 0; jt < Lk; jt += 32) {
        __syncthreads();
        for (int idx = tid; idx < 32*64; idx += 256) {
            int j = idx >> 6, dd = idx & 63;
            int jj = jt + j;
            sKV[j*KVP + dd] = (jj < Lk) ? Vg[(long)(batch*Lk + jj)*DD + h*64 + dd] : 0.0f;
        }
        __syncthreads();
        if (tid < 64) {
            int lim = min(32, Lk - jt);
            for (int j = 0; j < lim; j++) acc += sS[jt + j] * sKV[j*KVP + tid];
        }
    }
    if (tid < 64) O[(long)batch*DD + h*64 + tid] = acc;
}

// ---------------- elementwise add ----------------
__global__ void add_kernel(const float* __restrict__ a, const float* __restrict__ b,
                           float* __restrict__ c, int n) {
    int i = blockIdx.x*256 + threadIdx.x;
    if (i < n) c[i] = a[i] + b[i];
}

// ---------------- host ----------------
static float* sym_f(const void* s) { void* p = nullptr; cudaGetSymbolAddress(&p, s); return (float*)p; }
static int*   sym_i(const void* s) { void* p = nullptr; cudaGetSymbolAddress(&p, s); return (int*)p; }

extern "C" void kernel_launch(void* const* d_in, const int* in_sizes, int n_in,
                              void* d_out, int out_size) {
    const float* x    = (const float*)d_in[0];
    const float* vft  = (const float*)d_in[1];
    const float* his  = (const float*)d_in[2];
    const float* cap  = (const float*)d_in[3];
    const float* qry  = (const float*)d_in[4];
    const int* trg_m  = (const int*)d_in[5];
    const int* his_m  = (const int*)d_in[6];
    const int* cap_m  = (const int*)d_in[7];
    const int* qry_m  = (const int*)d_in[8];
    const int* tmp_m  = (const int*)d_in[9];
    const float* attw = (const float*)d_in[10];
    const float* attb = (const float*)d_in[11];
    const float* ffw1 = (const float*)d_in[12];
    const float* ffb1 = (const float*)d_in[13];
    const float* ffw2 = (const float*)d_in[14];
    const float* ffb2 = (const float*)d_in[15];
    const float* lng  = (const float*)d_in[16];
    const float* lnb  = (const float*)d_in[17];
    float* out = (float*)d_out;

    float* cur   = sym_f(g_cur);
    float* lnbuf = sym_f(g_ln);
    float* qb    = sym_f(g_q);
    float* ks    = sym_f(g_ks);
    float* vs    = sym_f(g_vs);
    float* ab    = sym_f(g_attn);
    float* ts    = sym_f(g_ts);
    float* st    = sym_f(g_st);
    float* ffh   = sym_f(g_ffh);
    float* big0  = sym_f(g_big0);
    float* big1  = sym_f(g_big1);
    float* big2  = sym_f(g_big2);
    float* big3  = sym_f(g_big3);
    float* big4  = sym_f(g_big4);
    float* big5  = sym_f(g_big5);
    int* map_perm = sym_i(g_map_perm);
    int* map_pt   = sym_i(g_map_pt);
    int* map_ps   = sym_i(g_map_ps);
    int* res_t    = sym_i(g_res_t);
    int* res_s    = sym_i(g_res_s);

    cudaFuncSetAttribute((const void*)attn_tc_kernel,
                         cudaFuncAttributeMaxDynamicSharedMemorySize, 120*1024);
    cudaFuncSetAttribute((const void*)attn1_kernel,
                         cudaFuncAttributeMaxDynamicSharedMemorySize, 32*1024);

    #define AW(i,j) (attw + ((i)*4+(j))*DD*DD)
    #define ABI(i,j) (attb + ((i)*4+(j))*DD)

    auto gemm = [](const float* A, const int* amap, const float* W, const float* bias,
                   const float* R, const int* rmap, float* C, int M, int N, int K, int relu) {
        dim3 grid(N/128, M/128);
        sgemm_tc_kernel<<<grid, 256>>>(A, amap, W, bias, R, rmap, C, M, N, K, relu);
    };
    auto attn = [](const float* Q, const float* K, const float* V, float* O,
                   int NB, int Lk, int qg, const int* mask, int mode, int mdiv) {
        int LkPad = (Lk + 31) & ~31;
        size_t sh = (size_t)(64*68 + LkPad*68 + 64*(LkPad+4)) * sizeof(float);
        attn_tc_kernel<<<dim3(NB, HH), 256, sh>>>(Q, K, V, O, Lk, LkPad, qg, mask, mode, mdiv);
    };
    auto attn1 = [](const float* Q, const float* K, const float* V, float* O,
                    int NB, int Lk, const int* mask, int mode, int mdiv) {
        size_t sh = (size_t)(64 + 32*KVP + Lk) * sizeof(float);
        attn1_kernel<<<dim3(NB, HH), 256, sh>>>(Q, K, V, O, Lk, mask, mode, mdiv);
    };
    auto ln = [&](const float* in, int li, float* o, int rows) {
        ln_kernel<<<rows, 128>>>(in, lng + li*DD, lnb + li*DD, o);
    };

    // launch 0: fused maps; launch 1: ln; launches 2-5: big vft projections
    build_maps_kernel<<<dim3(256, 5), 256>>>();
    ln(x, 0, lnbuf, NTOK_X);
    gemm(vft, map_perm, AW(4,1), ABI(4,1), nullptr, nullptr, big0, NTOK_VFT, DD, DD, 0); // mha4 K
    gemm(vft, map_perm, AW(4,2), ABI(4,2), nullptr, nullptr, big1, NTOK_VFT, DD, DD, 0); // mha4 V
    gemm(vft, nullptr,  AW(6,1), ABI(6,1), nullptr, nullptr, big4, NTOK_VFT, DD, DD, 0); // mha6 K (50176 rows!)
    gemm(vft, nullptr,  AW(6,2), ABI(6,2), nullptr, nullptr, big5, NTOK_VFT, DD, DD, 0); // mha6 V

    // ---- mha0: causal self-attention ----
    gemm(lnbuf, nullptr, AW(0,0), ABI(0,0), nullptr, nullptr, qb, NTOK_X, DD, DD, 0);
    gemm(lnbuf, nullptr, AW(0,1), ABI(0,1), nullptr, nullptr, ks, NTOK_X, DD, DD, 0);
    gemm(lnbuf, nullptr, AW(0,2), ABI(0,2), nullptr, nullptr, vs, NTOK_X, DD, DD, 0);
    attn(qb, ks, vs, ab, BB, TTRG, 1, trg_m, 1, 1);
    gemm(ab, nullptr, AW(0,3), ABI(0,3), x, nullptr, cur, NTOK_X, DD, DD, 0);

    // ---- mha1..3 ----
    {
        const float* kvsrc[3] = { his, cap, qry };
        const int    kvrows[3] = { BB*128, BB*64, BB*32 };
        const int    Lks[3]    = { 128, 64, 32 };
        const int*   masks[3]  = { his_m, cap_m, qry_m };
        for (int a = 0; a < 3; a++) {
            int wi = a + 1;
            ln(cur, wi, lnbuf, NTOK_X);
            gemm(lnbuf, nullptr, AW(wi,0), ABI(wi,0), nullptr, nullptr, qb, NTOK_X, DD, DD, 0);
            gemm(kvsrc[a], nullptr, AW(wi,1), ABI(wi,1), nullptr, nullptr, ks, kvrows[a], DD, DD, 0);
            gemm(kvsrc[a], nullptr, AW(wi,2), ABI(wi,2), nullptr, nullptr, vs, kvrows[a], DD, DD, 0);
            attn(qb, ks, vs, ab, BB, Lks[a], 1, masks[a], 2, 1);
            gemm(ab, nullptr, AW(wi,3), ABI(wi,3), cur, nullptr, cur, NTOK_X, DD, DD, 0);
        }
    }

    // ---- temporal2spatial: mha4 ----
    ln(cur, 4, lnbuf, NTOK_X);
    gemm(lnbuf, nullptr, AW(4,0), ABI(4,0), nullptr, nullptr, qb, NTOK_X, DD, DD, 0);
    attn(qb, big0, big1, big2, BB*SS, TT, SS, tmp_m, 2, SS);
    gemm(big2, nullptr, AW(4,3), ABI(4,3), cur, res_t, big3, NTOK_VFT, DD, DD, 0);

    // ---- mha5 ----
    ln(cur, 5, lnbuf, NTOK_X);
    gemm(lnbuf, nullptr, AW(5,0), ABI(5,0), nullptr, nullptr, qb, NTOK_X, DD, DD, 0);
    gemm(big3, map_pt, AW(5,1), ABI(5,1), nullptr, nullptr, big0, NTOK_VFT, DD, DD, 0);
    gemm(big3, map_pt, AW(5,2), ABI(5,2), nullptr, nullptr, big1, NTOK_VFT, DD, DD, 0);
    attn1(qb, big0, big1, ab, NTOK_X, SS, nullptr, 0, 1);
    gemm(ab, nullptr, AW(5,3), ABI(5,3), cur, nullptr, ts, NTOK_X, DD, DD, 0);
    // ffn0
    ln(ts, 6, lnbuf, NTOK_X);
    gemm(lnbuf, nullptr, ffw1 + 0*DD*DFF, ffb1 + 0*DFF, nullptr, nullptr, ffh, NTOK_X, DFF, DD, 1);
    gemm(ffh, nullptr, ffw2 + 0*DFF*DD, ffb2 + 0*DD, ts, nullptr, ts, NTOK_X, DD, DFF, 0);

    // ---- spatial2temporal: mha6 ----
    ln(cur, 7, lnbuf, NTOK_X);
    gemm(lnbuf, nullptr, AW(6,0), ABI(6,0), nullptr, nullptr, qb, NTOK_X, DD, DD, 0);
    attn(qb, big4, big5, big2, BB*TT, SS, TT, nullptr, 0, 1);
    gemm(big2, nullptr, AW(6,3), ABI(6,3), cur, res_s, big3, NTOK_SOUT, DD, DD, 0);

    // ---- mha7 ----
    ln(cur, 8, lnbuf, NTOK_X);
    gemm(lnbuf, nullptr, AW(7,0), ABI(7,0), nullptr, nullptr, qb, NTOK_X, DD, DD, 0);
    gemm(big3, map_ps, AW(7,1), ABI(7,1), nullptr, nullptr, big0, NTOK_SOUT, DD, DD, 0);
    gemm(big3, map_ps, AW(7,2), ABI(7,2), nullptr, nullptr, big1, NTOK_SOUT, DD, DD, 0);
    attn1(qb, big0, big1, ab, NTOK_X, TT, tmp_m, 2, TTRG);
    gemm(ab, nullptr, AW(7,3), ABI(7,3), cur, nullptr, st, NTOK_X, DD, DD, 0);
    // ffn1
    ln(st, 9, lnbuf, NTOK_X);
    gemm(lnbuf, nullptr, ffw1 + 1*DD*DFF, ffb1 + 1*DFF, nullptr, nullptr, ffh, NTOK_X, DFF, DD, 1);
    gemm(ffh, nullptr, ffw2 + 1*DFF*DD, ffb2 + 1*DD, st, nullptr, st, NTOK_X, DD, DFF, 0);

    // ---- combine + ffn2 ----
    add_kernel<<<(NTOK_X*DD + 255)/256, 256>>>(ts, st, cur, NTOK_X*DD);
    ln(cur, 10, lnbuf, NTOK_X);
    gemm(lnbuf, nullptr, ffw1 + 2*DD*DFF, ffb1 + 2*DFF, nullptr, nullptr, ffh, NTOK_X, DFF, DD, 1);
    gemm(ffh, nullptr, ffw2 + 2*DFF*DD, ffb2 + 2*DD, cur, nullptr, out, NTOK_X, DD, DFF, 0);

    #undef AW
    #undef ABI
}

// round 8
// speedup vs baseline: 3.5378x; 1.0535x over previous
#include <cuda_runtime.h>
#include <math.h>
#include <stdint.h>

// ---------------- problem constants ----------------
#define BB   16
#define TTRG 64
#define TT   64
#define SS   49
#define DD   512
#define DFF  2048
#define HH   8
#define NTOK_X    (BB*TTRG)          // 1024
#define NTOK_VFT  (BB*TT*SS)         // 50176
#define NTOK_SOUT (BB*TT*TTRG)       // 65536

// ---------------- scratch ----------------
__device__ float g_cur [NTOK_X*DD];
__device__ float g_ln  [NTOK_X*DD];
__device__ float g_q   [NTOK_X*DD];
__device__ float g_ks  [2048*DD];
__device__ float g_vs  [2048*DD];
__device__ float g_attn[NTOK_X*DD];
__device__ float g_ts  [NTOK_X*DD];
__device__ float g_st  [NTOK_X*DD];
__device__ float g_ffh [NTOK_X*DFF];
__device__ float g_big0[NTOK_SOUT*DD];
__device__ float g_big1[NTOK_SOUT*DD];
__device__ float g_big2[NTOK_SOUT*DD];
__device__ float g_big3[NTOK_SOUT*DD];
__device__ float g_big4[NTOK_SOUT*DD];
__device__ float g_big5[NTOK_SOUT*DD];
__device__ int   g_map_perm[NTOK_VFT];
__device__ int   g_map_pt  [NTOK_VFT];
__device__ int   g_map_ps  [NTOK_SOUT];
__device__ int   g_res_t   [NTOK_VFT];
__device__ int   g_res_s   [NTOK_SOUT];

// ---------------- fused map builder ----------------
__device__ __forceinline__ int swap_map(int m, int Bd, int Cd) {
    int c = m % Cd;
    int b = (m / Cd) % Bd;
    int a = m / (Cd*Bd);
    return (a*Cd + c)*Bd + b;
}
__global__ void build_maps_kernel() {
    int m = blockIdx.x*256 + threadIdx.x;
    int job = blockIdx.y;
    if (job == 0)      { if (m < NTOK_VFT)  g_map_perm[m] = swap_map(m, SS, TT); }
    else if (job == 1) { if (m < NTOK_VFT)  g_map_pt[m]   = swap_map(m, TTRG, SS); }
    else if (job == 2) { if (m < NTOK_SOUT) g_map_ps[m]   = swap_map(m, TTRG, TT); }
    else if (job == 3) { if (m < NTOK_VFT)  g_res_t[m]    = (m/(SS*TT))*TTRG + (m % TTRG); }
    else               { if (m < NTOK_SOUT) g_res_s[m]    = (m/(TT*TTRG))*TTRG + (m % TTRG); }
}

// ---------------- layernorm (D=512) ----------------
__global__ __launch_bounds__(128) void ln_kernel(const float* __restrict__ in,
                                                 const float* __restrict__ gamma,
                                                 const float* __restrict__ beta,
                                                 float* __restrict__ out) {
    int row = blockIdx.x;
    int tid = threadIdx.x;
    const float4* p = reinterpret_cast<const float4*>(in + (long)row*DD);
    float4 v = p[tid];
    float s = v.x + v.y + v.z + v.w;
    float q = v.x*v.x + v.y*v.y + v.z*v.z + v.w*v.w;
    #pragma unroll
    for (int o = 16; o; o >>= 1) {
        s += __shfl_xor_sync(0xffffffffu, s, o);
        q += __shfl_xor_sync(0xffffffffu, q, o);
    }
    __shared__ float ssum[4], ssq[4];
    int warp = tid >> 5, lane = tid & 31;
    if (lane == 0) { ssum[warp] = s; ssq[warp] = q; }
    __syncthreads();
    __shared__ float smean, sinv;
    if (tid == 0) {
        float S = ssum[0]+ssum[1]+ssum[2]+ssum[3];
        float Q = ssq[0]+ssq[1]+ssq[2]+ssq[3];
        float mean = S * (1.0f/DD);
        float var  = Q * (1.0f/DD) - mean*mean;
        float sd   = sqrtf(fmaxf(var, 0.0f));
        smean = mean;
        sinv  = 1.0f / (sd + 1e-6f);
    }
    __syncthreads();
    float mean = smean, inv = sinv;
    float4 gv = reinterpret_cast<const float4*>(gamma)[tid];
    float4 bv = reinterpret_cast<const float4*>(beta)[tid];
    float4 o;
    o.x = gv.x*(v.x-mean)*inv + bv.x;
    o.y = gv.y*(v.y-mean)*inv + bv.y;
    o.z = gv.z*(v.z-mean)*inv + bv.z;
    o.w = gv.w*(v.w-mean)*inv + bv.w;
    reinterpret_cast<float4*>(out + (long)row*DD)[tid] = o;
}

// ---------------- tf32/cp.async/ldmatrix helpers ----------------
__device__ __forceinline__ void mma_tf32(float* c, const uint32_t* a, const uint32_t* b) {
    asm volatile("mma.sync.aligned.m16n8k8.row.col.f32.tf32.tf32.f32 "
        "{%0,%1,%2,%3}, {%4,%5,%6,%7}, {%8,%9}, {%0,%1,%2,%3};"
        : "+f"(c[0]), "+f"(c[1]), "+f"(c[2]), "+f"(c[3])
        : "r"(a[0]), "r"(a[1]), "r"(a[2]), "r"(a[3]), "r"(b[0]), "r"(b[1]));
}
__device__ __forceinline__ void cp_async16(void* smem_ptr, const void* gptr) {
    uint32_t s = (uint32_t)__cvta_generic_to_shared(smem_ptr);
    asm volatile("cp.async.cg.shared.global [%0], [%1], 16;" :: "r"(s), "l"(gptr));
}
#define CP_COMMIT() asm volatile("cp.async.commit_group;")
#define CP_WAIT0()  asm volatile("cp.async.wait_group 0;")
__device__ __forceinline__ void ldsm_x4(uint32_t* r, const void* p) {
    uint32_t a = (uint32_t)__cvta_generic_to_shared(p);
    asm volatile("ldmatrix.sync.aligned.m8n8.x4.shared.b16 {%0,%1,%2,%3}, [%4];"
        : "=r"(r[0]), "=r"(r[1]), "=r"(r[2]), "=r"(r[3]) : "r"(a));
}

// ---------------- multi-chunk tf32 GEMM (128x128 tile, Kc=32, double-buffered) ----
// N per chunk, grid.x = nch * N/128; chunk = blockIdx.x / (N/128).
// A smem row-major [128][36]; B smem k-major [32][136].
#define TCP 136
#define ASP 36

struct GemmChunks {
    const float* w[3];
    const float* b[3];
    float*       c[3];
};

__global__ __launch_bounds__(256, 2) void sgemm_tc_kernel(
    const float* __restrict__ A, const int* __restrict__ amap,
    GemmChunks ch,
    const float* __restrict__ R, const int* __restrict__ rmap,
    int M, int N, int K, int relu)
{
    __shared__ float As[2][128][ASP];
    __shared__ float Bs[2][32][TCP];
    __shared__ int rowm[128];
    int tid = threadIdx.x;
    int ntiles = N >> 7;
    int widx = blockIdx.x / ntiles;
    int n0 = (blockIdx.x % ntiles) << 7;
    int m0 = blockIdx.y << 7;
    const float* W    = ch.w[widx];
    const float* bias = ch.b[widx];
    float*       C    = ch.c[widx];
    if (tid < 128) rowm[tid] = amap ? amap[m0 + tid] : (m0 + tid);
    __syncthreads();

    int wid = tid >> 5, lane = tid & 31;
    int warp_m = wid >> 2, warp_n = wid & 3;
    int gr = lane >> 2, gc = lane & 3;
    int lrow = lane & 15, lkq = (lane >> 4) << 2;

    int arow = tid >> 1, ak = (tid & 1) << 4;   // 16 k-floats per thread
    const float* aptr = A + (long)rowm[arow]*K + ak;
    int bk = tid >> 5, bn = (lane) << 2;        // rows bk, bk+8, bk+16, bk+24
    const float* bptr = W + (long)bk*N + n0 + bn;

    float acc[4][4][4];
    #pragma unroll
    for (int i = 0; i < 4; i++)
        #pragma unroll
        for (int j = 0; j < 4; j++)
            #pragma unroll
            for (int u = 0; u < 4; u++) acc[i][j][u] = 0.0f;

    // preload tile 0
    #pragma unroll
    for (int q = 0; q < 4; q++)
        cp_async16(&As[0][arow][ak + q*4], aptr + q*4);
    #pragma unroll
    for (int q = 0; q < 4; q++)
        cp_async16(&Bs[0][bk + q*8][bn], bptr + (long)(q*8)*N);
    CP_COMMIT();
    CP_WAIT0();
    __syncthreads();

    int buf = 0;
    for (int k0 = 0; k0 < K; k0 += 32) {
        bool has_next = (k0 + 32) < K;
        if (has_next) {
            #pragma unroll
            for (int q = 0; q < 4; q++)
                cp_async16(&As[buf^1][arow][ak + q*4], aptr + k0 + 32 + q*4);
            #pragma unroll
            for (int q = 0; q < 4; q++)
                cp_async16(&Bs[buf^1][bk + q*8][bn], bptr + (long)(k0 + 32 + q*8)*N);
            CP_COMMIT();
        }
        #pragma unroll
        for (int ks = 0; ks < 4; ks++) {
            int kb = ks << 3;
            uint32_t af[4][4], bf[4][2];
            #pragma unroll
            for (int mt = 0; mt < 4; mt++) {
                int mb = (warp_m << 6) + (mt << 4) + lrow;
                ldsm_x4(af[mt], &As[buf][mb][kb + lkq]);
            }
            #pragma unroll
            for (int nt = 0; nt < 4; nt++) {
                int nb = (warp_n << 5) + (nt << 3) + gr;
                bf[nt][0] = __float_as_uint(Bs[buf][kb+gc  ][nb]);
                bf[nt][1] = __float_as_uint(Bs[buf][kb+gc+4][nb]);
            }
            #pragma unroll
            for (int mt = 0; mt < 4; mt++)
                #pragma unroll
                for (int nt = 0; nt < 4; nt++)
                    mma_tf32(acc[mt][nt], af[mt], bf[nt]);
        }
        if (has_next) CP_WAIT0();
        __syncthreads();
        buf ^= 1;
    }

    #pragma unroll
    for (int mt = 0; mt < 4; mt++) {
        #pragma unroll
        for (int half = 0; half < 2; half++) {
            int m = m0 + (warp_m << 6) + (mt << 4) + gr + (half << 3);
            long rbase = 0;
            if (R) rbase = (long)(rmap ? rmap[m] : m) * N;
            #pragma unroll
            for (int nt = 0; nt < 4; nt++) {
                int n = n0 + (warp_n << 5) + (nt << 3) + (gc << 1);
                float v0 = acc[mt][nt][half*2 + 0];
                float v1 = acc[mt][nt][half*2 + 1];
                if (bias) { v0 += bias[n]; v1 += bias[n+1]; }
                if (relu) { v0 = fmaxf(v0, 0.0f); v1 = fmaxf(v1, 0.0f); }
                if (R) {
                    float2 rv = *reinterpret_cast<const float2*>(R + rbase + n);
                    v0 += rv.x; v1 += rv.y;
                }
                *reinterpret_cast<float2*>(C + (long)m*N + n) = make_float2(v0, v1);
            }
        }
    }
}

// ---------------- tensor-core attention, Lq=64, dk=64 ----------------
__global__ __launch_bounds__(256) void attn_tc_kernel(
    const float* __restrict__ Q, const float* __restrict__ Kg,
    const float* __restrict__ Vg, float* __restrict__ O,
    int Lk, int LkPad, int q_group,
    const int* __restrict__ mask, int mask_mode, int mask_div)
{
    extern __shared__ float sm[];
    float* sQ  = sm;                    // 64*68
    float* sKV = sm + 64*68;            // LkPad*68
    float* sS  = sKV + LkPad*68;        // 64*(LkPad+4)
    int batch = blockIdx.x, h = blockIdx.y;
    int tid = threadIdx.x;
    int qbase = (batch / q_group) * 64;
    int sp = LkPad + 4;

    int wid = tid >> 5, lane = tid & 31;
    int warp_m = wid >> 2, warp_n = wid & 3;
    int gr = lane >> 2, gc = lane & 3;
    int nw  = LkPad >> 2;
    int ntn = LkPad >> 5;

    for (int c4 = tid; c4 < 64*16; c4 += 256) {
        int i = c4 >> 4, d = (c4 & 15) << 2;
        cp_async16(&sQ[i*68 + d], &Q[(long)(qbase + i)*DD + h*64 + d]);
    }
    for (int c4 = tid; c4 < Lk*16; c4 += 256) {
        int j = c4 >> 4, d = (c4 & 15) << 2;
        cp_async16(&sKV[j*68 + d], &Kg[(long)(batch*Lk + j)*DD + h*64 + d]);
    }
    CP_COMMIT();
    for (int idx = Lk*64 + tid; idx < LkPad*64; idx += 256) {
        int j = idx >> 6, d = idx & 63;
        sKV[j*68 + d] = 0.0f;
    }
    CP_WAIT0();
    __syncthreads();

    // scores
    {
        float acc[2][4][4];
        #pragma unroll
        for (int mt = 0; mt < 2; mt++)
            #pragma unroll
            for (int nt = 0; nt < 4; nt++)
                #pragma unroll
                for (int u = 0; u < 4; u++) acc[mt][nt][u] = 0.0f;

        for (int kb = 0; kb < 64; kb += 8) {
            uint32_t af[2][4];
            #pragma unroll
            for (int mt = 0; mt < 2; mt++) {
                int mr = warp_m*32 + mt*16 + gr;
                af[mt][0] = __float_as_uint(sQ[mr*68 + kb+gc]);
                af[mt][1] = __float_as_uint(sQ[(mr+8)*68 + kb+gc]);
                af[mt][2] = __float_as_uint(sQ[mr*68 + kb+gc+4]);
                af[mt][3] = __float_as_uint(sQ[(mr+8)*68 + kb+gc+4]);
            }
            for (int nt = 0; nt < ntn; nt++) {
                int nc = warp_n*nw + nt*8 + gr;
                uint32_t bf[2];
                bf[0] = __float_as_uint(sKV[nc*68 + kb+gc]);
                bf[1] = __float_as_uint(sKV[nc*68 + kb+gc+4]);
                mma_tf32(acc[0][nt], af[0], bf);
                mma_tf32(acc[1][nt], af[1], bf);
            }
        }
        #pragma unroll
        for (int mt = 0; mt < 2; mt++)
            for (int nt = 0; nt < ntn; nt++) {
                int row = warp_m*32 + mt*16 + gr;
                int col = warp_n*nw + nt*8 + (gc << 1);
                sS[row*sp + col]       = acc[mt][nt][0]*0.125f;
                sS[row*sp + col + 1]   = acc[mt][nt][1]*0.125f;
                sS[(row+8)*sp + col]   = acc[mt][nt][2]*0.125f;
                sS[(row+8)*sp + col+1] = acc[mt][nt][3]*0.125f;
            }
    }
    __syncthreads();

    for (int c4 = tid; c4 < Lk*16; c4 += 256) {
        int j = c4 >> 4, d = (c4 & 15) << 2;
        cp_async16(&sKV[j*68 + d], &Vg[(long)(batch*Lk + j)*DD + h*64 + d]);
    }
    CP_COMMIT();

    for (int i = wid; i < 64; i += 8) {
        float mx = -3.4e38f;
        for (int j = lane; j < Lk; j += 32) {
            float v = sS[i*sp + j];
            bool dead = false;
            if (mask_mode == 1) dead = (mask[(long)(batch*64 + i)*Lk + j] == 0);
            else if (mask_mode == 2) dead = (mask[(batch/mask_div)*Lk + j] == 0);
            if (dead) { v = -1e9f; sS[i*sp + j] = v; }
            mx = fmaxf(mx, v);
        }
        #pragma unroll
        for (int o = 16; o; o >>= 1) mx = fmaxf(mx, __shfl_xor_sync(0xffffffffu, mx, o));
        float sum = 0.0f;
        for (int j = lane; j < Lk; j += 32) {
            float e = __expf(sS[i*sp + j] - mx);
            sS[i*sp + j] = e;
            sum += e;
        }
        #pragma unroll
        for (int o = 16; o; o >>= 1) sum += __shfl_xor_sync(0xffffffffu, sum, o);
        float inv = 1.0f / sum;
        for (int j = lane; j < Lk; j += 32) sS[i*sp + j] *= inv;
        for (int j = Lk + lane; j < LkPad; j += 32) sS[i*sp + j] = 0.0f;
    }
    CP_WAIT0();
    __syncthreads();

    // O = P @ V
    {
        float acc[2][2][4];
        #pragma unroll
        for (int mt = 0; mt < 2; mt++)
            #pragma unroll
            for (int nt = 0; nt < 2; nt++)
                #pragma unroll
                for (int u = 0; u < 4; u++) acc[mt][nt][u] = 0.0f;

        for (int kb = 0; kb < LkPad; kb += 8) {
            uint32_t af[2][4];
            #pragma unroll
            for (int mt = 0; mt < 2; mt++) {
                int mr = warp_m*32 + mt*16 + gr;
                af[mt][0] = __float_as_uint(sS[mr*sp + kb+gc]);
                af[mt][1] = __float_as_uint(sS[(mr+8)*sp + kb+gc]);
                af[mt][2] = __float_as_uint(sS[mr*sp + kb+gc+4]);
                af[mt][3] = __float_as_uint(sS[(mr+8)*sp + kb+gc+4]);
            }
            #pragma unroll
            for (int nt = 0; nt < 2; nt++) {
                int nc = warp_n*16 + nt*8 + gr;
                uint32_t bf[2];
                int k0r = kb+gc, k1r = kb+gc+4;
                bf[0] = (k0r < Lk) ? __float_as_uint(sKV[k0r*68 + nc]) : 0u;
                bf[1] = (k1r < Lk) ? __float_as_uint(sKV[k1r*68 + nc]) : 0u;
                mma_tf32(acc[0][nt], af[0], bf);
                mma_tf32(acc[1][nt], af[1], bf);
            }
        }
        #pragma unroll
        for (int mt = 0; mt < 2; mt++)
            #pragma unroll
            for (int nt = 0; nt < 2; nt++) {
                int i = warp_m*32 + mt*16 + gr;
                int d = warp_n*16 + nt*8 + (gc << 1);
                long base = (long)(batch*64 + i)*DD + h*64 + d;
                *reinterpret_cast<float2*>(O + base) =
                    make_float2(acc[mt][nt][0], acc[mt][nt][1]);
                *reinterpret_cast<float2*>(O + base + 8*DD) =
                    make_float2(acc[mt][nt][2], acc[mt][nt][3]);
            }
    }
}

// ---------------- fp32 attention for Lq=1 (mha5/mha7) ----------------
#define KVP 68
__global__ __launch_bounds__(256) void attn1_kernel(
    const float* __restrict__ Q, const float* __restrict__ Kg,
    const float* __restrict__ Vg, float* __restrict__ O,
    int Lk, const int* __restrict__ mask, int mask_mode, int mask_div)
{
    extern __shared__ float sm[];
    float* sQ  = sm;
    float* sKV = sm + 64;
    float* sS  = sKV + 32*KVP;
    int batch = blockIdx.x, h = blockIdx.y;
    int tid = threadIdx.x;

    if (tid < 64) sQ[tid] = Q[(long)batch*DD + h*64 + tid];
    for (int jt = 0; jt < Lk; jt += 32) {
        __syncthreads();
        for (int idx = tid; idx < 32*64; idx += 256) {
            int j = idx >> 6, d = idx & 63;
            int jj = jt + j;
            sKV[j*KVP + d] = (jj < Lk) ? Kg[(long)(batch*Lk + jj)*DD + h*64 + d] : 0.0f;
        }
        __syncthreads();
        if (tid < 32) {
            int jj = jt + tid;
            if (jj < Lk) {
                const float4* q4 = reinterpret_cast<const float4*>(sQ);
                const float4* k4 = reinterpret_cast<const float4*>(sKV + tid*KVP);
                float s = 0.0f;
                #pragma unroll
                for (int d = 0; d < 16; d++) {
                    float4 a = q4[d], b = k4[d];
                    s += a.x*b.x + a.y*b.y + a.z*b.z + a.w*b.w;
                }
                s *= 0.125f;
                if (mask_mode == 2 && mask[(batch/mask_div)*Lk + jj] == 0) s = -1e9f;
                sS[jj] = s;
            }
        }
    }
    __syncthreads();
    if (tid < 32) {
        float m = -3.4e38f;
        for (int j = tid; j < Lk; j += 32) m = fmaxf(m, sS[j]);
        #pragma unroll
        for (int o = 16; o; o >>= 1) m = fmaxf(m, __shfl_xor_sync(0xffffffffu, m, o));
        float sum = 0.0f;
        for (int j = tid; j < Lk; j += 32) {
            float e = __expf(sS[j] - m);
            sS[j] = e;
            sum += e;
        }
        #pragma unroll
        for (int o = 16; o; o >>= 1) sum += __shfl_xor_sync(0xffffffffu, sum, o);
        float inv = 1.0f / sum;
        for (int j = tid; j < Lk; j += 32) sS[j] *= inv;
    }
    float acc = 0.0f;
    for (int jt = 0; jt < Lk; jt += 32) {
        __syncthreads();
        for (int idx = tid; idx < 32*64; idx += 256) {
            int j = idx >> 6, dd = idx & 63;
            int jj = jt + j;
            sKV[j*KVP + dd] = (jj < Lk) ? Vg[(long)(batch*Lk + jj)*DD + h*64 + dd] : 0.0f;
        }
        __syncthreads();
        if (tid < 64) {
            int lim = min(32, Lk - jt);
            for (int j = 0; j < lim; j++) acc += sS[jt + j] * sKV[j*KVP + tid];
        }
    }
    if (tid < 64) O[(long)batch*DD + h*64 + tid] = acc;
}

// ---------------- elementwise add ----------------
__global__ void add_kernel(const float* __restrict__ a, const float* __restrict__ b,
                           float* __restrict__ c, int n) {
    int i = blockIdx.x*256 + threadIdx.x;
    if (i < n) c[i] = a[i] + b[i];
}

// ---------------- host ----------------
static float* sym_f(const void* s) { void* p = nullptr; cudaGetSymbolAddress(&p, s); return (float*)p; }
static int*   sym_i(const void* s) { void* p = nullptr; cudaGetSymbolAddress(&p, s); return (int*)p; }

extern "C" void kernel_launch(void* const* d_in, const int* in_sizes, int n_in,
                              void* d_out, int out_size) {
    const float* x    = (const float*)d_in[0];
    const float* vft  = (const float*)d_in[1];
    const float* his  = (const float*)d_in[2];
    const float* cap  = (const float*)d_in[3];
    const float* qry  = (const float*)d_in[4];
    const int* trg_m  = (const int*)d_in[5];
    const int* his_m  = (const int*)d_in[6];
    const int* cap_m  = (const int*)d_in[7];
    const int* qry_m  = (const int*)d_in[8];
    const int* tmp_m  = (const int*)d_in[9];
    const float* attw = (const float*)d_in[10];
    const float* attb = (const float*)d_in[11];
    const float* ffw1 = (const float*)d_in[12];
    const float* ffb1 = (const float*)d_in[13];
    const float* ffw2 = (const float*)d_in[14];
    const float* ffb2 = (const float*)d_in[15];
    const float* lng  = (const float*)d_in[16];
    const float* lnb  = (const float*)d_in[17];
    float* out = (float*)d_out;

    float* cur   = sym_f(g_cur);
    float* lnbuf = sym_f(g_ln);
    float* qb    = sym_f(g_q);
    float* ks    = sym_f(g_ks);
    float* vs    = sym_f(g_vs);
    float* ab    = sym_f(g_attn);
    float* ts    = sym_f(g_ts);
    float* st    = sym_f(g_st);
    float* ffh   = sym_f(g_ffh);
    float* big0  = sym_f(g_big0);
    float* big1  = sym_f(g_big1);
    float* big2  = sym_f(g_big2);
    float* big3  = sym_f(g_big3);
    float* big4  = sym_f(g_big4);
    float* big5  = sym_f(g_big5);
    int* map_perm = sym_i(g_map_perm);
    int* map_pt   = sym_i(g_map_pt);
    int* map_ps   = sym_i(g_map_ps);
    int* res_t    = sym_i(g_res_t);
    int* res_s    = sym_i(g_res_s);

    cudaFuncSetAttribute((const void*)attn_tc_kernel,
                         cudaFuncAttributeMaxDynamicSharedMemorySize, 120*1024);
    cudaFuncSetAttribute((const void*)attn1_kernel,
                         cudaFuncAttributeMaxDynamicSharedMemorySize, 32*1024);

    #define AW(i,j) (attw + ((i)*4+(j))*DD*DD)
    #define ABI(i,j) (attb + ((i)*4+(j))*DD)

    // batched gemm: up to 3 (W,bias,C) chunks sharing A
    auto gemmN = [](const float* A, const int* amap, int nch,
                    const float* w0, const float* b0, float* c0,
                    const float* w1, const float* b1, float* c1,
                    const float* w2, const float* b2, float* c2,
                    const float* R, const int* rmap,
                    int M, int N, int K, int relu) {
        GemmChunks ch;
        ch.w[0] = w0; ch.b[0] = b0; ch.c[0] = c0;
        ch.w[1] = w1; ch.b[1] = b1; ch.c[1] = c1;
        ch.w[2] = w2; ch.b[2] = b2; ch.c[2] = c2;
        dim3 grid(nch * (N/128), M/128);
        sgemm_tc_kernel<<<grid, 256>>>(A, amap, ch, R, rmap, M, N, K, relu);
    };
    auto gemm = [&](const float* A, const int* amap, const float* W, const float* bias,
                    const float* R, const int* rmap, float* C, int M, int N, int K, int relu) {
        gemmN(A, amap, 1, W, bias, C, nullptr, nullptr, nullptr,
              nullptr, nullptr, nullptr, R, rmap, M, N, K, relu);
    };
    auto attn = [](const float* Q, const float* K, const float* V, float* O,
                   int NB, int Lk, int qg, const int* mask, int mode, int mdiv) {
        int LkPad = (Lk + 31) & ~31;
        size_t sh = (size_t)(64*68 + LkPad*68 + 64*(LkPad+4)) * sizeof(float);
        attn_tc_kernel<<<dim3(NB, HH), 256, sh>>>(Q, K, V, O, Lk, LkPad, qg, mask, mode, mdiv);
    };
    auto attn1 = [](const float* Q, const float* K, const float* V, float* O,
                    int NB, int Lk, const int* mask, int mode, int mdiv) {
        size_t sh = (size_t)(64 + 32*KVP + Lk) * sizeof(float);
        attn1_kernel<<<dim3(NB, HH), 256, sh>>>(Q, K, V, O, Lk, mask, mode, mdiv);
    };
    auto ln = [&](const float* in, int li, float* o, int rows) {
        ln_kernel<<<rows, 128>>>(in, lng + li*DD, lnb + li*DD, o);
    };

    build_maps_kernel<<<dim3(256, 5), 256>>>();
    ln(x, 0, lnbuf, NTOK_X);
    // big vft projections
    gemm(vft, map_perm, AW(4,1), ABI(4,1), nullptr, nullptr, big0, NTOK_VFT, DD, DD, 0);
    gemm(vft, map_perm, AW(4,2), ABI(4,2), nullptr, nullptr, big1, NTOK_VFT, DD, DD, 0);
    gemm(vft, nullptr,  AW(6,1), ABI(6,1), nullptr, nullptr, big4, NTOK_VFT, DD, DD, 0);
    gemm(vft, nullptr,  AW(6,2), ABI(6,2), nullptr, nullptr, big5, NTOK_VFT, DD, DD, 0);

    // ---- mha0: QKV in one launch ----
    gemmN(lnbuf, nullptr, 3,
          AW(0,0), ABI(0,0), qb, AW(0,1), ABI(0,1), ks, AW(0,2), ABI(0,2), vs,
          nullptr, nullptr, NTOK_X, DD, DD, 0);
    attn(qb, ks, vs, ab, BB, TTRG, 1, trg_m, 1, 1);
    gemm(ab, nullptr, AW(0,3), ABI(0,3), x, nullptr, cur, NTOK_X, DD, DD, 0);

    // ---- mha1..3 ----
    {
        const float* kvsrc[3] = { his, cap, qry };
        const int    kvrows[3] = { BB*128, BB*64, BB*32 };
        const int    Lks[3]    = { 128, 64, 32 };
        const int*   masks[3]  = { his_m, cap_m, qry_m };
        for (int a = 0; a < 3; a++) {
            int wi = a + 1;
            ln(cur, wi, lnbuf, NTOK_X);
            gemm(lnbuf, nullptr, AW(wi,0), ABI(wi,0), nullptr, nullptr, qb, NTOK_X, DD, DD, 0);
            gemmN(kvsrc[a], nullptr, 2,
                  AW(wi,1), ABI(wi,1), ks, AW(wi,2), ABI(wi,2), vs,
                  nullptr, nullptr, nullptr,
                  nullptr, nullptr, kvrows[a], DD, DD, 0);
            attn(qb, ks, vs, ab, BB, Lks[a], 1, masks[a], 2, 1);
            gemm(ab, nullptr, AW(wi,3), ABI(wi,3), cur, nullptr, cur, NTOK_X, DD, DD, 0);
        }
    }

    // ---- temporal2spatial: mha4 ----
    ln(cur, 4, lnbuf, NTOK_X);
    gemm(lnbuf, nullptr, AW(4,0), ABI(4,0), nullptr, nullptr, qb, NTOK_X, DD, DD, 0);
    attn(qb, big0, big1, big2, BB*SS, TT, SS, tmp_m, 2, SS);
    gemm(big2, nullptr, AW(4,3), ABI(4,3), cur, res_t, big3, NTOK_VFT, DD, DD, 0);

    // ---- mha5 ----
    ln(cur, 5, lnbuf, NTOK_X);
    gemm(lnbuf, nullptr, AW(5,0), ABI(5,0), nullptr, nullptr, qb, NTOK_X, DD, DD, 0);
    gemm(big3, map_pt, AW(5,1), ABI(5,1), nullptr, nullptr, big0, NTOK_VFT, DD, DD, 0);
    gemm(big3, map_pt, AW(5,2), ABI(5,2), nullptr, nullptr, big1, NTOK_VFT, DD, DD, 0);
    attn1(qb, big0, big1, ab, NTOK_X, SS, nullptr, 0, 1);
    gemm(ab, nullptr, AW(5,3), ABI(5,3), cur, nullptr, ts, NTOK_X, DD, DD, 0);
    // ffn0
    ln(ts, 6, lnbuf, NTOK_X);
    gemm(lnbuf, nullptr, ffw1 + 0*DD*DFF, ffb1 + 0*DFF, nullptr, nullptr, ffh, NTOK_X, DFF, DD, 1);
    gemm(ffh, nullptr, ffw2 + 0*DFF*DD, ffb2 + 0*DD, ts, nullptr, ts, NTOK_X, DD, DFF, 0);

    // ---- spatial2temporal: mha6 ----
    ln(cur, 7, lnbuf, NTOK_X);
    gemm(lnbuf, nullptr, AW(6,0), ABI(6,0), nullptr, nullptr, qb, NTOK_X, DD, DD, 0);
    attn(qb, big4, big5, big2, BB*TT, SS, TT, nullptr, 0, 1);
    gemm(big2, nullptr, AW(6,3), ABI(6,3), cur, res_s, big3, NTOK_SOUT, DD, DD, 0);

    // ---- mha7 ----
    ln(cur, 8, lnbuf, NTOK_X);
    gemm(lnbuf, nullptr, AW(7,0), ABI(7,0), nullptr, nullptr, qb, NTOK_X, DD, DD, 0);
    gemm(big3, map_ps, AW(7,1), ABI(7,1), nullptr, nullptr, big0, NTOK_SOUT, DD, DD, 0);
    gemm(big3, map_ps, AW(7,2), ABI(7,2), nullptr, nullptr, big1, NTOK_SOUT, DD, DD, 0);
    attn1(qb, big0, big1, ab, NTOK_X, TT, tmp_m, 2, TTRG);
    gemm(ab, nullptr, AW(7,3), ABI(7,3), cur, nullptr, st, NTOK_X, DD, DD, 0);
    // ffn1
    ln(st, 9, lnbuf, NTOK_X);
    gemm(lnbuf, nullptr, ffw1 + 1*DD*DFF, ffb1 + 1*DFF, nullptr, nullptr, ffh, NTOK_X, DFF, DD, 1);
    gemm(ffh, nullptr, ffw2 + 1*DFF*DD, ffb2 + 1*DD, st, nullptr, st, NTOK_X, DD, DFF, 0);

    // ---- combine + ffn2 ----
    add_kernel<<<(NTOK_X*DD + 255)/256, 256>>>(ts, st, cur, NTOK_X*DD);
    ln(cur, 10, lnbuf, NTOK_X);
    gemm(lnbuf, nullptr, ffw1 + 2*DD*DFF, ffb1 + 2*DFF, nullptr, nullptr, ffh, NTOK_X, DFF, DD, 1);
    gemm(ffh, nullptr, ffw2 + 2*DFF*DD, ffb2 + 2*DD, cur, nullptr, out, NTOK_X, DD, DFF, 0);

    #undef AW
    #undef ABI
}

// round 9
// speedup vs baseline: 3.6486x; 1.0313x over previous
#include <cuda_runtime.h>
#include <math.h>
#include <stdint.h>

// ---------------- problem constants ----------------
#define BB   16
#define TTRG 64
#define TT   64
#define SS   49
#define DD   512
#define DFF  2048
#define HH   8
#define NTOK_X    (BB*TTRG)          // 1024
#define NTOK_VFT  (BB*TT*SS)         // 50176
#define NTOK_SOUT (BB*TT*TTRG)       // 65536

// ---------------- scratch ----------------
__device__ float g_cur [NTOK_X*DD];
__device__ float g_ln  [NTOK_X*DD];
__device__ float g_q   [NTOK_X*DD];
__device__ float g_ks  [2048*DD];
__device__ float g_vs  [2048*DD];
__device__ float g_attn[NTOK_X*DD];
__device__ float g_ts  [NTOK_X*DD];
__device__ float g_st  [NTOK_X*DD];
__device__ float g_ffh [NTOK_X*DFF];
__device__ float g_big0[NTOK_SOUT*DD];
__device__ float g_big1[NTOK_SOUT*DD];
__device__ float g_big2[NTOK_SOUT*DD];
__device__ float g_big3[NTOK_SOUT*DD];
__device__ float g_big4[NTOK_SOUT*DD];
__device__ float g_big5[NTOK_SOUT*DD];
__device__ int   g_map_perm[NTOK_VFT];
__device__ int   g_map_pt  [NTOK_VFT];
__device__ int   g_map_ps  [NTOK_SOUT];
__device__ int   g_res_t   [NTOK_VFT];
__device__ int   g_res_s   [NTOK_SOUT];

// ---------------- fused map builder ----------------
__device__ __forceinline__ int swap_map(int m, int Bd, int Cd) {
    int c = m % Cd;
    int b = (m / Cd) % Bd;
    int a = m / (Cd*Bd);
    return (a*Cd + c)*Bd + b;
}
__global__ void build_maps_kernel() {
    int m = blockIdx.x*256 + threadIdx.x;
    int job = blockIdx.y;
    if (job == 0)      { if (m < NTOK_VFT)  g_map_perm[m] = swap_map(m, SS, TT); }
    else if (job == 1) { if (m < NTOK_VFT)  g_map_pt[m]   = swap_map(m, TTRG, SS); }
    else if (job == 2) { if (m < NTOK_SOUT) g_map_ps[m]   = swap_map(m, TTRG, TT); }
    else if (job == 3) { if (m < NTOK_VFT)  g_res_t[m]    = (m/(SS*TT))*TTRG + (m % TTRG); }
    else               { if (m < NTOK_SOUT) g_res_s[m]    = (m/(TT*TTRG))*TTRG + (m % TTRG); }
}

// ---------------- layernorm (D=512) ----------------
__global__ __launch_bounds__(128) void ln_kernel(const float* __restrict__ in,
                                                 const float* __restrict__ gamma,
                                                 const float* __restrict__ beta,
                                                 float* __restrict__ out) {
    int row = blockIdx.x;
    int tid = threadIdx.x;
    const float4* p = reinterpret_cast<const float4*>(in + (long)row*DD);
    float4 v = p[tid];
    float s = v.x + v.y + v.z + v.w;
    float q = v.x*v.x + v.y*v.y + v.z*v.z + v.w*v.w;
    #pragma unroll
    for (int o = 16; o; o >>= 1) {
        s += __shfl_xor_sync(0xffffffffu, s, o);
        q += __shfl_xor_sync(0xffffffffu, q, o);
    }
    __shared__ float ssum[4], ssq[4];
    int warp = tid >> 5, lane = tid & 31;
    if (lane == 0) { ssum[warp] = s; ssq[warp] = q; }
    __syncthreads();
    __shared__ float smean, sinv;
    if (tid == 0) {
        float S = ssum[0]+ssum[1]+ssum[2]+ssum[3];
        float Q = ssq[0]+ssq[1]+ssq[2]+ssq[3];
        float mean = S * (1.0f/DD);
        float var  = Q * (1.0f/DD) - mean*mean;
        float sd   = sqrtf(fmaxf(var, 0.0f));
        smean = mean;
        sinv  = 1.0f / (sd + 1e-6f);
    }
    __syncthreads();
    float mean = smean, inv = sinv;
    float4 gv = reinterpret_cast<const float4*>(gamma)[tid];
    float4 bv = reinterpret_cast<const float4*>(beta)[tid];
    float4 o;
    o.x = gv.x*(v.x-mean)*inv + bv.x;
    o.y = gv.y*(v.y-mean)*inv + bv.y;
    o.z = gv.z*(v.z-mean)*inv + bv.z;
    o.w = gv.w*(v.w-mean)*inv + bv.w;
    reinterpret_cast<float4*>(out + (long)row*DD)[tid] = o;
}

// ---------------- tf32/cp.async/ldmatrix helpers ----------------
__device__ __forceinline__ void mma_tf32(float* c, const uint32_t* a, const uint32_t* b) {
    asm volatile("mma.sync.aligned.m16n8k8.row.col.f32.tf32.tf32.f32 "
        "{%0,%1,%2,%3}, {%4,%5,%6,%7}, {%8,%9}, {%0,%1,%2,%3};"
        : "+f"(c[0]), "+f"(c[1]), "+f"(c[2]), "+f"(c[3])
        : "r"(a[0]), "r"(a[1]), "r"(a[2]), "r"(a[3]), "r"(b[0]), "r"(b[1]));
}
__device__ __forceinline__ void cp_async16(void* smem_ptr, const void* gptr) {
    uint32_t s = (uint32_t)__cvta_generic_to_shared(smem_ptr);
    asm volatile("cp.async.cg.shared.global [%0], [%1], 16;" :: "r"(s), "l"(gptr));
}
#define CP_COMMIT() asm volatile("cp.async.commit_group;")
#define CP_WAIT0()  asm volatile("cp.async.wait_group 0;")
__device__ __forceinline__ void ldsm_x4(uint32_t* r, const void* p) {
    uint32_t a = (uint32_t)__cvta_generic_to_shared(p);
    asm volatile("ldmatrix.sync.aligned.m8n8.x4.shared.b16 {%0,%1,%2,%3}, [%4];"
        : "=r"(r[0]), "=r"(r[1]), "=r"(r[2]), "=r"(r[3]) : "r"(a));
}

// ---------------- multi-chunk tf32 GEMM (128x128 tile, Kc=32, double-buffered) ----
// Fragment-level A double-buffering (ldsm ping-pong) to hide smem latency.
#define TCP 136
#define ASP 36

struct GemmChunks {
    const float* w[3];
    const float* b[3];
    float*       c[3];
};

__global__ __launch_bounds__(256, 2) void sgemm_tc_kernel(
    const float* __restrict__ A, const int* __restrict__ amap,
    GemmChunks ch,
    const float* __restrict__ R, const int* __restrict__ rmap,
    int M, int N, int K, int relu)
{
    __shared__ float As[2][128][ASP];
    __shared__ float Bs[2][32][TCP];
    __shared__ int rowm[128];
    int tid = threadIdx.x;
    int ntiles = N >> 7;
    int widx = blockIdx.x / ntiles;
    int n0 = (blockIdx.x % ntiles) << 7;
    int m0 = blockIdx.y << 7;
    const float* W    = ch.w[widx];
    const float* bias = ch.b[widx];
    float*       C    = ch.c[widx];
    if (tid < 128) rowm[tid] = amap ? amap[m0 + tid] : (m0 + tid);
    __syncthreads();

    int wid = tid >> 5, lane = tid & 31;
    int warp_m = wid >> 2, warp_n = wid & 3;
    int gr = lane >> 2, gc = lane & 3;
    int lrow = lane & 15, lkq = (lane >> 4) << 2;

    int arow = tid >> 1, ak = (tid & 1) << 4;
    const float* aptr = A + (long)rowm[arow]*K + ak;
    int bk = tid >> 5, bn = (lane) << 2;
    const float* bptr = W + (long)bk*N + n0 + bn;

    float acc[4][4][4];
    #pragma unroll
    for (int i = 0; i < 4; i++)
        #pragma unroll
        for (int j = 0; j < 4; j++)
            #pragma unroll
            for (int u = 0; u < 4; u++) acc[i][j][u] = 0.0f;

    // preload tile 0
    #pragma unroll
    for (int q = 0; q < 4; q++)
        cp_async16(&As[0][arow][ak + q*4], aptr + q*4);
    #pragma unroll
    for (int q = 0; q < 4; q++)
        cp_async16(&Bs[0][bk + q*8][bn], bptr + (long)(q*8)*N);
    CP_COMMIT();
    CP_WAIT0();
    __syncthreads();

    int mbase = warp_m << 6;
    int buf = 0;
    for (int k0 = 0; k0 < K; k0 += 32) {
        bool has_next = (k0 + 32) < K;
        if (has_next) {
            #pragma unroll
            for (int q = 0; q < 4; q++)
                cp_async16(&As[buf^1][arow][ak + q*4], aptr + k0 + 32 + q*4);
            #pragma unroll
            for (int q = 0; q < 4; q++)
                cp_async16(&Bs[buf^1][bk + q*8][bn], bptr + (long)(k0 + 32 + q*8)*N);
            CP_COMMIT();
        }
        // fragment double-buffered ks loop
        uint32_t afb[2][4][4];
        #pragma unroll
        for (int mt = 0; mt < 4; mt++)
            ldsm_x4(afb[0][mt], &As[buf][mbase + (mt << 4) + lrow][lkq]);
        #pragma unroll
        for (int ks = 0; ks < 4; ks++) {
            int cur = ks & 1;
            if (ks < 3) {
                #pragma unroll
                for (int mt = 0; mt < 4; mt++)
                    ldsm_x4(afb[cur ^ 1][mt],
                            &As[buf][mbase + (mt << 4) + lrow][((ks + 1) << 3) + lkq]);
            }
            int kb = ks << 3;
            uint32_t bf[4][2];
            #pragma unroll
            for (int nt = 0; nt < 4; nt++) {
                int nb = (warp_n << 5) + (nt << 3) + gr;
                bf[nt][0] = __float_as_uint(Bs[buf][kb+gc  ][nb]);
                bf[nt][1] = __float_as_uint(Bs[buf][kb+gc+4][nb]);
            }
            #pragma unroll
            for (int mt = 0; mt < 4; mt++)
                #pragma unroll
                for (int nt = 0; nt < 4; nt++)
                    mma_tf32(acc[mt][nt], afb[cur][mt], bf[nt]);
        }
        if (has_next) CP_WAIT0();
        __syncthreads();
        buf ^= 1;
    }

    #pragma unroll
    for (int mt = 0; mt < 4; mt++) {
        #pragma unroll
        for (int half = 0; half < 2; half++) {
            int m = m0 + (warp_m << 6) + (mt << 4) + gr + (half << 3);
            long rbase = 0;
            if (R) rbase = (long)(rmap ? rmap[m] : m) * N;
            #pragma unroll
            for (int nt = 0; nt < 4; nt++) {
                int n = n0 + (warp_n << 5) + (nt << 3) + (gc << 1);
                float v0 = acc[mt][nt][half*2 + 0];
                float v1 = acc[mt][nt][half*2 + 1];
                if (bias) { v0 += bias[n]; v1 += bias[n+1]; }
                if (relu) { v0 = fmaxf(v0, 0.0f); v1 = fmaxf(v1, 0.0f); }
                if (R) {
                    float2 rv = *reinterpret_cast<const float2*>(R + rbase + n);
                    v0 += rv.x; v1 += rv.y;
                }
                *reinterpret_cast<float2*>(C + (long)m*N + n) = make_float2(v0, v1);
            }
        }
    }
}

// ---------------- tensor-core attention, Lq=64, dk=64 ----------------
__global__ __launch_bounds__(256) void attn_tc_kernel(
    const float* __restrict__ Q, const float* __restrict__ Kg,
    const float* __restrict__ Vg, float* __restrict__ O,
    int Lk, int LkPad, int q_group,
    const int* __restrict__ mask, int mask_mode, int mask_div)
{
    extern __shared__ float sm[];
    float* sQ  = sm;                    // 64*68
    float* sKV = sm + 64*68;            // LkPad*68
    float* sS  = sKV + LkPad*68;        // 64*(LkPad+4)
    int batch = blockIdx.x, h = blockIdx.y;
    int tid = threadIdx.x;
    int qbase = (batch / q_group) * 64;
    int sp = LkPad + 4;

    int wid = tid >> 5, lane = tid & 31;
    int warp_m = wid >> 2, warp_n = wid & 3;
    int gr = lane >> 2, gc = lane & 3;
    int nw  = LkPad >> 2;
    int ntn = LkPad >> 5;

    for (int c4 = tid; c4 < 64*16; c4 += 256) {
        int i = c4 >> 4, d = (c4 & 15) << 2;
        cp_async16(&sQ[i*68 + d], &Q[(long)(qbase + i)*DD + h*64 + d]);
    }
    for (int c4 = tid; c4 < Lk*16; c4 += 256) {
        int j = c4 >> 4, d = (c4 & 15) << 2;
        cp_async16(&sKV[j*68 + d], &Kg[(long)(batch*Lk + j)*DD + h*64 + d]);
    }
    CP_COMMIT();
    for (int idx = Lk*64 + tid; idx < LkPad*64; idx += 256) {
        int j = idx >> 6, d = idx & 63;
        sKV[j*68 + d] = 0.0f;
    }
    CP_WAIT0();
    __syncthreads();

    // scores
    {
        float acc[2][4][4];
        #pragma unroll
        for (int mt = 0; mt < 2; mt++)
            #pragma unroll
            for (int nt = 0; nt < 4; nt++)
                #pragma unroll
                for (int u = 0; u < 4; u++) acc[mt][nt][u] = 0.0f;

        for (int kb = 0; kb < 64; kb += 8) {
            uint32_t af[2][4];
            #pragma unroll
            for (int mt = 0; mt < 2; mt++) {
                int mr = warp_m*32 + mt*16 + gr;
                af[mt][0] = __float_as_uint(sQ[mr*68 + kb+gc]);
                af[mt][1] = __float_as_uint(sQ[(mr+8)*68 + kb+gc]);
                af[mt][2] = __float_as_uint(sQ[mr*68 + kb+gc+4]);
                af[mt][3] = __float_as_uint(sQ[(mr+8)*68 + kb+gc+4]);
            }
            for (int nt = 0; nt < ntn; nt++) {
                int nc = warp_n*nw + nt*8 + gr;
                uint32_t bf[2];
                bf[0] = __float_as_uint(sKV[nc*68 + kb+gc]);
                bf[1] = __float_as_uint(sKV[nc*68 + kb+gc+4]);
                mma_tf32(acc[0][nt], af[0], bf);
                mma_tf32(acc[1][nt], af[1], bf);
            }
        }
        #pragma unroll
        for (int mt = 0; mt < 2; mt++)
            for (int nt = 0; nt < ntn; nt++) {
                int row = warp_m*32 + mt*16 + gr;
                int col = warp_n*nw + nt*8 + (gc << 1);
                sS[row*sp + col]       = acc[mt][nt][0]*0.125f;
                sS[row*sp + col + 1]   = acc[mt][nt][1]*0.125f;
                sS[(row+8)*sp + col]   = acc[mt][nt][2]*0.125f;
                sS[(row+8)*sp + col+1] = acc[mt][nt][3]*0.125f;
            }
    }
    __syncthreads();

    for (int c4 = tid; c4 < Lk*16; c4 += 256) {
        int j = c4 >> 4, d = (c4 & 15) << 2;
        cp_async16(&sKV[j*68 + d], &Vg[(long)(batch*Lk + j)*DD + h*64 + d]);
    }
    CP_COMMIT();

    for (int i = wid; i < 64; i += 8) {
        float mx = -3.4e38f;
        for (int j = lane; j < Lk; j += 32) {
            float v = sS[i*sp + j];
            bool dead = false;
            if (mask_mode == 1) dead = (mask[(long)(batch*64 + i)*Lk + j] == 0);
            else if (mask_mode == 2) dead = (mask[(batch/mask_div)*Lk + j] == 0);
            if (dead) { v = -1e9f; sS[i*sp + j] = v; }
            mx = fmaxf(mx, v);
        }
        #pragma unroll
        for (int o = 16; o; o >>= 1) mx = fmaxf(mx, __shfl_xor_sync(0xffffffffu, mx, o));
        float sum = 0.0f;
        for (int j = lane; j < Lk; j += 32) {
            float e = __expf(sS[i*sp + j] - mx);
            sS[i*sp + j] = e;
            sum += e;
        }
        #pragma unroll
        for (int o = 16; o; o >>= 1) sum += __shfl_xor_sync(0xffffffffu, sum, o);
        float inv = 1.0f / sum;
        for (int j = lane; j < Lk; j += 32) sS[i*sp + j] *= inv;
        for (int j = Lk + lane; j < LkPad; j += 32) sS[i*sp + j] = 0.0f;
    }
    CP_WAIT0();
    __syncthreads();

    // O = P @ V
    {
        float acc[2][2][4];
        #pragma unroll
        for (int mt = 0; mt < 2; mt++)
            #pragma unroll
            for (int nt = 0; nt < 2; nt++)
                #pragma unroll
                for (int u = 0; u < 4; u++) acc[mt][nt][u] = 0.0f;

        for (int kb = 0; kb < LkPad; kb += 8) {
            uint32_t af[2][4];
            #pragma unroll
            for (int mt = 0; mt < 2; mt++) {
                int mr = warp_m*32 + mt*16 + gr;
                af[mt][0] = __float_as_uint(sS[mr*sp + kb+gc]);
                af[mt][1] = __float_as_uint(sS[(mr+8)*sp + kb+gc]);
                af[mt][2] = __float_as_uint(sS[mr*sp + kb+gc+4]);
                af[mt][3] = __float_as_uint(sS[(mr+8)*sp + kb+gc+4]);
            }
            #pragma unroll
            for (int nt = 0; nt < 2; nt++) {
                int nc = warp_n*16 + nt*8 + gr;
                uint32_t bf[2];
                int k0r = kb+gc, k1r = kb+gc+4;
                bf[0] = (k0r < Lk) ? __float_as_uint(sKV[k0r*68 + nc]) : 0u;
                bf[1] = (k1r < Lk) ? __float_as_uint(sKV[k1r*68 + nc]) : 0u;
                mma_tf32(acc[0][nt], af[0], bf);
                mma_tf32(acc[1][nt], af[1], bf);
            }
        }
        #pragma unroll
        for (int mt = 0; mt < 2; mt++)
            #pragma unroll
            for (int nt = 0; nt < 2; nt++) {
                int i = warp_m*32 + mt*16 + gr;
                int d = warp_n*16 + nt*8 + (gc << 1);
                long base = (long)(batch*64 + i)*DD + h*64 + d;
                *reinterpret_cast<float2*>(O + base) =
                    make_float2(acc[mt][nt][0], acc[mt][nt][1]);
                *reinterpret_cast<float2*>(O + base + 8*DD) =
                    make_float2(acc[mt][nt][2], acc[mt][nt][3]);
            }
    }
}

// ---------------- fp32 attention for Lq=1 (mha5/mha7) ----------------
#define KVP 68
__global__ __launch_bounds__(256) void attn1_kernel(
    const float* __restrict__ Q, const float* __restrict__ Kg,
    const float* __restrict__ Vg, float* __restrict__ O,
    int Lk, const int* __restrict__ mask, int mask_mode, int mask_div)
{
    extern __shared__ float sm[];
    float* sQ  = sm;
    float* sKV = sm + 64;
    float* sS  = sKV + 32*KVP;
    int batch = blockIdx.x, h = blockIdx.y;
    int tid = threadIdx.x;

    if (tid < 64) sQ[tid] = Q[(long)batch*DD + h*64 + tid];
    for (int jt = 0; jt < Lk; jt += 32) {
        __syncthreads();
        for (int idx = tid; idx < 32*64; idx += 256) {
            int j = idx >> 6, d = idx & 63;
            int jj = jt + j;
            sKV[j*KVP + d] = (jj < Lk) ? Kg[(long)(batch*Lk + jj)*DD + h*64 + d] : 0.0f;
        }
        __syncthreads();
        if (tid < 32) {
            int jj = jt + tid;
            if (jj < Lk) {
                const float4* q4 = reinterpret_cast<const float4*>(sQ);
                const float4* k4 = reinterpret_cast<const float4*>(sKV + tid*KVP);
                float s = 0.0f;
                #pragma unroll
                for (int d = 0; d < 16; d++) {
                    float4 a = q4[d], b = k4[d];
                    s += a.x*b.x + a.y*b.y + a.z*b.z + a.w*b.w;
                }
                s *= 0.125f;
                if (mask_mode == 2 && mask[(batch/mask_div)*Lk + jj] == 0) s = -1e9f;
                sS[jj] = s;
            }
        }
    }
    __syncthreads();
    if (tid < 32) {
        float m = -3.4e38f;
        for (int j = tid; j < Lk; j += 32) m = fmaxf(m, sS[j]);
        #pragma unroll
        for (int o = 16; o; o >>= 1) m = fmaxf(m, __shfl_xor_sync(0xffffffffu, m, o));
        float sum = 0.0f;
        for (int j = tid; j < Lk; j += 32) {
            float e = __expf(sS[j] - m);
            sS[j] = e;
            sum += e;
        }
        #pragma unroll
        for (int o = 16; o; o >>= 1) sum += __shfl_xor_sync(0xffffffffu, sum, o);
        float inv = 1.0f / sum;
        for (int j = tid; j < Lk; j += 32) sS[j] *= inv;
    }
    float acc = 0.0f;
    for (int jt = 0; jt < Lk; jt += 32) {
        __syncthreads();
        for (int idx = tid; idx < 32*64; idx += 256) {
            int j = idx >> 6, dd = idx & 63;
            int jj = jt + j;
            sKV[j*KVP + dd] = (jj < Lk) ? Vg[(long)(batch*Lk + jj)*DD + h*64 + dd] : 0.0f;
        }
        __syncthreads();
        if (tid < 64) {
            int lim = min(32, Lk - jt);
            for (int j = 0; j < lim; j++) acc += sS[jt + j] * sKV[j*KVP + tid];
        }
    }
    if (tid < 64) O[(long)batch*DD + h*64 + tid] = acc;
}

// ---------------- elementwise add ----------------
__global__ void add_kernel(const float* __restrict__ a, const float* __restrict__ b,
                           float* __restrict__ c, int n) {
    int i = blockIdx.x*256 + threadIdx.x;
    if (i < n) c[i] = a[i] + b[i];
}

// ---------------- host ----------------
static float* sym_f(const void* s) { void* p = nullptr; cudaGetSymbolAddress(&p, s); return (float*)p; }
static int*   sym_i(const void* s) { void* p = nullptr; cudaGetSymbolAddress(&p, s); return (int*)p; }

extern "C" void kernel_launch(void* const* d_in, const int* in_sizes, int n_in,
                              void* d_out, int out_size) {
    const float* x    = (const float*)d_in[0];
    const float* vft  = (const float*)d_in[1];
    const float* his  = (const float*)d_in[2];
    const float* cap  = (const float*)d_in[3];
    const float* qry  = (const float*)d_in[4];
    const int* trg_m  = (const int*)d_in[5];
    const int* his_m  = (const int*)d_in[6];
    const int* cap_m  = (const int*)d_in[7];
    const int* qry_m  = (const int*)d_in[8];
    const int* tmp_m  = (const int*)d_in[9];
    const float* attw = (const float*)d_in[10];
    const float* attb = (const float*)d_in[11];
    const float* ffw1 = (const float*)d_in[12];
    const float* ffb1 = (const float*)d_in[13];
    const float* ffw2 = (const float*)d_in[14];
    const float* ffb2 = (const float*)d_in[15];
    const float* lng  = (const float*)d_in[16];
    const float* lnb  = (const float*)d_in[17];
    float* out = (float*)d_out;

    float* cur   = sym_f(g_cur);
    float* lnbuf = sym_f(g_ln);
    float* qb    = sym_f(g_q);
    float* ks    = sym_f(g_ks);
    float* vs    = sym_f(g_vs);
    float* ab    = sym_f(g_attn);
    float* ts    = sym_f(g_ts);
    float* st    = sym_f(g_st);
    float* ffh   = sym_f(g_ffh);
    float* big0  = sym_f(g_big0);
    float* big1  = sym_f(g_big1);
    float* big2  = sym_f(g_big2);
    float* big3  = sym_f(g_big3);
    float* big4  = sym_f(g_big4);
    float* big5  = sym_f(g_big5);
    int* map_perm = sym_i(g_map_perm);
    int* map_pt   = sym_i(g_map_pt);
    int* map_ps   = sym_i(g_map_ps);
    int* res_t    = sym_i(g_res_t);
    int* res_s    = sym_i(g_res_s);

    cudaFuncSetAttribute((const void*)attn_tc_kernel,
                         cudaFuncAttributeMaxDynamicSharedMemorySize, 120*1024);
    cudaFuncSetAttribute((const void*)attn1_kernel,
                         cudaFuncAttributeMaxDynamicSharedMemorySize, 32*1024);

    #define AW(i,j) (attw + ((i)*4+(j))*DD*DD)
    #define ABI(i,j) (attb + ((i)*4+(j))*DD)

    auto gemmN = [](const float* A, const int* amap, int nch,
                    const float* w0, const float* b0, float* c0,
                    const float* w1, const float* b1, float* c1,
                    const float* w2, const float* b2, float* c2,
                    const float* R, const int* rmap,
                    int M, int N, int K, int relu) {
        GemmChunks ch;
        ch.w[0] = w0; ch.b[0] = b0; ch.c[0] = c0;
        ch.w[1] = w1; ch.b[1] = b1; ch.c[1] = c1;
        ch.w[2] = w2; ch.b[2] = b2; ch.c[2] = c2;
        dim3 grid(nch * (N/128), M/128);
        sgemm_tc_kernel<<<grid, 256>>>(A, amap, ch, R, rmap, M, N, K, relu);
    };
    auto gemm = [&](const float* A, const int* amap, const float* W, const float* bias,
                    const float* R, const int* rmap, float* C, int M, int N, int K, int relu) {
        gemmN(A, amap, 1, W, bias, C, nullptr, nullptr, nullptr,
              nullptr, nullptr, nullptr, R, rmap, M, N, K, relu);
    };
    auto attn = [](const float* Q, const float* K, const float* V, float* O,
                   int NB, int Lk, int qg, const int* mask, int mode, int mdiv) {
        int LkPad = (Lk + 31) & ~31;
        size_t sh = (size_t)(64*68 + LkPad*68 + 64*(LkPad+4)) * sizeof(float);
        attn_tc_kernel<<<dim3(NB, HH), 256, sh>>>(Q, K, V, O, Lk, LkPad, qg, mask, mode, mdiv);
    };
    auto attn1 = [](const float* Q, const float* K, const float* V, float* O,
                    int NB, int Lk, const int* mask, int mode, int mdiv) {
        size_t sh = (size_t)(64 + 32*KVP + Lk) * sizeof(float);
        attn1_kernel<<<dim3(NB, HH), 256, sh>>>(Q, K, V, O, Lk, mask, mode, mdiv);
    };
    auto ln = [&](const float* in, int li, float* o, int rows) {
        ln_kernel<<<rows, 128>>>(in, lng + li*DD, lnb + li*DD, o);
    };

    build_maps_kernel<<<dim3(256, 5), 256>>>();
    ln(x, 0, lnbuf, NTOK_X);
    // big vft projections: K+V pairs batched (shared A/amap)
    gemmN(vft, map_perm, 2, AW(4,1), ABI(4,1), big0, AW(4,2), ABI(4,2), big1,
          nullptr, nullptr, nullptr, nullptr, nullptr, NTOK_VFT, DD, DD, 0);
    gemmN(vft, nullptr, 2, AW(6,1), ABI(6,1), big4, AW(6,2), ABI(6,2), big5,
          nullptr, nullptr, nullptr, nullptr, nullptr, NTOK_VFT, DD, DD, 0);

    // ---- mha0: QKV in one launch ----
    gemmN(lnbuf, nullptr, 3,
          AW(0,0), ABI(0,0), qb, AW(0,1), ABI(0,1), ks, AW(0,2), ABI(0,2), vs,
          nullptr, nullptr, NTOK_X, DD, DD, 0);
    attn(qb, ks, vs, ab, BB, TTRG, 1, trg_m, 1, 1);
    gemm(ab, nullptr, AW(0,3), ABI(0,3), x, nullptr, cur, NTOK_X, DD, DD, 0);

    // ---- mha1..3 ----
    {
        const float* kvsrc[3] = { his, cap, qry };
        const int    kvrows[3] = { BB*128, BB*64, BB*32 };
        const int    Lks[3]    = { 128, 64, 32 };
        const int*   masks[3]  = { his_m, cap_m, qry_m };
        for (int a = 0; a < 3; a++) {
            int wi = a + 1;
            ln(cur, wi, lnbuf, NTOK_X);
            gemm(lnbuf, nullptr, AW(wi,0), ABI(wi,0), nullptr, nullptr, qb, NTOK_X, DD, DD, 0);
            gemmN(kvsrc[a], nullptr, 2,
                  AW(wi,1), ABI(wi,1), ks, AW(wi,2), ABI(wi,2), vs,
                  nullptr, nullptr, nullptr,
                  nullptr, nullptr, kvrows[a], DD, DD, 0);
            attn(qb, ks, vs, ab, BB, Lks[a], 1, masks[a], 2, 1);
            gemm(ab, nullptr, AW(wi,3), ABI(wi,3), cur, nullptr, cur, NTOK_X, DD, DD, 0);
        }
    }

    // ---- temporal2spatial: mha4 ----
    ln(cur, 4, lnbuf, NTOK_X);
    gemm(lnbuf, nullptr, AW(4,0), ABI(4,0), nullptr, nullptr, qb, NTOK_X, DD, DD, 0);
    attn(qb, big0, big1, big2, BB*SS, TT, SS, tmp_m, 2, SS);
    gemm(big2, nullptr, AW(4,3), ABI(4,3), cur, res_t, big3, NTOK_VFT, DD, DD, 0);

    // ---- mha5: K+V pair batched ----
    ln(cur, 5, lnbuf, NTOK_X);
    gemm(lnbuf, nullptr, AW(5,0), ABI(5,0), nullptr, nullptr, qb, NTOK_X, DD, DD, 0);
    gemmN(big3, map_pt, 2, AW(5,1), ABI(5,1), big0, AW(5,2), ABI(5,2), big1,
          nullptr, nullptr, nullptr, nullptr, nullptr, NTOK_VFT, DD, DD, 0);
    attn1(qb, big0, big1, ab, NTOK_X, SS, nullptr, 0, 1);
    gemm(ab, nullptr, AW(5,3), ABI(5,3), cur, nullptr, ts, NTOK_X, DD, DD, 0);
    // ffn0
    ln(ts, 6, lnbuf, NTOK_X);
    gemm(lnbuf, nullptr, ffw1 + 0*DD*DFF, ffb1 + 0*DFF, nullptr, nullptr, ffh, NTOK_X, DFF, DD, 1);
    gemm(ffh, nullptr, ffw2 + 0*DFF*DD, ffb2 + 0*DD, ts, nullptr, ts, NTOK_X, DD, DFF, 0);

    // ---- spatial2temporal: mha6 ----
    ln(cur, 7, lnbuf, NTOK_X);
    gemm(lnbuf, nullptr, AW(6,0), ABI(6,0), nullptr, nullptr, qb, NTOK_X, DD, DD, 0);
    attn(qb, big4, big5, big2, BB*TT, SS, TT, nullptr, 0, 1);
    gemm(big2, nullptr, AW(6,3), ABI(6,3), cur, res_s, big3, NTOK_SOUT, DD, DD, 0);

    // ---- mha7: K+V pair batched ----
    ln(cur, 8, lnbuf, NTOK_X);
    gemm(lnbuf, nullptr, AW(7,0), ABI(7,0), nullptr, nullptr, qb, NTOK_X, DD, DD, 0);
    gemmN(big3, map_ps, 2, AW(7,1), ABI(7,1), big0, AW(7,2), ABI(7,2), big1,
          nullptr, nullptr, nullptr, nullptr, nullptr, NTOK_SOUT, DD, DD, 0);
    attn1(qb, big0, big1, ab, NTOK_X, TT, tmp_m, 2, TTRG);
    gemm(ab, nullptr, AW(7,3), ABI(7,3), cur, nullptr, st, NTOK_X, DD, DD, 0);
    // ffn1
    ln(st, 9, lnbuf, NTOK_X);
    gemm(lnbuf, nullptr, ffw1 + 1*DD*DFF, ffb1 + 1*DFF, nullptr, nullptr, ffh, NTOK_X, DFF, DD, 1);
    gemm(ffh, nullptr, ffw2 + 1*DFF*DD, ffb2 + 1*DD, st, nullptr, st, NTOK_X, DD, DFF, 0);

    // ---- combine + ffn2 ----
    add_kernel<<<(NTOK_X*DD + 255)/256, 256>>>(ts, st, cur, NTOK_X*DD);
    ln(cur, 10, lnbuf, NTOK_X);
    gemm(lnbuf, nullptr, ffw1 + 2*DD*DFF, ffb1 + 2*DFF, nullptr, nullptr, ffh, NTOK_X, DFF, DD, 1);
    gemm(ffh, nullptr, ffw2 + 2*DFF*DD, ffb2 + 2*DD, cur, nullptr, out, NTOK_X, DD, DFF, 0);

    #undef AW
    #undef ABI
}

// round 10
// speedup vs baseline: 3.8500x; 1.0552x over previous
#include <cuda_runtime.h>
#include <math.h>
#include <stdint.h>

// ---------------- problem constants ----------------
#define BB   16
#define TTRG 64
#define TT   64
#define SS   49
#define DD   512
#define DFF  2048
#define HH   8
#define NTOK_X    (BB*TTRG)          // 1024
#define NTOK_VFT  (BB*TT*SS)         // 50176
#define NTOK_SOUT (BB*TT*TTRG)       // 65536

// ---------------- scratch ----------------
__device__ float g_cur [NTOK_X*DD];
__device__ float g_ln  [NTOK_X*DD];
__device__ float g_q   [NTOK_X*DD];
__device__ float g_ks  [2048*DD];
__device__ float g_vs  [2048*DD];
__device__ float g_attn[NTOK_X*DD];
__device__ float g_ts  [NTOK_X*DD];
__device__ float g_st  [NTOK_X*DD];
__device__ float g_ffh [NTOK_X*DFF];
__device__ float g_big0[NTOK_SOUT*DD];
__device__ float g_big1[NTOK_SOUT*DD];
__device__ float g_big2[NTOK_SOUT*DD];
__device__ float g_big3[NTOK_SOUT*DD];
__device__ float g_big4[NTOK_SOUT*DD];
__device__ float g_big5[NTOK_SOUT*DD];
__device__ int   g_map_perm[NTOK_VFT];
__device__ int   g_map_pt  [NTOK_VFT];
__device__ int   g_map_ps  [NTOK_SOUT];
__device__ int   g_res_t   [NTOK_VFT];
__device__ int   g_res_s   [NTOK_SOUT];

// ---------------- fused map builder ----------------
__device__ __forceinline__ int swap_map(int m, int Bd, int Cd) {
    int c = m % Cd;
    int b = (m / Cd) % Bd;
    int a = m / (Cd*Bd);
    return (a*Cd + c)*Bd + b;
}
__global__ void build_maps_kernel() {
    int m = blockIdx.x*256 + threadIdx.x;
    int job = blockIdx.y;
    if (job == 0)      { if (m < NTOK_VFT)  g_map_perm[m] = swap_map(m, SS, TT); }
    else if (job == 1) { if (m < NTOK_VFT)  g_map_pt[m]   = swap_map(m, TTRG, SS); }
    else if (job == 2) { if (m < NTOK_SOUT) g_map_ps[m]   = swap_map(m, TTRG, TT); }
    else if (job == 3) { if (m < NTOK_VFT)  g_res_t[m]    = (m/(SS*TT))*TTRG + (m % TTRG); }
    else               { if (m < NTOK_SOUT) g_res_s[m]    = (m/(TT*TTRG))*TTRG + (m % TTRG); }
}

// ---------------- block-diagonal weight builders ----------------
// BWK[512,4096]: BWK[h*64+c][h'*512+d] = (h==h') ? W[d*512 + h*64 + c] : 0
__global__ void build_bwk_kernel(const float* __restrict__ W, float* __restrict__ BWK) {
    int idx = blockIdx.x*256 + threadIdx.x;
    if (idx >= 512*4096) return;
    int k = idx >> 12, n = idx & 4095;
    int hk = k >> 6, c = k & 63;
    int hn = n >> 9, d = n & 511;
    BWK[idx] = (hk == hn) ? W[d*512 + hk*64 + c] : 0.0f;
}
// BWV[4096,512]: BWV[h*512+d][h'*64+e] = (h==h') ? W[d*512 + h*64 + e] : 0
__global__ void build_bwv_kernel(const float* __restrict__ W, float* __restrict__ BWV) {
    int idx = blockIdx.x*256 + threadIdx.x;
    if (idx >= 4096*512) return;
    int k = idx >> 9, n = idx & 511;
    int hk = k >> 9, d = k & 511;
    int hn = n >> 6, e = n & 63;
    BWV[idx] = (hk == hn) ? W[d*512 + hn*64 + e] : 0.0f;
}

// ---------------- layernorm (D=512) ----------------
__global__ __launch_bounds__(128) void ln_kernel(const float* __restrict__ in,
                                                 const float* __restrict__ gamma,
                                                 const float* __restrict__ beta,
                                                 float* __restrict__ out) {
    int row = blockIdx.x;
    int tid = threadIdx.x;
    const float4* p = reinterpret_cast<const float4*>(in + (long)row*DD);
    float4 v = p[tid];
    float s = v.x + v.y + v.z + v.w;
    float q = v.x*v.x + v.y*v.y + v.z*v.z + v.w*v.w;
    #pragma unroll
    for (int o = 16; o; o >>= 1) {
        s += __shfl_xor_sync(0xffffffffu, s, o);
        q += __shfl_xor_sync(0xffffffffu, q, o);
    }
    __shared__ float ssum[4], ssq[4];
    int warp = tid >> 5, lane = tid & 31;
    if (lane == 0) { ssum[warp] = s; ssq[warp] = q; }
    __syncthreads();
    __shared__ float smean, sinv;
    if (tid == 0) {
        float S = ssum[0]+ssum[1]+ssum[2]+ssum[3];
        float Q = ssq[0]+ssq[1]+ssq[2]+ssq[3];
        float mean = S * (1.0f/DD);
        float var  = Q * (1.0f/DD) - mean*mean;
        float sd   = sqrtf(fmaxf(var, 0.0f));
        smean = mean;
        sinv  = 1.0f / (sd + 1e-6f);
    }
    __syncthreads();
    float mean = smean, inv = sinv;
    float4 gv = reinterpret_cast<const float4*>(gamma)[tid];
    float4 bv = reinterpret_cast<const float4*>(beta)[tid];
    float4 o;
    o.x = gv.x*(v.x-mean)*inv + bv.x;
    o.y = gv.y*(v.y-mean)*inv + bv.y;
    o.z = gv.z*(v.z-mean)*inv + bv.z;
    o.w = gv.w*(v.w-mean)*inv + bv.w;
    reinterpret_cast<float4*>(out + (long)row*DD)[tid] = o;
}

// ---------------- tf32/cp.async/ldmatrix helpers ----------------
__device__ __forceinline__ void mma_tf32(float* c, const uint32_t* a, const uint32_t* b) {
    asm volatile("mma.sync.aligned.m16n8k8.row.col.f32.tf32.tf32.f32 "
        "{%0,%1,%2,%3}, {%4,%5,%6,%7}, {%8,%9}, {%0,%1,%2,%3};"
        : "+f"(c[0]), "+f"(c[1]), "+f"(c[2]), "+f"(c[3])
        : "r"(a[0]), "r"(a[1]), "r"(a[2]), "r"(a[3]), "r"(b[0]), "r"(b[1]));
}
__device__ __forceinline__ void cp_async16(void* smem_ptr, const void* gptr) {
    uint32_t s = (uint32_t)__cvta_generic_to_shared(smem_ptr);
    asm volatile("cp.async.cg.shared.global [%0], [%1], 16;" :: "r"(s), "l"(gptr));
}
#define CP_COMMIT() asm volatile("cp.async.commit_group;")
#define CP_WAIT0()  asm volatile("cp.async.wait_group 0;")
__device__ __forceinline__ void ldsm_x4(uint32_t* r, const void* p) {
    uint32_t a = (uint32_t)__cvta_generic_to_shared(p);
    asm volatile("ldmatrix.sync.aligned.m8n8.x4.shared.b16 {%0,%1,%2,%3}, [%4];"
        : "=r"(r[0]), "=r"(r[1]), "=r"(r[2]), "=r"(r[3]) : "r"(a));
}

// ---------------- multi-chunk tf32 GEMM (128x128 tile, Kc=32, double-buffered) ----
#define TCP 136
#define ASP 36

struct GemmChunks {
    const float* w[3];
    const float* b[3];
    float*       c[3];
};

__global__ __launch_bounds__(256, 2) void sgemm_tc_kernel(
    const float* __restrict__ A, const int* __restrict__ amap,
    GemmChunks ch,
    const float* __restrict__ R, const int* __restrict__ rmap,
    int M, int N, int K, int relu)
{
    __shared__ float As[2][128][ASP];
    __shared__ float Bs[2][32][TCP];
    __shared__ int rowm[128];
    int tid = threadIdx.x;
    int ntiles = N >> 7;
    int widx = blockIdx.x / ntiles;
    int n0 = (blockIdx.x % ntiles) << 7;
    int m0 = blockIdx.y << 7;
    const float* W    = ch.w[widx];
    const float* bias = ch.b[widx];
    float*       C    = ch.c[widx];
    if (tid < 128) rowm[tid] = amap ? amap[m0 + tid] : (m0 + tid);
    __syncthreads();

    int wid = tid >> 5, lane = tid & 31;
    int warp_m = wid >> 2, warp_n = wid & 3;
    int gr = lane >> 2, gc = lane & 3;
    int lrow = lane & 15, lkq = (lane >> 4) << 2;

    int arow = tid >> 1, ak = (tid & 1) << 4;
    const float* aptr = A + (long)rowm[arow]*K + ak;
    int bk = tid >> 5, bn = (lane) << 2;
    const float* bptr = W + (long)bk*N + n0 + bn;

    float acc[4][4][4];
    #pragma unroll
    for (int i = 0; i < 4; i++)
        #pragma unroll
        for (int j = 0; j < 4; j++)
            #pragma unroll
            for (int u = 0; u < 4; u++) acc[i][j][u] = 0.0f;

    #pragma unroll
    for (int q = 0; q < 4; q++)
        cp_async16(&As[0][arow][ak + q*4], aptr + q*4);
    #pragma unroll
    for (int q = 0; q < 4; q++)
        cp_async16(&Bs[0][bk + q*8][bn], bptr + (long)(q*8)*N);
    CP_COMMIT();
    CP_WAIT0();
    __syncthreads();

    int mbase = warp_m << 6;
    int buf = 0;
    for (int k0 = 0; k0 < K; k0 += 32) {
        bool has_next = (k0 + 32) < K;
        if (has_next) {
            #pragma unroll
            for (int q = 0; q < 4; q++)
                cp_async16(&As[buf^1][arow][ak + q*4], aptr + k0 + 32 + q*4);
            #pragma unroll
            for (int q = 0; q < 4; q++)
                cp_async16(&Bs[buf^1][bk + q*8][bn], bptr + (long)(k0 + 32 + q*8)*N);
            CP_COMMIT();
        }
        uint32_t afb[2][4][4];
        #pragma unroll
        for (int mt = 0; mt < 4; mt++)
            ldsm_x4(afb[0][mt], &As[buf][mbase + (mt << 4) + lrow][lkq]);
        #pragma unroll
        for (int ks = 0; ks < 4; ks++) {
            int cur = ks & 1;
            if (ks < 3) {
                #pragma unroll
                for (int mt = 0; mt < 4; mt++)
                    ldsm_x4(afb[cur ^ 1][mt],
                            &As[buf][mbase + (mt << 4) + lrow][((ks + 1) << 3) + lkq]);
            }
            int kb = ks << 3;
            uint32_t bf[4][2];
            #pragma unroll
            for (int nt = 0; nt < 4; nt++) {
                int nb = (warp_n << 5) + (nt << 3) + gr;
                bf[nt][0] = __float_as_uint(Bs[buf][kb+gc  ][nb]);
                bf[nt][1] = __float_as_uint(Bs[buf][kb+gc+4][nb]);
            }
            #pragma unroll
            for (int mt = 0; mt < 4; mt++)
                #pragma unroll
                for (int nt = 0; nt < 4; nt++)
                    mma_tf32(acc[mt][nt], afb[cur][mt], bf[nt]);
        }
        if (has_next) CP_WAIT0();
        __syncthreads();
        buf ^= 1;
    }

    #pragma unroll
    for (int mt = 0; mt < 4; mt++) {
        #pragma unroll
        for (int half = 0; half < 2; half++) {
            int m = m0 + (warp_m << 6) + (mt << 4) + gr + (half << 3);
            long rbase = 0;
            if (R) rbase = (long)(rmap ? rmap[m] : m) * N;
            #pragma unroll
            for (int nt = 0; nt < 4; nt++) {
                int n = n0 + (warp_n << 5) + (nt << 3) + (gc << 1);
                float v0 = acc[mt][nt][half*2 + 0];
                float v1 = acc[mt][nt][half*2 + 1];
                if (bias) { v0 += bias[n]; v1 += bias[n+1]; }
                if (relu) { v0 = fmaxf(v0, 0.0f); v1 = fmaxf(v1, 0.0f); }
                if (R) {
                    float2 rv = *reinterpret_cast<const float2*>(R + rbase + n);
                    v0 += rv.x; v1 += rv.y;
                }
                *reinterpret_cast<float2*>(C + (long)m*N + n) = make_float2(v0, v1);
            }
        }
    }
}

// ---------------- tensor-core attention, Lq=64, dk=64 ----------------
__global__ __launch_bounds__(256) void attn_tc_kernel(
    const float* __restrict__ Q, const float* __restrict__ Kg,
    const float* __restrict__ Vg, float* __restrict__ O,
    int Lk, int LkPad, int q_group,
    const int* __restrict__ mask, int mask_mode, int mask_div)
{
    extern __shared__ float sm[];
    float* sQ  = sm;
    float* sKV = sm + 64*68;
    float* sS  = sKV + LkPad*68;
    int batch = blockIdx.x, h = blockIdx.y;
    int tid = threadIdx.x;
    int qbase = (batch / q_group) * 64;
    int sp = LkPad + 4;

    int wid = tid >> 5, lane = tid & 31;
    int warp_m = wid >> 2, warp_n = wid & 3;
    int gr = lane >> 2, gc = lane & 3;
    int nw  = LkPad >> 2;
    int ntn = LkPad >> 5;

    for (int c4 = tid; c4 < 64*16; c4 += 256) {
        int i = c4 >> 4, d = (c4 & 15) << 2;
        cp_async16(&sQ[i*68 + d], &Q[(long)(qbase + i)*DD + h*64 + d]);
    }
    for (int c4 = tid; c4 < Lk*16; c4 += 256) {
        int j = c4 >> 4, d = (c4 & 15) << 2;
        cp_async16(&sKV[j*68 + d], &Kg[(long)(batch*Lk + j)*DD + h*64 + d]);
    }
    CP_COMMIT();
    for (int idx = Lk*64 + tid; idx < LkPad*64; idx += 256) {
        int j = idx >> 6, d = idx & 63;
        sKV[j*68 + d] = 0.0f;
    }
    CP_WAIT0();
    __syncthreads();

    {
        float acc[2][4][4];
        #pragma unroll
        for (int mt = 0; mt < 2; mt++)
            #pragma unroll
            for (int nt = 0; nt < 4; nt++)
                #pragma unroll
                for (int u = 0; u < 4; u++) acc[mt][nt][u] = 0.0f;

        for (int kb = 0; kb < 64; kb += 8) {
            uint32_t af[2][4];
            #pragma unroll
            for (int mt = 0; mt < 2; mt++) {
                int mr = warp_m*32 + mt*16 + gr;
                af[mt][0] = __float_as_uint(sQ[mr*68 + kb+gc]);
                af[mt][1] = __float_as_uint(sQ[(mr+8)*68 + kb+gc]);
                af[mt][2] = __float_as_uint(sQ[mr*68 + kb+gc+4]);
                af[mt][3] = __float_as_uint(sQ[(mr+8)*68 + kb+gc+4]);
            }
            for (int nt = 0; nt < ntn; nt++) {
                int nc = warp_n*nw + nt*8 + gr;
                uint32_t bf[2];
                bf[0] = __float_as_uint(sKV[nc*68 + kb+gc]);
                bf[1] = __float_as_uint(sKV[nc*68 + kb+gc+4]);
                mma_tf32(acc[0][nt], af[0], bf);
                mma_tf32(acc[1][nt], af[1], bf);
            }
        }
        #pragma unroll
        for (int mt = 0; mt < 2; mt++)
            for (int nt = 0; nt < ntn; nt++) {
                int row = warp_m*32 + mt*16 + gr;
                int col = warp_n*nw + nt*8 + (gc << 1);
                sS[row*sp + col]       = acc[mt][nt][0]*0.125f;
                sS[row*sp + col + 1]   = acc[mt][nt][1]*0.125f;
                sS[(row+8)*sp + col]   = acc[mt][nt][2]*0.125f;
                sS[(row+8)*sp + col+1] = acc[mt][nt][3]*0.125f;
            }
    }
    __syncthreads();

    for (int c4 = tid; c4 < Lk*16; c4 += 256) {
        int j = c4 >> 4, d = (c4 & 15) << 2;
        cp_async16(&sKV[j*68 + d], &Vg[(long)(batch*Lk + j)*DD + h*64 + d]);
    }
    CP_COMMIT();

    for (int i = wid; i < 64; i += 8) {
        float mx = -3.4e38f;
        for (int j = lane; j < Lk; j += 32) {
            float v = sS[i*sp + j];
            bool dead = false;
            if (mask_mode == 1) dead = (mask[(long)(batch*64 + i)*Lk + j] == 0);
            else if (mask_mode == 2) dead = (mask[(batch/mask_div)*Lk + j] == 0);
            if (dead) { v = -1e9f; sS[i*sp + j] = v; }
            mx = fmaxf(mx, v);
        }
        #pragma unroll
        for (int o = 16; o; o >>= 1) mx = fmaxf(mx, __shfl_xor_sync(0xffffffffu, mx, o));
        float sum = 0.0f;
        for (int j = lane; j < Lk; j += 32) {
            float e = __expf(sS[i*sp + j] - mx);
            sS[i*sp + j] = e;
            sum += e;
        }
        #pragma unroll
        for (int o = 16; o; o >>= 1) sum += __shfl_xor_sync(0xffffffffu, sum, o);
        float inv = 1.0f / sum;
        for (int j = lane; j < Lk; j += 32) sS[i*sp + j] *= inv;
        for (int j = Lk + lane; j < LkPad; j += 32) sS[i*sp + j] = 0.0f;
    }
    CP_WAIT0();
    __syncthreads();

    {
        float acc[2][2][4];
        #pragma unroll
        for (int mt = 0; mt < 2; mt++)
            #pragma unroll
            for (int nt = 0; nt < 2; nt++)
                #pragma unroll
                for (int u = 0; u < 4; u++) acc[mt][nt][u] = 0.0f;

        for (int kb = 0; kb < LkPad; kb += 8) {
            uint32_t af[2][4];
            #pragma unroll
            for (int mt = 0; mt < 2; mt++) {
                int mr = warp_m*32 + mt*16 + gr;
                af[mt][0] = __float_as_uint(sS[mr*sp + kb+gc]);
                af[mt][1] = __float_as_uint(sS[(mr+8)*sp + kb+gc]);
                af[mt][2] = __float_as_uint(sS[mr*sp + kb+gc+4]);
                af[mt][3] = __float_as_uint(sS[(mr+8)*sp + kb+gc+4]);
            }
            #pragma unroll
            for (int nt = 0; nt < 2; nt++) {
                int nc = warp_n*16 + nt*8 + gr;
                uint32_t bf[2];
                int k0r = kb+gc, k1r = kb+gc+4;
                bf[0] = (k0r < Lk) ? __float_as_uint(sKV[k0r*68 + nc]) : 0u;
                bf[1] = (k1r < Lk) ? __float_as_uint(sKV[k1r*68 + nc]) : 0u;
                mma_tf32(acc[0][nt], af[0], bf);
                mma_tf32(acc[1][nt], af[1], bf);
            }
        }
        #pragma unroll
        for (int mt = 0; mt < 2; mt++)
            #pragma unroll
            for (int nt = 0; nt < 2; nt++) {
                int i = warp_m*32 + mt*16 + gr;
                int d = warp_n*16 + nt*8 + (gc << 1);
                long base = (long)(batch*64 + i)*DD + h*64 + d;
                *reinterpret_cast<float2*>(O + base) =
                    make_float2(acc[mt][nt][0], acc[mt][nt][1]);
                *reinterpret_cast<float2*>(O + base + 8*DD) =
                    make_float2(acc[mt][nt][2], acc[mt][nt][3]);
            }
    }
}

// ---------------- wide Lq=1 attention over RAW rows (mha5/mha7) ----------------
// QT: [NQ, 4096] per-head 512-dim projected queries. SRC: raw rows [*, 512].
// map: row gather, key j of query q = SRC[map[q*Lk + j]].
// SB out: [NQ, 4096] = per-head probability-weighted sums of raw rows.
__global__ __launch_bounds__(256) void attn_wide_kernel(
    const float* __restrict__ QT, const float* __restrict__ SRC,
    const int* __restrict__ map, float* __restrict__ SB,
    int Lk, const int* __restrict__ mask, int mask_mode, int mask_div)
{
    __shared__ float qt8[8*512];
    __shared__ float krow[8][516];
    __shared__ float sS[8][72];
    __shared__ int   rows[64];
    int q = blockIdx.x;
    int tid = threadIdx.x;
    int h = tid >> 5, lane = tid & 31;

    for (int i = tid; i < 4096; i += 256) qt8[i] = QT[(long)q*4096 + i];
    if (tid < Lk) rows[tid] = map[q*Lk + tid];
    __syncthreads();

    // scores: s_j = (qt_h . src_row_j) / 8
    for (int jt = 0; jt < Lk; jt += 8) {
        int nj = min(8, Lk - jt);
        for (int idx = tid; idx < nj*512; idx += 256) {
            int j = idx >> 9, d = idx & 511;
            krow[j][d] = SRC[(long)rows[jt + j]*512 + d];
        }
        __syncthreads();
        for (int j = 0; j < nj; j++) {
            float s = 0.0f;
            #pragma unroll
            for (int i = 0; i < 16; i++)
                s += qt8[h*512 + i*32 + lane] * krow[j][i*32 + lane];
            #pragma unroll
            for (int o = 16; o; o >>= 1) s += __shfl_xor_sync(0xffffffffu, s, o);
            if (lane == 0) sS[h][jt + j] = s * 0.125f;
        }
        __syncthreads();
    }

    // softmax per head (warp h)
    {
        float mx = -3.4e38f;
        for (int j = lane; j < Lk; j += 32) {
            float v = sS[h][j];
            if (mask_mode == 2 && mask[(q/mask_div)*Lk + j] == 0) { v = -1e9f; sS[h][j] = v; }
            mx = fmaxf(mx, v);
        }
        #pragma unroll
        for (int o = 16; o; o >>= 1) mx = fmaxf(mx, __shfl_xor_sync(0xffffffffu, mx, o));
        float sum = 0.0f;
        for (int j = lane; j < Lk; j += 32) {
            float e = __expf(sS[h][j] - mx);
            sS[h][j] = e;
            sum += e;
        }
        #pragma unroll
        for (int o = 16; o; o >>= 1) sum += __shfl_xor_sync(0xffffffffu, sum, o);
        float inv = 1.0f / sum;
        for (int j = lane; j < Lk; j += 32) sS[h][j] *= inv;
    }
    __syncthreads();

    // weighted sum of raw rows: SB[q][h*512+d] = sum_j p_j * src_row_j[d]
    float acc[16];
    #pragma unroll
    for (int i = 0; i < 16; i++) acc[i] = 0.0f;
    for (int jt = 0; jt < Lk; jt += 8) {
        int nj = min(8, Lk - jt);
        for (int idx = tid; idx < nj*512; idx += 256) {
            int j = idx >> 9, d = idx & 511;
            krow[j][d] = SRC[(long)rows[jt + j]*512 + d];
        }
        __syncthreads();
        for (int j = 0; j < nj; j++) {
            float p = sS[h][jt + j];
            #pragma unroll
            for (int i = 0; i < 16; i++)
                acc[i] += p * krow[j][i*32 + lane];
        }
        __syncthreads();
    }
    #pragma unroll
    for (int i = 0; i < 16; i++)
        SB[(long)q*4096 + h*512 + i*32 + lane] = acc[i];
}

// ---------------- elementwise add ----------------
__global__ void add_kernel(const float* __restrict__ a, const float* __restrict__ b,
                           float* __restrict__ c, int n) {
    int i = blockIdx.x*256 + threadIdx.x;
    if (i < n) c[i] = a[i] + b[i];
}

// ---------------- host ----------------
static float* sym_f(const void* s) { void* p = nullptr; cudaGetSymbolAddress(&p, s); return (float*)p; }
static int*   sym_i(const void* s) { void* p = nullptr; cudaGetSymbolAddress(&p, s); return (int*)p; }

extern "C" void kernel_launch(void* const* d_in, const int* in_sizes, int n_in,
                              void* d_out, int out_size) {
    const float* x    = (const float*)d_in[0];
    const float* vft  = (const float*)d_in[1];
    const float* his  = (const float*)d_in[2];
    const float* cap  = (const float*)d_in[3];
    const float* qry  = (const float*)d_in[4];
    const int* trg_m  = (const int*)d_in[5];
    const int* his_m  = (const int*)d_in[6];
    const int* cap_m  = (const int*)d_in[7];
    const int* qry_m  = (const int*)d_in[8];
    const int* tmp_m  = (const int*)d_in[9];
    const float* attw = (const float*)d_in[10];
    const float* attb = (const float*)d_in[11];
    const float* ffw1 = (const float*)d_in[12];
    const float* ffb1 = (const float*)d_in[13];
    const float* ffw2 = (const float*)d_in[14];
    const float* ffb2 = (const float*)d_in[15];
    const float* lng  = (const float*)d_in[16];
    const float* lnb  = (const float*)d_in[17];
    float* out = (float*)d_out;

    float* cur   = sym_f(g_cur);
    float* lnbuf = sym_f(g_ln);
    float* qb    = sym_f(g_q);
    float* ks    = sym_f(g_ks);
    float* vs    = sym_f(g_vs);
    float* ab    = sym_f(g_attn);
    float* ts    = sym_f(g_ts);
    float* st    = sym_f(g_st);
    float* ffh   = sym_f(g_ffh);
    float* big0  = sym_f(g_big0);
    float* big1  = sym_f(g_big1);
    float* big2  = sym_f(g_big2);
    float* big3  = sym_f(g_big3);
    float* big4  = sym_f(g_big4);
    float* big5  = sym_f(g_big5);
    int* map_perm = sym_i(g_map_perm);
    int* map_pt   = sym_i(g_map_pt);
    int* map_ps   = sym_i(g_map_ps);
    int* res_t    = sym_i(g_res_t);
    int* res_s    = sym_i(g_res_s);

    cudaFuncSetAttribute((const void*)attn_tc_kernel,
                         cudaFuncAttributeMaxDynamicSharedMemorySize, 120*1024);

    #define AW(i,j) (attw + ((i)*4+(j))*DD*DD)
    #define ABI(i,j) (attb + ((i)*4+(j))*DD)

    auto gemmN = [](const float* A, const int* amap, int nch,
                    const float* w0, const float* b0, float* c0,
                    const float* w1, const float* b1, float* c1,
                    const float* w2, const float* b2, float* c2,
                    const float* R, const int* rmap,
                    int M, int N, int K, int relu) {
        GemmChunks ch;
        ch.w[0] = w0; ch.b[0] = b0; ch.c[0] = c0;
        ch.w[1] = w1; ch.b[1] = b1; ch.c[1] = c1;
        ch.w[2] = w2; ch.b[2] = b2; ch.c[2] = c2;
        dim3 grid(nch * (N/128), M/128);
        sgemm_tc_kernel<<<grid, 256>>>(A, amap, ch, R, rmap, M, N, K, relu);
    };
    auto gemm = [&](const float* A, const int* amap, const float* W, const float* bias,
                    const float* R, const int* rmap, float* C, int M, int N, int K, int relu) {
        gemmN(A, amap, 1, W, bias, C, nullptr, nullptr, nullptr,
              nullptr, nullptr, nullptr, R, rmap, M, N, K, relu);
    };
    auto attn = [](const float* Q, const float* K, const float* V, float* O,
                   int NB, int Lk, int qg, const int* mask, int mode, int mdiv) {
        int LkPad = (Lk + 31) & ~31;
        size_t sh = (size_t)(64*68 + LkPad*68 + 64*(LkPad+4)) * sizeof(float);
        attn_tc_kernel<<<dim3(NB, HH), 256, sh>>>(Q, K, V, O, Lk, LkPad, qg, mask, mode, mdiv);
    };
    auto ln = [&](const float* in, int li, float* o, int rows) {
        ln_kernel<<<rows, 128>>>(in, lng + li*DD, lnb + li*DD, o);
    };
    // factored Lq=1 attention: QT gemm -> attn_wide over raw rows -> SB projection
    auto mha_lq1 = [&](int wi, const float* SRC, const int* map, int Lk,
                       float* bwscratch, const int* mask, int mode, int mdiv,
                       float* result /*ab*/) {
        float* BWK = bwscratch;                  // 512*4096
        float* BWV = bwscratch + 512*4096;       // 4096*512
        build_bwk_kernel<<<(512*4096+255)/256, 256>>>(AW(wi,1), BWK);
        build_bwv_kernel<<<(4096*512+255)/256, 256>>>(AW(wi,2), BWV);
        gemm(qb, nullptr, BWK, nullptr, nullptr, nullptr, big0, NTOK_X, 4096, DD, 0);   // QT
        attn_wide_kernel<<<NTOK_X, 256>>>(big0, SRC, map, big1, Lk, mask, mode, mdiv);  // SB
        gemm(big1, nullptr, BWV, ABI(wi,2), nullptr, nullptr, result, NTOK_X, DD, 4096, 0);
    };

    build_maps_kernel<<<dim3(256, 5), 256>>>();
    ln(x, 0, lnbuf, NTOK_X);
    // big vft projections (mha4 + mha6 K/V)
    gemmN(vft, map_perm, 2, AW(4,1), ABI(4,1), big0, AW(4,2), ABI(4,2), big1,
          nullptr, nullptr, nullptr, nullptr, nullptr, NTOK_VFT, DD, DD, 0);
    gemmN(vft, nullptr, 2, AW(6,1), ABI(6,1), big4, AW(6,2), ABI(6,2), big5,
          nullptr, nullptr, nullptr, nullptr, nullptr, NTOK_VFT, DD, DD, 0);

    // ---- mha0 ----
    gemmN(lnbuf, nullptr, 3,
          AW(0,0), ABI(0,0), qb, AW(0,1), ABI(0,1), ks, AW(0,2), ABI(0,2), vs,
          nullptr, nullptr, NTOK_X, DD, DD, 0);
    attn(qb, ks, vs, ab, BB, TTRG, 1, trg_m, 1, 1);
    gemm(ab, nullptr, AW(0,3), ABI(0,3), x, nullptr, cur, NTOK_X, DD, DD, 0);

    // ---- mha1..3 ----
    {
        const float* kvsrc[3] = { his, cap, qry };
        const int    kvrows[3] = { BB*128, BB*64, BB*32 };
        const int    Lks[3]    = { 128, 64, 32 };
        const int*   masks[3]  = { his_m, cap_m, qry_m };
        for (int a = 0; a < 3; a++) {
            int wi = a + 1;
            ln(cur, wi, lnbuf, NTOK_X);
            gemm(lnbuf, nullptr, AW(wi,0), ABI(wi,0), nullptr, nullptr, qb, NTOK_X, DD, DD, 0);
            gemmN(kvsrc[a], nullptr, 2,
                  AW(wi,1), ABI(wi,1), ks, AW(wi,2), ABI(wi,2), vs,
                  nullptr, nullptr, nullptr,
                  nullptr, nullptr, kvrows[a], DD, DD, 0);
            attn(qb, ks, vs, ab, BB, Lks[a], 1, masks[a], 2, 1);
            gemm(ab, nullptr, AW(wi,3), ABI(wi,3), cur, nullptr, cur, NTOK_X, DD, DD, 0);
        }
    }

    // ---- temporal2spatial: mha4 ----
    ln(cur, 4, lnbuf, NTOK_X);
    gemm(lnbuf, nullptr, AW(4,0), ABI(4,0), nullptr, nullptr, qb, NTOK_X, DD, DD, 0);
    attn(qb, big0, big1, big2, BB*SS, TT, SS, tmp_m, 2, SS);
    gemm(big2, nullptr, AW(4,3), ABI(4,3), cur, res_t, big3, NTOK_VFT, DD, DD, 0);

    // ---- mha5: factored Lq=1 attention over raw t_out rows ----
    ln(cur, 5, lnbuf, NTOK_X);
    gemm(lnbuf, nullptr, AW(5,0), ABI(5,0), nullptr, nullptr, qb, NTOK_X, DD, DD, 0);
    mha_lq1(5, big3, map_pt, SS, big2, nullptr, 0, 1, ab);
    gemm(ab, nullptr, AW(5,3), ABI(5,3), cur, nullptr, ts, NTOK_X, DD, DD, 0);
    // ffn0
    ln(ts, 6, lnbuf, NTOK_X);
    gemm(lnbuf, nullptr, ffw1 + 0*DD*DFF, ffb1 + 0*DFF, nullptr, nullptr, ffh, NTOK_X, DFF, DD, 1);
    gemm(ffh, nullptr, ffw2 + 0*DFF*DD, ffb2 + 0*DD, ts, nullptr, ts, NTOK_X, DD, DFF, 0);

    // ---- spatial2temporal: mha6 ----
    ln(cur, 7, lnbuf, NTOK_X);
    gemm(lnbuf, nullptr, AW(6,0), ABI(6,0), nullptr, nullptr, qb, NTOK_X, DD, DD, 0);
    attn(qb, big4, big5, big2, BB*TT, SS, TT, nullptr, 0, 1);
    gemm(big2, nullptr, AW(6,3), ABI(6,3), cur, res_s, big3, NTOK_SOUT, DD, DD, 0);

    // ---- mha7: factored Lq=1 attention over raw s_out rows ----
    ln(cur, 8, lnbuf, NTOK_X);
    gemm(lnbuf, nullptr, AW(7,0), ABI(7,0), nullptr, nullptr, qb, NTOK_X, DD, DD, 0);
    mha_lq1(7, big3, map_ps, TT, big4, tmp_m, 2, TTRG, ab);
    gemm(ab, nullptr, AW(7,3), ABI(7,3), cur, nullptr, st, NTOK_X, DD, DD, 0);
    // ffn1
    ln(st, 9, lnbuf, NTOK_X);
    gemm(lnbuf, nullptr, ffw1 + 1*DD*DFF, ffb1 + 1*DFF, nullptr, nullptr, ffh, NTOK_X, DFF, DD, 1);
    gemm(ffh, nullptr, ffw2 + 1*DFF*DD, ffb2 + 1*DD, st, nullptr, st, NTOK_X, DD, DFF, 0);

    // ---- combine + ffn2 ----
    add_kernel<<<(NTOK_X*DD + 255)/256, 256>>>(ts, st, cur, NTOK_X*DD);
    ln(cur, 10, lnbuf, NTOK_X);
    gemm(lnbuf, nullptr, ffw1 + 2*DD*DFF, ffb1 + 2*DFF, nullptr, nullptr, ffh, NTOK_X, DFF, DD, 1);
    gemm(ffh, nullptr, ffw2 + 2*DFF*DD, ffb2 + 2*DD, cur, nullptr, out, NTOK_X, DD, DFF, 0);

    #undef AW
    #undef ABI
}

// round 11
// speedup vs baseline: 4.4432x; 1.1541x over previous
#include <cuda_runtime.h>
#include <math.h>
#include <stdint.h>

// ---------------- problem constants ----------------
#define BB   16
#define TTRG 64
#define TT   64
#define SS   49
#define DD   512
#define DFF  2048
#define HH   8
#define NTOK_X    (BB*TTRG)          // 1024
#define NTOK_VFT  (BB*TT*SS)         // 50176
#define NTOK_SOUT (BB*TT*TTRG)       // 65536

// ---------------- scratch ----------------
__device__ float g_cur [NTOK_X*DD];
__device__ float g_lnA [NTOK_X*DD];
__device__ float g_lnB [NTOK_X*DD];
__device__ float g_qA  [NTOK_X*DD];
__device__ float g_qB  [NTOK_X*DD];
__device__ float g_ks  [2048*DD];
__device__ float g_vs  [2048*DD];
__device__ float g_abA [NTOK_X*DD];
__device__ float g_abB [NTOK_X*DD];
__device__ float g_ts  [NTOK_X*DD];
__device__ float g_st  [NTOK_X*DD];
__device__ float g_ffhA[NTOK_X*DFF];
__device__ float g_ffhB[NTOK_X*DFF];
__device__ float g_big0[NTOK_SOUT*DD];
__device__ float g_big1[NTOK_SOUT*DD];
__device__ float g_big2[NTOK_SOUT*DD];
__device__ float g_big3[NTOK_SOUT*DD];
__device__ float g_big4[NTOK_SOUT*DD];
__device__ float g_big5[NTOK_SOUT*DD];
__device__ float g_big6[NTOK_SOUT*DD];
__device__ float g_big7[NTOK_SOUT*DD];
__device__ int   g_map_perm[NTOK_VFT];
__device__ int   g_map_pt  [NTOK_VFT];
__device__ int   g_map_ps  [NTOK_SOUT];
__device__ int   g_res_t   [NTOK_VFT];
__device__ int   g_res_s   [NTOK_SOUT];

// ---------------- fused map builder ----------------
__device__ __forceinline__ int swap_map(int m, int Bd, int Cd) {
    int c = m % Cd;
    int b = (m / Cd) % Bd;
    int a = m / (Cd*Bd);
    return (a*Cd + c)*Bd + b;
}
__global__ void build_maps_kernel() {
    int m = blockIdx.x*256 + threadIdx.x;
    int job = blockIdx.y;
    if (job == 0)      { if (m < NTOK_VFT)  g_map_perm[m] = swap_map(m, SS, TT); }
    else if (job == 1) { if (m < NTOK_VFT)  g_map_pt[m]   = swap_map(m, TTRG, SS); }
    else if (job == 2) { if (m < NTOK_SOUT) g_map_ps[m]   = swap_map(m, TTRG, TT); }
    else if (job == 3) { if (m < NTOK_VFT)  g_res_t[m]    = (m/(SS*TT))*TTRG + (m % TTRG); }
    else               { if (m < NTOK_SOUT) g_res_s[m]    = (m/(TT*TTRG))*TTRG + (m % TTRG); }
}

// ---------------- block-diagonal weight builders ----------------
__global__ void build_bwk_kernel(const float* __restrict__ W, float* __restrict__ BWK) {
    int idx = blockIdx.x*256 + threadIdx.x;
    if (idx >= 512*4096) return;
    int k = idx >> 12, n = idx & 4095;
    int hk = k >> 6, c = k & 63;
    int hn = n >> 9, d = n & 511;
    BWK[idx] = (hk == hn) ? W[d*512 + hk*64 + c] : 0.0f;
}
__global__ void build_bwv_kernel(const float* __restrict__ W, float* __restrict__ BWV) {
    int idx = blockIdx.x*256 + threadIdx.x;
    if (idx >= 4096*512) return;
    int k = idx >> 9, n = idx & 511;
    int hk = k >> 9, d = k & 511;
    int hn = n >> 6, e = n & 63;
    BWV[idx] = (hk == hn) ? W[d*512 + hn*64 + e] : 0.0f;
}

// ---------------- layernorm (D=512) ----------------
__global__ __launch_bounds__(128) void ln_kernel(const float* __restrict__ in,
                                                 const float* __restrict__ gamma,
                                                 const float* __restrict__ beta,
                                                 float* __restrict__ out) {
    int row = blockIdx.x;
    int tid = threadIdx.x;
    const float4* p = reinterpret_cast<const float4*>(in + (long)row*DD);
    float4 v = p[tid];
    float s = v.x + v.y + v.z + v.w;
    float q = v.x*v.x + v.y*v.y + v.z*v.z + v.w*v.w;
    #pragma unroll
    for (int o = 16; o; o >>= 1) {
        s += __shfl_xor_sync(0xffffffffu, s, o);
        q += __shfl_xor_sync(0xffffffffu, q, o);
    }
    __shared__ float ssum[4], ssq[4];
    int warp = tid >> 5, lane = tid & 31;
    if (lane == 0) { ssum[warp] = s; ssq[warp] = q; }
    __syncthreads();
    __shared__ float smean, sinv;
    if (tid == 0) {
        float S = ssum[0]+ssum[1]+ssum[2]+ssum[3];
        float Q = ssq[0]+ssq[1]+ssq[2]+ssq[3];
        float mean = S * (1.0f/DD);
        float var  = Q * (1.0f/DD) - mean*mean;
        float sd   = sqrtf(fmaxf(var, 0.0f));
        smean = mean;
        sinv  = 1.0f / (sd + 1e-6f);
    }
    __syncthreads();
    float mean = smean, inv = sinv;
    float4 gv = reinterpret_cast<const float4*>(gamma)[tid];
    float4 bv = reinterpret_cast<const float4*>(beta)[tid];
    float4 o;
    o.x = gv.x*(v.x-mean)*inv + bv.x;
    o.y = gv.y*(v.y-mean)*inv + bv.y;
    o.z = gv.z*(v.z-mean)*inv + bv.z;
    o.w = gv.w*(v.w-mean)*inv + bv.w;
    reinterpret_cast<float4*>(out + (long)row*DD)[tid] = o;
}

// ---------------- tf32/cp.async/ldmatrix helpers ----------------
__device__ __forceinline__ void mma_tf32(float* c, const uint32_t* a, const uint32_t* b) {
    asm volatile("mma.sync.aligned.m16n8k8.row.col.f32.tf32.tf32.f32 "
        "{%0,%1,%2,%3}, {%4,%5,%6,%7}, {%8,%9}, {%0,%1,%2,%3};"
        : "+f"(c[0]), "+f"(c[1]), "+f"(c[2]), "+f"(c[3])
        : "r"(a[0]), "r"(a[1]), "r"(a[2]), "r"(a[3]), "r"(b[0]), "r"(b[1]));
}
__device__ __forceinline__ void cp_async16(void* smem_ptr, const void* gptr) {
    uint32_t s = (uint32_t)__cvta_generic_to_shared(smem_ptr);
    asm volatile("cp.async.cg.shared.global [%0], [%1], 16;" :: "r"(s), "l"(gptr));
}
#define CP_COMMIT() asm volatile("cp.async.commit_group;")
#define CP_WAIT0()  asm volatile("cp.async.wait_group 0;")
__device__ __forceinline__ void ldsm_x4(uint32_t* r, const void* p) {
    uint32_t a = (uint32_t)__cvta_generic_to_shared(p);
    asm volatile("ldmatrix.sync.aligned.m8n8.x4.shared.b16 {%0,%1,%2,%3}, [%4];"
        : "=r"(r[0]), "=r"(r[1]), "=r"(r[2]), "=r"(r[3]) : "r"(a));
}

// ---------------- multi-chunk tf32 GEMM (128x128 tile, Kc=32, double-buffered) ----
#define TCP 136
#define ASP 36

struct GemmChunks {
    const float* w[3];
    const float* b[3];
    float*       c[3];
};

__global__ __launch_bounds__(256, 2) void sgemm_tc_kernel(
    const float* __restrict__ A, const int* __restrict__ amap,
    GemmChunks ch,
    const float* __restrict__ R, const int* __restrict__ rmap,
    int M, int N, int K, int relu)
{
    __shared__ float As[2][128][ASP];
    __shared__ float Bs[2][32][TCP];
    __shared__ int rowm[128];
    int tid = threadIdx.x;
    int ntiles = N >> 7;
    int widx = blockIdx.x / ntiles;
    int n0 = (blockIdx.x % ntiles) << 7;
    int m0 = blockIdx.y << 7;
    const float* W    = ch.w[widx];
    const float* bias = ch.b[widx];
    float*       C    = ch.c[widx];
    if (tid < 128) rowm[tid] = amap ? amap[m0 + tid] : (m0 + tid);
    __syncthreads();

    int wid = tid >> 5, lane = tid & 31;
    int warp_m = wid >> 2, warp_n = wid & 3;
    int gr = lane >> 2, gc = lane & 3;
    int lrow = lane & 15, lkq = (lane >> 4) << 2;

    int arow = tid >> 1, ak = (tid & 1) << 4;
    const float* aptr = A + (long)rowm[arow]*K + ak;
    int bk = tid >> 5, bn = (lane) << 2;
    const float* bptr = W + (long)bk*N + n0 + bn;

    float acc[4][4][4];
    #pragma unroll
    for (int i = 0; i < 4; i++)
        #pragma unroll
        for (int j = 0; j < 4; j++)
            #pragma unroll
            for (int u = 0; u < 4; u++) acc[i][j][u] = 0.0f;

    #pragma unroll
    for (int q = 0; q < 4; q++)
        cp_async16(&As[0][arow][ak + q*4], aptr + q*4);
    #pragma unroll
    for (int q = 0; q < 4; q++)
        cp_async16(&Bs[0][bk + q*8][bn], bptr + (long)(q*8)*N);
    CP_COMMIT();
    CP_WAIT0();
    __syncthreads();

    int mbase = warp_m << 6;
    int buf = 0;
    for (int k0 = 0; k0 < K; k0 += 32) {
        bool has_next = (k0 + 32) < K;
        if (has_next) {
            #pragma unroll
            for (int q = 0; q < 4; q++)
                cp_async16(&As[buf^1][arow][ak + q*4], aptr + k0 + 32 + q*4);
            #pragma unroll
            for (int q = 0; q < 4; q++)
                cp_async16(&Bs[buf^1][bk + q*8][bn], bptr + (long)(k0 + 32 + q*8)*N);
            CP_COMMIT();
        }
        uint32_t afb[2][4][4];
        #pragma unroll
        for (int mt = 0; mt < 4; mt++)
            ldsm_x4(afb[0][mt], &As[buf][mbase + (mt << 4) + lrow][lkq]);
        #pragma unroll
        for (int ks = 0; ks < 4; ks++) {
            int cur = ks & 1;
            if (ks < 3) {
                #pragma unroll
                for (int mt = 0; mt < 4; mt++)
                    ldsm_x4(afb[cur ^ 1][mt],
                            &As[buf][mbase + (mt << 4) + lrow][((ks + 1) << 3) + lkq]);
            }
            int kb = ks << 3;
            uint32_t bf[4][2];
            #pragma unroll
            for (int nt = 0; nt < 4; nt++) {
                int nb = (warp_n << 5) + (nt << 3) + gr;
                bf[nt][0] = __float_as_uint(Bs[buf][kb+gc  ][nb]);
                bf[nt][1] = __float_as_uint(Bs[buf][kb+gc+4][nb]);
            }
            #pragma unroll
            for (int mt = 0; mt < 4; mt++)
                #pragma unroll
                for (int nt = 0; nt < 4; nt++)
                    mma_tf32(acc[mt][nt], afb[cur][mt], bf[nt]);
        }
        if (has_next) CP_WAIT0();
        __syncthreads();
        buf ^= 1;
    }

    #pragma unroll
    for (int mt = 0; mt < 4; mt++) {
        #pragma unroll
        for (int half = 0; half < 2; half++) {
            int m = m0 + (warp_m << 6) + (mt << 4) + gr + (half << 3);
            long rbase = 0;
            if (R) rbase = (long)(rmap ? rmap[m] : m) * N;
            #pragma unroll
            for (int nt = 0; nt < 4; nt++) {
                int n = n0 + (warp_n << 5) + (nt << 3) + (gc << 1);
                float v0 = acc[mt][nt][half*2 + 0];
                float v1 = acc[mt][nt][half*2 + 1];
                if (bias) { v0 += bias[n]; v1 += bias[n+1]; }
                if (relu) { v0 = fmaxf(v0, 0.0f); v1 = fmaxf(v1, 0.0f); }
                if (R) {
                    float2 rv = *reinterpret_cast<const float2*>(R + rbase + n);
                    v0 += rv.x; v1 += rv.y;
                }
                *reinterpret_cast<float2*>(C + (long)m*N + n) = make_float2(v0, v1);
            }
        }
    }
}

// ---------------- tensor-core attention, Lq=64, dk=64 ----------------
__global__ __launch_bounds__(256) void attn_tc_kernel(
    const float* __restrict__ Q, const float* __restrict__ Kg,
    const float* __restrict__ Vg, float* __restrict__ O,
    int Lk, int LkPad, int q_group,
    const int* __restrict__ mask, int mask_mode, int mask_div)
{
    extern __shared__ float sm[];
    float* sQ  = sm;
    float* sKV = sm + 64*68;
    float* sS  = sKV + LkPad*68;
    int batch = blockIdx.x, h = blockIdx.y;
    int tid = threadIdx.x;
    int qbase = (batch / q_group) * 64;
    int sp = LkPad + 4;

    int wid = tid >> 5, lane = tid & 31;
    int warp_m = wid >> 2, warp_n = wid & 3;
    int gr = lane >> 2, gc = lane & 3;
    int nw  = LkPad >> 2;
    int ntn = LkPad >> 5;

    for (int c4 = tid; c4 < 64*16; c4 += 256) {
        int i = c4 >> 4, d = (c4 & 15) << 2;
        cp_async16(&sQ[i*68 + d], &Q[(long)(qbase + i)*DD + h*64 + d]);
    }
    for (int c4 = tid; c4 < Lk*16; c4 += 256) {
        int j = c4 >> 4, d = (c4 & 15) << 2;
        cp_async16(&sKV[j*68 + d], &Kg[(long)(batch*Lk + j)*DD + h*64 + d]);
    }
    CP_COMMIT();
    for (int idx = Lk*64 + tid; idx < LkPad*64; idx += 256) {
        int j = idx >> 6, d = idx & 63;
        sKV[j*68 + d] = 0.0f;
    }
    CP_WAIT0();
    __syncthreads();

    {
        float acc[2][4][4];
        #pragma unroll
        for (int mt = 0; mt < 2; mt++)
            #pragma unroll
            for (int nt = 0; nt < 4; nt++)
                #pragma unroll
                for (int u = 0; u < 4; u++) acc[mt][nt][u] = 0.0f;

        for (int kb = 0; kb < 64; kb += 8) {
            uint32_t af[2][4];
            #pragma unroll
            for (int mt = 0; mt < 2; mt++) {
                int mr = warp_m*32 + mt*16 + gr;
                af[mt][0] = __float_as_uint(sQ[mr*68 + kb+gc]);
                af[mt][1] = __float_as_uint(sQ[(mr+8)*68 + kb+gc]);
                af[mt][2] = __float_as_uint(sQ[mr*68 + kb+gc+4]);
                af[mt][3] = __float_as_uint(sQ[(mr+8)*68 + kb+gc+4]);
            }
            for (int nt = 0; nt < ntn; nt++) {
                int nc = warp_n*nw + nt*8 + gr;
                uint32_t bf[2];
                bf[0] = __float_as_uint(sKV[nc*68 + kb+gc]);
                bf[1] = __float_as_uint(sKV[nc*68 + kb+gc+4]);
                mma_tf32(acc[0][nt], af[0], bf);
                mma_tf32(acc[1][nt], af[1], bf);
            }
        }
        #pragma unroll
        for (int mt = 0; mt < 2; mt++)
            for (int nt = 0; nt < ntn; nt++) {
                int row = warp_m*32 + mt*16 + gr;
                int col = warp_n*nw + nt*8 + (gc << 1);
                sS[row*sp + col]       = acc[mt][nt][0]*0.125f;
                sS[row*sp + col + 1]   = acc[mt][nt][1]*0.125f;
                sS[(row+8)*sp + col]   = acc[mt][nt][2]*0.125f;
                sS[(row+8)*sp + col+1] = acc[mt][nt][3]*0.125f;
            }
    }
    __syncthreads();

    for (int c4 = tid; c4 < Lk*16; c4 += 256) {
        int j = c4 >> 4, d = (c4 & 15) << 2;
        cp_async16(&sKV[j*68 + d], &Vg[(long)(batch*Lk + j)*DD + h*64 + d]);
    }
    CP_COMMIT();

    for (int i = wid; i < 64; i += 8) {
        float mx = -3.4e38f;
        for (int j = lane; j < Lk; j += 32) {
            float v = sS[i*sp + j];
            bool dead = false;
            if (mask_mode == 1) dead = (mask[(long)(batch*64 + i)*Lk + j] == 0);
            else if (mask_mode == 2) dead = (mask[(batch/mask_div)*Lk + j] == 0);
            if (dead) { v = -1e9f; sS[i*sp + j] = v; }
            mx = fmaxf(mx, v);
        }
        #pragma unroll
        for (int o = 16; o; o >>= 1) mx = fmaxf(mx, __shfl_xor_sync(0xffffffffu, mx, o));
        float sum = 0.0f;
        for (int j = lane; j < Lk; j += 32) {
            float e = __expf(sS[i*sp + j] - mx);
            sS[i*sp + j] = e;
            sum += e;
        }
        #pragma unroll
        for (int o = 16; o; o >>= 1) sum += __shfl_xor_sync(0xffffffffu, sum, o);
        float inv = 1.0f / sum;
        for (int j = lane; j < Lk; j += 32) sS[i*sp + j] *= inv;
        for (int j = Lk + lane; j < LkPad; j += 32) sS[i*sp + j] = 0.0f;
    }
    CP_WAIT0();
    __syncthreads();

    {
        float acc[2][2][4];
        #pragma unroll
        for (int mt = 0; mt < 2; mt++)
            #pragma unroll
            for (int nt = 0; nt < 2; nt++)
                #pragma unroll
                for (int u = 0; u < 4; u++) acc[mt][nt][u] = 0.0f;

        for (int kb = 0; kb < LkPad; kb += 8) {
            uint32_t af[2][4];
            #pragma unroll
            for (int mt = 0; mt < 2; mt++) {
                int mr = warp_m*32 + mt*16 + gr;
                af[mt][0] = __float_as_uint(sS[mr*sp + kb+gc]);
                af[mt][1] = __float_as_uint(sS[(mr+8)*sp + kb+gc]);
                af[mt][2] = __float_as_uint(sS[mr*sp + kb+gc+4]);
                af[mt][3] = __float_as_uint(sS[(mr+8)*sp + kb+gc+4]);
            }
            #pragma unroll
            for (int nt = 0; nt < 2; nt++) {
                int nc = warp_n*16 + nt*8 + gr;
                uint32_t bf[2];
                int k0r = kb+gc, k1r = kb+gc+4;
                bf[0] = (k0r < Lk) ? __float_as_uint(sKV[k0r*68 + nc]) : 0u;
                bf[1] = (k1r < Lk) ? __float_as_uint(sKV[k1r*68 + nc]) : 0u;
                mma_tf32(acc[0][nt], af[0], bf);
                mma_tf32(acc[1][nt], af[1], bf);
            }
        }
        #pragma unroll
        for (int mt = 0; mt < 2; mt++)
            #pragma unroll
            for (int nt = 0; nt < 2; nt++) {
                int i = warp_m*32 + mt*16 + gr;
                int d = warp_n*16 + nt*8 + (gc << 1);
                long base = (long)(batch*64 + i)*DD + h*64 + d;
                *reinterpret_cast<float2*>(O + base) =
                    make_float2(acc[mt][nt][0], acc[mt][nt][1]);
                *reinterpret_cast<float2*>(O + base + 8*DD) =
                    make_float2(acc[mt][nt][2], acc[mt][nt][3]);
            }
    }
}

// ---------------- wide Lq=1 attention over RAW rows ----------------
__global__ __launch_bounds__(256) void attn_wide_kernel(
    const float* __restrict__ QT, const float* __restrict__ SRC,
    const int* __restrict__ map, float* __restrict__ SB,
    int Lk, const int* __restrict__ mask, int mask_mode, int mask_div)
{
    __shared__ float qt8[8*512];
    __shared__ float krow[8][516];
    __shared__ float sS[8][72];
    __shared__ int   rows[64];
    int q = blockIdx.x;
    int tid = threadIdx.x;
    int h = tid >> 5, lane = tid & 31;

    for (int i = tid; i < 4096; i += 256) qt8[i] = QT[(long)q*4096 + i];
    if (tid < Lk) rows[tid] = map[q*Lk + tid];
    __syncthreads();

    for (int jt = 0; jt < Lk; jt += 8) {
        int nj = min(8, Lk - jt);
        for (int idx = tid; idx < nj*512; idx += 256) {
            int j = idx >> 9, d = idx & 511;
            krow[j][d] = SRC[(long)rows[jt + j]*512 + d];
        }
        __syncthreads();
        for (int j = 0; j < nj; j++) {
            float s = 0.0f;
            #pragma unroll
            for (int i = 0; i < 16; i++)
                s += qt8[h*512 + i*32 + lane] * krow[j][i*32 + lane];
            #pragma unroll
            for (int o = 16; o; o >>= 1) s += __shfl_xor_sync(0xffffffffu, s, o);
            if (lane == 0) sS[h][jt + j] = s * 0.125f;
        }
        __syncthreads();
    }

    {
        float mx = -3.4e38f;
        for (int j = lane; j < Lk; j += 32) {
            float v = sS[h][j];
            if (mask_mode == 2 && mask[(q/mask_div)*Lk + j] == 0) { v = -1e9f; sS[h][j] = v; }
            mx = fmaxf(mx, v);
        }
        #pragma unroll
        for (int o = 16; o; o >>= 1) mx = fmaxf(mx, __shfl_xor_sync(0xffffffffu, mx, o));
        float sum = 0.0f;
        for (int j = lane; j < Lk; j += 32) {
            float e = __expf(sS[h][j] - mx);
            sS[h][j] = e;
            sum += e;
        }
        #pragma unroll
        for (int o = 16; o; o >>= 1) sum += __shfl_xor_sync(0xffffffffu, sum, o);
        float inv = 1.0f / sum;
        for (int j = lane; j < Lk; j += 32) sS[h][j] *= inv;
    }
    __syncthreads();

    float acc[16];
    #pragma unroll
    for (int i = 0; i < 16; i++) acc[i] = 0.0f;
    for (int jt = 0; jt < Lk; jt += 8) {
        int nj = min(8, Lk - jt);
        for (int idx = tid; idx < nj*512; idx += 256) {
            int j = idx >> 9, d = idx & 511;
            krow[j][d] = SRC[(long)rows[jt + j]*512 + d];
        }
        __syncthreads();
        for (int j = 0; j < nj; j++) {
            float p = sS[h][jt + j];
            #pragma unroll
            for (int i = 0; i < 16; i++)
                acc[i] += p * krow[j][i*32 + lane];
        }
        __syncthreads();
    }
    #pragma unroll
    for (int i = 0; i < 16; i++)
        SB[(long)q*4096 + h*512 + i*32 + lane] = acc[i];
}

// ---------------- elementwise add ----------------
__global__ void add_kernel(const float* __restrict__ a, const float* __restrict__ b,
                           float* __restrict__ c, int n) {
    int i = blockIdx.x*256 + threadIdx.x;
    if (i < n) c[i] = a[i] + b[i];
}

// ---------------- host ----------------
static float* sym_f(const void* s) { void* p = nullptr; cudaGetSymbolAddress(&p, s); return (float*)p; }
static int*   sym_i(const void* s) { void* p = nullptr; cudaGetSymbolAddress(&p, s); return (int*)p; }

extern "C" void kernel_launch(void* const* d_in, const int* in_sizes, int n_in,
                              void* d_out, int out_size) {
    const float* x    = (const float*)d_in[0];
    const float* vft  = (const float*)d_in[1];
    const float* his  = (const float*)d_in[2];
    const float* cap  = (const float*)d_in[3];
    const float* qry  = (const float*)d_in[4];
    const int* trg_m  = (const int*)d_in[5];
    const int* his_m  = (const int*)d_in[6];
    const int* cap_m  = (const int*)d_in[7];
    const int* qry_m  = (const int*)d_in[8];
    const int* tmp_m  = (const int*)d_in[9];
    const float* attw = (const float*)d_in[10];
    const float* attb = (const float*)d_in[11];
    const float* ffw1 = (const float*)d_in[12];
    const float* ffb1 = (const float*)d_in[13];
    const float* ffw2 = (const float*)d_in[14];
    const float* ffb2 = (const float*)d_in[15];
    const float* lng  = (const float*)d_in[16];
    const float* lnb  = (const float*)d_in[17];
    float* out = (float*)d_out;

    float* cur   = sym_f(g_cur);
    float* lnA   = sym_f(g_lnA);
    float* lnB   = sym_f(g_lnB);
    float* qA    = sym_f(g_qA);
    float* qB    = sym_f(g_qB);
    float* ks    = sym_f(g_ks);
    float* vs    = sym_f(g_vs);
    float* abA   = sym_f(g_abA);
    float* abB   = sym_f(g_abB);
    float* ts    = sym_f(g_ts);
    float* st    = sym_f(g_st);
    float* ffhA  = sym_f(g_ffhA);
    float* ffhB  = sym_f(g_ffhB);
    float* big0  = sym_f(g_big0);
    float* big1  = sym_f(g_big1);
    float* big2  = sym_f(g_big2);
    float* big3  = sym_f(g_big3);
    float* big4  = sym_f(g_big4);
    float* big5  = sym_f(g_big5);
    float* big6  = sym_f(g_big6);
    float* big7  = sym_f(g_big7);
    int* map_perm = sym_i(g_map_perm);
    int* map_pt   = sym_i(g_map_pt);
    int* map_ps   = sym_i(g_map_ps);
    int* res_t    = sym_i(g_res_t);
    int* res_s    = sym_i(g_res_s);

    // streams & events (host-side objects only; created once)
    static cudaStream_t sA = nullptr, sB = nullptr;
    static cudaEvent_t eStart, eMaps, eVft, eCur, eB, eEnd;
    if (!sA) {
        cudaStreamCreateWithFlags(&sA, cudaStreamNonBlocking);
        cudaStreamCreateWithFlags(&sB, cudaStreamNonBlocking);
        cudaEventCreateWithFlags(&eStart, cudaEventDisableTiming);
        cudaEventCreateWithFlags(&eMaps,  cudaEventDisableTiming);
        cudaEventCreateWithFlags(&eVft,   cudaEventDisableTiming);
        cudaEventCreateWithFlags(&eCur,   cudaEventDisableTiming);
        cudaEventCreateWithFlags(&eB,     cudaEventDisableTiming);
        cudaEventCreateWithFlags(&eEnd,   cudaEventDisableTiming);
    }

    cudaFuncSetAttribute((const void*)attn_tc_kernel,
                         cudaFuncAttributeMaxDynamicSharedMemorySize, 120*1024);

    #define AW(i,j) (attw + ((i)*4+(j))*DD*DD)
    #define ABI(i,j) (attb + ((i)*4+(j))*DD)

    auto gemmN = [](cudaStream_t st_, const float* A, const int* amap, int nch,
                    const float* w0, const float* b0, float* c0,
                    const float* w1, const float* b1, float* c1,
                    const float* R, const int* rmap,
                    int M, int N, int K, int relu) {
        GemmChunks ch;
        ch.w[0] = w0; ch.b[0] = b0; ch.c[0] = c0;
        ch.w[1] = w1; ch.b[1] = b1; ch.c[1] = c1;
        ch.w[2] = nullptr; ch.b[2] = nullptr; ch.c[2] = nullptr;
        dim3 grid(nch * (N/128), M/128);
        sgemm_tc_kernel<<<grid, 256, 0, st_>>>(A, amap, ch, R, rmap, M, N, K, relu);
    };
    auto gemm3 = [](cudaStream_t st_, const float* A,
                    const float* w0, const float* b0, float* c0,
                    const float* w1, const float* b1, float* c1,
                    const float* w2, const float* b2, float* c2,
                    int M, int N, int K) {
        GemmChunks ch;
        ch.w[0] = w0; ch.b[0] = b0; ch.c[0] = c0;
        ch.w[1] = w1; ch.b[1] = b1; ch.c[1] = c1;
        ch.w[2] = w2; ch.b[2] = b2; ch.c[2] = c2;
        dim3 grid(3 * (N/128), M/128);
        sgemm_tc_kernel<<<grid, 256, 0, st_>>>(A, nullptr, ch, nullptr, nullptr, M, N, K, 0);
    };
    auto gemm = [&](cudaStream_t st_, const float* A, const int* amap,
                    const float* W, const float* bias,
                    const float* R, const int* rmap, float* C,
                    int M, int N, int K, int relu) {
        gemmN(st_, A, amap, 1, W, bias, C, nullptr, nullptr, nullptr, R, rmap, M, N, K, relu);
    };
    auto attn = [](cudaStream_t st_, const float* Q, const float* K, const float* V, float* O,
                   int NB, int Lk, int qg, const int* mask, int mode, int mdiv) {
        int LkPad = (Lk + 31) & ~31;
        size_t sh = (size_t)(64*68 + LkPad*68 + 64*(LkPad+4)) * sizeof(float);
        attn_tc_kernel<<<dim3(NB, HH), 256, sh, st_>>>(Q, K, V, O, Lk, LkPad, qg, mask, mode, mdiv);
    };
    auto ln = [&](cudaStream_t st_, const float* in, int li, float* o, int rows) {
        ln_kernel<<<rows, 128, 0, st_>>>(in, lng + li*DD, lnb + li*DD, o);
    };
    // factored Lq=1 attention on a given stream with given scratch base
    auto mha_lq1 = [&](cudaStream_t st_, int wi, const float* q_in, const float* SRC,
                       const int* map, int Lk, float* scratch,
                       const int* mask, int mode, int mdiv, float* result) {
        float* BWK = scratch;
        float* BWV = scratch + 512*4096;
        float* QT  = scratch + 2*512*4096;
        float* SB  = QT + 1024*4096;
        build_bwk_kernel<<<(512*4096+255)/256, 256, 0, st_>>>(AW(wi,1), BWK);
        build_bwv_kernel<<<(4096*512+255)/256, 256, 0, st_>>>(AW(wi,2), BWV);
        gemm(st_, q_in, nullptr, BWK, nullptr, nullptr, nullptr, QT, NTOK_X, 4096, DD, 0);
        attn_wide_kernel<<<NTOK_X, 256, 0, st_>>>(QT, SRC, map, SB, Lk, mask, mode, mdiv);
        gemm(st_, SB, nullptr, BWV, ABI(wi,2), nullptr, nullptr, result, NTOK_X, DD, 4096, 0);
    };

    // ---- fork from capture (legacy) stream ----
    cudaEventRecord(eStart, 0);
    cudaStreamWaitEvent(sA, eStart, 0);
    cudaStreamWaitEvent(sB, eStart, 0);

    // sA: maps (needed by sB's gathered projection and both chains' attn_wide)
    build_maps_kernel<<<dim3(256, 5), 256, 0, sA>>>();
    cudaEventRecord(eMaps, sA);

    // sB: big vft projections, overlapped with mha0-3 on sA
    cudaStreamWaitEvent(sB, eMaps, 0);
    gemmN(sB, vft, map_perm, 2, AW(4,1), ABI(4,1), big0, AW(4,2), ABI(4,2), big1,
          nullptr, nullptr, NTOK_VFT, DD, DD, 0);
    gemmN(sB, vft, nullptr, 2, AW(6,1), ABI(6,1), big4, AW(6,2), ABI(6,2), big5,
          nullptr, nullptr, NTOK_VFT, DD, DD, 0);
    cudaEventRecord(eVft, sB);

    // sA: mha0 (QKV batched)
    ln(sA, x, 0, lnA, NTOK_X);
    gemm3(sA, lnA, AW(0,0), ABI(0,0), qA, AW(0,1), ABI(0,1), ks, AW(0,2), ABI(0,2), vs,
          NTOK_X, DD, DD);
    attn(sA, qA, ks, vs, abA, BB, TTRG, 1, trg_m, 1, 1);
    gemm(sA, abA, nullptr, AW(0,3), ABI(0,3), x, nullptr, cur, NTOK_X, DD, DD, 0);

    // sA: mha1..3
    {
        const float* kvsrc[3] = { his, cap, qry };
        const int    kvrows[3] = { BB*128, BB*64, BB*32 };
        const int    Lks[3]    = { 128, 64, 32 };
        const int*   masks[3]  = { his_m, cap_m, qry_m };
        for (int a = 0; a < 3; a++) {
            int wi = a + 1;
            ln(sA, cur, wi, lnA, NTOK_X);
            gemm(sA, lnA, nullptr, AW(wi,0), ABI(wi,0), nullptr, nullptr, qA, NTOK_X, DD, DD, 0);
            gemmN(sA, kvsrc[a], nullptr, 2,
                  AW(wi,1), ABI(wi,1), ks, AW(wi,2), ABI(wi,2), vs,
                  nullptr, nullptr, kvrows[a], DD, DD, 0);
            attn(sA, qA, ks, vs, abA, BB, Lks[a], 1, masks[a], 2, 1);
            gemm(sA, abA, nullptr, AW(wi,3), ABI(wi,3), cur, nullptr, cur, NTOK_X, DD, DD, 0);
        }
    }
    cudaEventRecord(eCur, sA);   // cur (mm) finalized

    // ================= chain A (sA): temporal2spatial -> mha5 -> ffn0 =================
    ln(sA, cur, 4, lnA, NTOK_X);
    gemm(sA, lnA, nullptr, AW(4,0), ABI(4,0), nullptr, nullptr, qA, NTOK_X, DD, DD, 0);
    cudaStreamWaitEvent(sA, eVft, 0);
    attn(sA, qA, big0, big1, big2, BB*SS, TT, SS, tmp_m, 2, SS);
    gemm(sA, big2, nullptr, AW(4,3), ABI(4,3), cur, res_t, big3, NTOK_VFT, DD, DD, 0);
    // mha5 (scratch carved from big2 — free after out-proj consumed it)
    ln(sA, cur, 5, lnA, NTOK_X);
    gemm(sA, lnA, nullptr, AW(5,0), ABI(5,0), nullptr, nullptr, qA, NTOK_X, DD, DD, 0);
    mha_lq1(sA, 5, qA, big3, map_pt, SS, big2, nullptr, 0, 1, abA);
    gemm(sA, abA, nullptr, AW(5,3), ABI(5,3), cur, nullptr, ts, NTOK_X, DD, DD, 0);
    // ffn0
    ln(sA, ts, 6, lnA, NTOK_X);
    gemm(sA, lnA, nullptr, ffw1 + 0*DD*DFF, ffb1 + 0*DFF, nullptr, nullptr, ffhA, NTOK_X, DFF, DD, 1);
    gemm(sA, ffhA, nullptr, ffw2 + 0*DFF*DD, ffb2 + 0*DD, ts, nullptr, ts, NTOK_X, DD, DFF, 0);

    // ================= chain B (sB): spatial2temporal -> mha7 -> ffn1 =================
    cudaStreamWaitEvent(sB, eCur, 0);
    ln(sB, cur, 7, lnB, NTOK_X);
    gemm(sB, lnB, nullptr, AW(6,0), ABI(6,0), nullptr, nullptr, qB, NTOK_X, DD, DD, 0);
    attn(sB, qB, big4, big5, big6, BB*TT, SS, TT, nullptr, 0, 1);
    gemm(sB, big6, nullptr, AW(6,3), ABI(6,3), cur, res_s, big7, NTOK_SOUT, DD, DD, 0);
    // mha7 (scratch carved from big4 — free after attention consumed it)
    ln(sB, cur, 8, lnB, NTOK_X);
    gemm(sB, lnB, nullptr, AW(7,0), ABI(7,0), nullptr, nullptr, qB, NTOK_X, DD, DD, 0);
    mha_lq1(sB, 7, qB, big7, map_ps, TT, big4, tmp_m, 2, TTRG, abB);
    gemm(sB, abB, nullptr, AW(7,3), ABI(7,3), cur, nullptr, st, NTOK_X, DD, DD, 0);
    // ffn1
    ln(sB, st, 9, lnB, NTOK_X);
    gemm(sB, lnB, nullptr, ffw1 + 1*DD*DFF, ffb1 + 1*DFF, nullptr, nullptr, ffhB, NTOK_X, DFF, DD, 1);
    gemm(sB, ffhB, nullptr, ffw2 + 1*DFF*DD, ffb2 + 1*DD, st, nullptr, st, NTOK_X, DD, DFF, 0);
    cudaEventRecord(eB, sB);

    // ---- join on sA: combine + ffn2 ----
    cudaStreamWaitEvent(sA, eB, 0);
    add_kernel<<<(NTOK_X*DD + 255)/256, 256, 0, sA>>>(ts, st, cur, NTOK_X*DD);
    ln(sA, cur, 10, lnA, NTOK_X);
    gemm(sA, lnA, nullptr, ffw1 + 2*DD*DFF, ffb1 + 2*DFF, nullptr, nullptr, ffhA, NTOK_X, DFF, DD, 1);
    gemm(sA, ffhA, nullptr, ffw2 + 2*DFF*DD, ffb2 + 2*DD, cur, nullptr, out, NTOK_X, DD, DFF, 0);

    cudaEventRecord(eEnd, sA);
    cudaStreamWaitEvent(0, eEnd, 0);

    #undef AW
    #undef ABI
}

// round 12
// speedup vs baseline: 5.0991x; 1.1476x over previous
#include <cuda_runtime.h>
#include <math.h>
#include <stdint.h>

// ---------------- problem constants ----------------
#define BB   16
#define TTRG 64
#define TT   64
#define SS   49
#define DD   512
#define DFF  2048
#define HH   8
#define NTOK_X    (BB*TTRG)          // 1024
#define NTOK_VFT  (BB*TT*SS)         // 50176
#define NTOK_SOUT (BB*TT*TTRG)       // 65536

// ---------------- scratch ----------------
__device__ float g_cur [NTOK_X*DD];
__device__ float g_lnA [NTOK_X*DD];
__device__ float g_lnB [NTOK_X*DD];
__device__ float g_qA  [NTOK_X*DD];
__device__ float g_qB  [NTOK_X*DD];
__device__ float g_ks  [2048*DD];
__device__ float g_vs  [2048*DD];
__device__ float g_abA [NTOK_X*DD];
__device__ float g_abB [NTOK_X*DD];
__device__ float g_ts  [NTOK_X*DD];
__device__ float g_st  [NTOK_X*DD];
__device__ float g_ffhA[NTOK_X*DFF];
__device__ float g_ffhB[NTOK_X*DFF];
__device__ float g_big0[NTOK_SOUT*DD];   // mha4 K
__device__ float g_big1[NTOK_SOUT*DD];   // mha4 V
__device__ float g_big2[NTOK_SOUT*DD];   // mha4 attn out (ao_A)
__device__ float g_big3[NTOK_SOUT*DD];   // chain A scratch
__device__ float g_big4[NTOK_SOUT*DD];   // mha6 K
__device__ float g_big5[NTOK_SOUT*DD];   // mha6 V
__device__ float g_big6[NTOK_SOUT*DD];   // mha6 attn out (ao_B)
__device__ float g_big7[NTOK_SOUT*DD];   // chain B scratch
__device__ int   g_map_perm[NTOK_VFT];
__device__ int   g_map_pt  [NTOK_VFT];
__device__ int   g_map_ps  [NTOK_SOUT];

// ---------------- fused map builder ----------------
__device__ __forceinline__ int swap_map(int m, int Bd, int Cd) {
    int c = m % Cd;
    int b = (m / Cd) % Bd;
    int a = m / (Cd*Bd);
    return (a*Cd + c)*Bd + b;
}
__global__ void build_maps_kernel() {
    int m = blockIdx.x*256 + threadIdx.x;
    int job = blockIdx.y;
    if (job == 0)      { if (m < NTOK_VFT)  g_map_perm[m] = swap_map(m, SS, TT); }
    else if (job == 1) { if (m < NTOK_VFT)  g_map_pt[m]   = swap_map(m, TTRG, SS); }
    else               { if (m < NTOK_SOUT) g_map_ps[m]   = swap_map(m, TTRG, TT); }
}

// ---------------- block-diagonal weight builders ----------------
__global__ void build_bwk_kernel(const float* __restrict__ W, float* __restrict__ BWK) {
    int idx = blockIdx.x*256 + threadIdx.x;
    if (idx >= 512*4096) return;
    int k = idx >> 12, n = idx & 4095;
    int hk = k >> 6, c = k & 63;
    int hn = n >> 9, d = n & 511;
    BWK[idx] = (hk == hn) ? W[d*512 + hk*64 + c] : 0.0f;
}
__global__ void build_bwv_kernel(const float* __restrict__ W, float* __restrict__ BWV) {
    int idx = blockIdx.x*256 + threadIdx.x;
    if (idx >= 4096*512) return;
    int k = idx >> 9, n = idx & 511;
    int hk = k >> 9, d = k & 511;
    int hn = n >> 6, e = n & 63;
    BWV[idx] = (hk == hn) ? W[d*512 + hn*64 + e] : 0.0f;
}
// biasv[n] = sum_d b1[d]*W[d*512+n] + b2[n]
__global__ void bias_compose_kernel(const float* __restrict__ b1, const float* __restrict__ W,
                                    const float* __restrict__ b2, float* __restrict__ biasv) {
    int n = blockIdx.x*128 + threadIdx.x;
    if (n >= 512) return;
    float s = 0.0f;
    for (int d = 0; d < 512; d++) s += b1[d] * W[d*512 + n];
    biasv[n] = s + b2[n];
}

// ---------------- layernorm (D=512) ----------------
__global__ __launch_bounds__(128) void ln_kernel(const float* __restrict__ in,
                                                 const float* __restrict__ gamma,
                                                 const float* __restrict__ beta,
                                                 float* __restrict__ out) {
    int row = blockIdx.x;
    int tid = threadIdx.x;
    const float4* p = reinterpret_cast<const float4*>(in + (long)row*DD);
    float4 v = p[tid];
    float s = v.x + v.y + v.z + v.w;
    float q = v.x*v.x + v.y*v.y + v.z*v.z + v.w*v.w;
    #pragma unroll
    for (int o = 16; o; o >>= 1) {
        s += __shfl_xor_sync(0xffffffffu, s, o);
        q += __shfl_xor_sync(0xffffffffu, q, o);
    }
    __shared__ float ssum[4], ssq[4];
    int warp = tid >> 5, lane = tid & 31;
    if (lane == 0) { ssum[warp] = s; ssq[warp] = q; }
    __syncthreads();
    __shared__ float smean, sinv;
    if (tid == 0) {
        float S = ssum[0]+ssum[1]+ssum[2]+ssum[3];
        float Q = ssq[0]+ssq[1]+ssq[2]+ssq[3];
        float mean = S * (1.0f/DD);
        float var  = Q * (1.0f/DD) - mean*mean;
        float sd   = sqrtf(fmaxf(var, 0.0f));
        smean = mean;
        sinv  = 1.0f / (sd + 1e-6f);
    }
    __syncthreads();
    float mean = smean, inv = sinv;
    float4 gv = reinterpret_cast<const float4*>(gamma)[tid];
    float4 bv = reinterpret_cast<const float4*>(beta)[tid];
    float4 o;
    o.x = gv.x*(v.x-mean)*inv + bv.x;
    o.y = gv.y*(v.y-mean)*inv + bv.y;
    o.z = gv.z*(v.z-mean)*inv + bv.z;
    o.w = gv.w*(v.w-mean)*inv + bv.w;
    reinterpret_cast<float4*>(out + (long)row*DD)[tid] = o;
}

// ---------------- tf32/cp.async/ldmatrix helpers ----------------
__device__ __forceinline__ void mma_tf32(float* c, const uint32_t* a, const uint32_t* b) {
    asm volatile("mma.sync.aligned.m16n8k8.row.col.f32.tf32.tf32.f32 "
        "{%0,%1,%2,%3}, {%4,%5,%6,%7}, {%8,%9}, {%0,%1,%2,%3};"
        : "+f"(c[0]), "+f"(c[1]), "+f"(c[2]), "+f"(c[3])
        : "r"(a[0]), "r"(a[1]), "r"(a[2]), "r"(a[3]), "r"(b[0]), "r"(b[1]));
}
__device__ __forceinline__ void cp_async16(void* smem_ptr, const void* gptr) {
    uint32_t s = (uint32_t)__cvta_generic_to_shared(smem_ptr);
    asm volatile("cp.async.cg.shared.global [%0], [%1], 16;" :: "r"(s), "l"(gptr));
}
#define CP_COMMIT() asm volatile("cp.async.commit_group;")
#define CP_WAIT0()  asm volatile("cp.async.wait_group 0;")
__device__ __forceinline__ void ldsm_x4(uint32_t* r, const void* p) {
    uint32_t a = (uint32_t)__cvta_generic_to_shared(p);
    asm volatile("ldmatrix.sync.aligned.m8n8.x4.shared.b16 {%0,%1,%2,%3}, [%4];"
        : "=r"(r[0]), "=r"(r[1]), "=r"(r[2]), "=r"(r[3]) : "r"(a));
}

// ---------------- multi-chunk tf32 GEMM (128x128 tile, Kc=32, double-buffered) ----
#define TCP 136
#define ASP 36

struct GemmChunks {
    const float* w[3];
    const float* b[3];
    float*       c[3];
};

__global__ __launch_bounds__(256, 2) void sgemm_tc_kernel(
    const float* __restrict__ A, const int* __restrict__ amap,
    GemmChunks ch,
    const float* __restrict__ R, const int* __restrict__ rmap,
    int M, int N, int K, int relu)
{
    __shared__ float As[2][128][ASP];
    __shared__ float Bs[2][32][TCP];
    __shared__ int rowm[128];
    int tid = threadIdx.x;
    int ntiles = N >> 7;
    int widx = blockIdx.x / ntiles;
    int n0 = (blockIdx.x % ntiles) << 7;
    int m0 = blockIdx.y << 7;
    const float* W    = ch.w[widx];
    const float* bias = ch.b[widx];
    float*       C    = ch.c[widx];
    if (tid < 128) rowm[tid] = amap ? amap[m0 + tid] : (m0 + tid);
    __syncthreads();

    int wid = tid >> 5, lane = tid & 31;
    int warp_m = wid >> 2, warp_n = wid & 3;
    int gr = lane >> 2, gc = lane & 3;
    int lrow = lane & 15, lkq = (lane >> 4) << 2;

    int arow = tid >> 1, ak = (tid & 1) << 4;
    const float* aptr = A + (long)rowm[arow]*K + ak;
    int bk = tid >> 5, bn = (lane) << 2;
    const float* bptr = W + (long)bk*N + n0 + bn;

    float acc[4][4][4];
    #pragma unroll
    for (int i = 0; i < 4; i++)
        #pragma unroll
        for (int j = 0; j < 4; j++)
            #pragma unroll
            for (int u = 0; u < 4; u++) acc[i][j][u] = 0.0f;

    #pragma unroll
    for (int q = 0; q < 4; q++)
        cp_async16(&As[0][arow][ak + q*4], aptr + q*4);
    #pragma unroll
    for (int q = 0; q < 4; q++)
        cp_async16(&Bs[0][bk + q*8][bn], bptr + (long)(q*8)*N);
    CP_COMMIT();
    CP_WAIT0();
    __syncthreads();

    int mbase = warp_m << 6;
    int buf = 0;
    for (int k0 = 0; k0 < K; k0 += 32) {
        bool has_next = (k0 + 32) < K;
        if (has_next) {
            #pragma unroll
            for (int q = 0; q < 4; q++)
                cp_async16(&As[buf^1][arow][ak + q*4], aptr + k0 + 32 + q*4);
            #pragma unroll
            for (int q = 0; q < 4; q++)
                cp_async16(&Bs[buf^1][bk + q*8][bn], bptr + (long)(k0 + 32 + q*8)*N);
            CP_COMMIT();
        }
        uint32_t afb[2][4][4];
        #pragma unroll
        for (int mt = 0; mt < 4; mt++)
            ldsm_x4(afb[0][mt], &As[buf][mbase + (mt << 4) + lrow][lkq]);
        #pragma unroll
        for (int ks = 0; ks < 4; ks++) {
            int cur = ks & 1;
            if (ks < 3) {
                #pragma unroll
                for (int mt = 0; mt < 4; mt++)
                    ldsm_x4(afb[cur ^ 1][mt],
                            &As[buf][mbase + (mt << 4) + lrow][((ks + 1) << 3) + lkq]);
            }
            int kb = ks << 3;
            uint32_t bf[4][2];
            #pragma unroll
            for (int nt = 0; nt < 4; nt++) {
                int nb = (warp_n << 5) + (nt << 3) + gr;
                bf[nt][0] = __float_as_uint(Bs[buf][kb+gc  ][nb]);
                bf[nt][1] = __float_as_uint(Bs[buf][kb+gc+4][nb]);
            }
            #pragma unroll
            for (int mt = 0; mt < 4; mt++)
                #pragma unroll
                for (int nt = 0; nt < 4; nt++)
                    mma_tf32(acc[mt][nt], afb[cur][mt], bf[nt]);
        }
        if (has_next) CP_WAIT0();
        __syncthreads();
        buf ^= 1;
    }

    #pragma unroll
    for (int mt = 0; mt < 4; mt++) {
        #pragma unroll
        for (int half = 0; half < 2; half++) {
            int m = m0 + (warp_m << 6) + (mt << 4) + gr + (half << 3);
            long rbase = 0;
            if (R) rbase = (long)(rmap ? rmap[m] : m) * N;
            #pragma unroll
            for (int nt = 0; nt < 4; nt++) {
                int n = n0 + (warp_n << 5) + (nt << 3) + (gc << 1);
                float v0 = acc[mt][nt][half*2 + 0];
                float v1 = acc[mt][nt][half*2 + 1];
                if (bias) { v0 += bias[n]; v1 += bias[n+1]; }
                if (relu) { v0 = fmaxf(v0, 0.0f); v1 = fmaxf(v1, 0.0f); }
                if (R) {
                    float2 rv = *reinterpret_cast<const float2*>(R + rbase + n);
                    v0 += rv.x; v1 += rv.y;
                }
                *reinterpret_cast<float2*>(C + (long)m*N + n) = make_float2(v0, v1);
            }
        }
    }
}

// ---------------- tensor-core attention, Lq=64, dk=64 ----------------
__global__ __launch_bounds__(256) void attn_tc_kernel(
    const float* __restrict__ Q, const float* __restrict__ Kg,
    const float* __restrict__ Vg, float* __restrict__ O,
    int Lk, int LkPad, int q_group,
    const int* __restrict__ mask, int mask_mode, int mask_div)
{
    extern __shared__ float sm[];
    float* sQ  = sm;
    float* sKV = sm + 64*68;
    float* sS  = sKV + LkPad*68;
    int batch = blockIdx.x, h = blockIdx.y;
    int tid = threadIdx.x;
    int qbase = (batch / q_group) * 64;
    int sp = LkPad + 4;

    int wid = tid >> 5, lane = tid & 31;
    int warp_m = wid >> 2, warp_n = wid & 3;
    int gr = lane >> 2, gc = lane & 3;
    int nw  = LkPad >> 2;
    int ntn = LkPad >> 5;

    for (int c4 = tid; c4 < 64*16; c4 += 256) {
        int i = c4 >> 4, d = (c4 & 15) << 2;
        cp_async16(&sQ[i*68 + d], &Q[(long)(qbase + i)*DD + h*64 + d]);
    }
    for (int c4 = tid; c4 < Lk*16; c4 += 256) {
        int j = c4 >> 4, d = (c4 & 15) << 2;
        cp_async16(&sKV[j*68 + d], &Kg[(long)(batch*Lk + j)*DD + h*64 + d]);
    }
    CP_COMMIT();
    for (int idx = Lk*64 + tid; idx < LkPad*64; idx += 256) {
        int j = idx >> 6, d = idx & 63;
        sKV[j*68 + d] = 0.0f;
    }
    CP_WAIT0();
    __syncthreads();

    {
        float acc[2][4][4];
        #pragma unroll
        for (int mt = 0; mt < 2; mt++)
            #pragma unroll
            for (int nt = 0; nt < 4; nt++)
                #pragma unroll
                for (int u = 0; u < 4; u++) acc[mt][nt][u] = 0.0f;

        for (int kb = 0; kb < 64; kb += 8) {
            uint32_t af[2][4];
            #pragma unroll
            for (int mt = 0; mt < 2; mt++) {
                int mr = warp_m*32 + mt*16 + gr;
                af[mt][0] = __float_as_uint(sQ[mr*68 + kb+gc]);
                af[mt][1] = __float_as_uint(sQ[(mr+8)*68 + kb+gc]);
                af[mt][2] = __float_as_uint(sQ[mr*68 + kb+gc+4]);
                af[mt][3] = __float_as_uint(sQ[(mr+8)*68 + kb+gc+4]);
            }
            for (int nt = 0; nt < ntn; nt++) {
                int nc = warp_n*nw + nt*8 + gr;
                uint32_t bf[2];
                bf[0] = __float_as_uint(sKV[nc*68 + kb+gc]);
                bf[1] = __float_as_uint(sKV[nc*68 + kb+gc+4]);
                mma_tf32(acc[0][nt], af[0], bf);
                mma_tf32(acc[1][nt], af[1], bf);
            }
        }
        #pragma unroll
        for (int mt = 0; mt < 2; mt++)
            for (int nt = 0; nt < ntn; nt++) {
                int row = warp_m*32 + mt*16 + gr;
                int col = warp_n*nw + nt*8 + (gc << 1);
                sS[row*sp + col]       = acc[mt][nt][0]*0.125f;
                sS[row*sp + col + 1]   = acc[mt][nt][1]*0.125f;
                sS[(row+8)*sp + col]   = acc[mt][nt][2]*0.125f;
                sS[(row+8)*sp + col+1] = acc[mt][nt][3]*0.125f;
            }
    }
    __syncthreads();

    for (int c4 = tid; c4 < Lk*16; c4 += 256) {
        int j = c4 >> 4, d = (c4 & 15) << 2;
        cp_async16(&sKV[j*68 + d], &Vg[(long)(batch*Lk + j)*DD + h*64 + d]);
    }
    CP_COMMIT();

    for (int i = wid; i < 64; i += 8) {
        float mx = -3.4e38f;
        for (int j = lane; j < Lk; j += 32) {
            float v = sS[i*sp + j];
            bool dead = false;
            if (mask_mode == 1) dead = (mask[(long)(batch*64 + i)*Lk + j] == 0);
            else if (mask_mode == 2) dead = (mask[(batch/mask_div)*Lk + j] == 0);
            if (dead) { v = -1e9f; sS[i*sp + j] = v; }
            mx = fmaxf(mx, v);
        }
        #pragma unroll
        for (int o = 16; o; o >>= 1) mx = fmaxf(mx, __shfl_xor_sync(0xffffffffu, mx, o));
        float sum = 0.0f;
        for (int j = lane; j < Lk; j += 32) {
            float e = __expf(sS[i*sp + j] - mx);
            sS[i*sp + j] = e;
            sum += e;
        }
        #pragma unroll
        for (int o = 16; o; o >>= 1) sum += __shfl_xor_sync(0xffffffffu, sum, o);
        float inv = 1.0f / sum;
        for (int j = lane; j < Lk; j += 32) sS[i*sp + j] *= inv;
        for (int j = Lk + lane; j < LkPad; j += 32) sS[i*sp + j] = 0.0f;
    }
    CP_WAIT0();
    __syncthreads();

    {
        float acc[2][2][4];
        #pragma unroll
        for (int mt = 0; mt < 2; mt++)
            #pragma unroll
            for (int nt = 0; nt < 2; nt++)
                #pragma unroll
                for (int u = 0; u < 4; u++) acc[mt][nt][u] = 0.0f;

        for (int kb = 0; kb < LkPad; kb += 8) {
            uint32_t af[2][4];
            #pragma unroll
            for (int mt = 0; mt < 2; mt++) {
                int mr = warp_m*32 + mt*16 + gr;
                af[mt][0] = __float_as_uint(sS[mr*sp + kb+gc]);
                af[mt][1] = __float_as_uint(sS[(mr+8)*sp + kb+gc]);
                af[mt][2] = __float_as_uint(sS[mr*sp + kb+gc+4]);
                af[mt][3] = __float_as_uint(sS[(mr+8)*sp + kb+gc+4]);
            }
            #pragma unroll
            for (int nt = 0; nt < 2; nt++) {
                int nc = warp_n*16 + nt*8 + gr;
                uint32_t bf[2];
                int k0r = kb+gc, k1r = kb+gc+4;
                bf[0] = (k0r < Lk) ? __float_as_uint(sKV[k0r*68 + nc]) : 0u;
                bf[1] = (k1r < Lk) ? __float_as_uint(sKV[k1r*68 + nc]) : 0u;
                mma_tf32(acc[0][nt], af[0], bf);
                mma_tf32(acc[1][nt], af[1], bf);
            }
        }
        #pragma unroll
        for (int mt = 0; mt < 2; mt++)
            #pragma unroll
            for (int nt = 0; nt < 2; nt++) {
                int i = warp_m*32 + mt*16 + gr;
                int d = warp_n*16 + nt*8 + (gc << 1);
                long base = (long)(batch*64 + i)*DD + h*64 + d;
                *reinterpret_cast<float2*>(O + base) =
                    make_float2(acc[mt][nt][0], acc[mt][nt][1]);
                *reinterpret_cast<float2*>(O + base + 8*DD) =
                    make_float2(acc[mt][nt][2], acc[mt][nt][3]);
            }
    }
}

// ---------------- wide Lq=1 attention over RAW rows ----------------
__global__ __launch_bounds__(256) void attn_wide_kernel(
    const float* __restrict__ QT, const float* __restrict__ SRC,
    const int* __restrict__ map, float* __restrict__ SB,
    int Lk, const int* __restrict__ mask, int mask_mode, int mask_div)
{
    __shared__ float qt8[8*512];
    __shared__ float krow[8][516];
    __shared__ float sS[8][72];
    __shared__ int   rows[64];
    int q = blockIdx.x;
    int tid = threadIdx.x;
    int h = tid >> 5, lane = tid & 31;

    for (int i = tid; i < 4096; i += 256) qt8[i] = QT[(long)q*4096 + i];
    if (tid < Lk) rows[tid] = map[q*Lk + tid];
    __syncthreads();

    for (int jt = 0; jt < Lk; jt += 8) {
        int nj = min(8, Lk - jt);
        for (int idx = tid; idx < nj*512; idx += 256) {
            int j = idx >> 9, d = idx & 511;
            krow[j][d] = SRC[(long)rows[jt + j]*512 + d];
        }
        __syncthreads();
        for (int j = 0; j < nj; j++) {
            float s = 0.0f;
            #pragma unroll
            for (int i = 0; i < 16; i++)
                s += qt8[h*512 + i*32 + lane] * krow[j][i*32 + lane];
            #pragma unroll
            for (int o = 16; o; o >>= 1) s += __shfl_xor_sync(0xffffffffu, s, o);
            if (lane == 0) sS[h][jt + j] = s * 0.125f;
        }
        __syncthreads();
    }

    {
        float mx = -3.4e38f;
        for (int j = lane; j < Lk; j += 32) {
            float v = sS[h][j];
            if (mask_mode == 2 && mask[(q/mask_div)*Lk + j] == 0) { v = -1e9f; sS[h][j] = v; }
            mx = fmaxf(mx, v);
        }
        #pragma unroll
        for (int o = 16; o; o >>= 1) mx = fmaxf(mx, __shfl_xor_sync(0xffffffffu, mx, o));
        float sum = 0.0f;
        for (int j = lane; j < Lk; j += 32) {
            float e = __expf(sS[h][j] - mx);
            sS[h][j] = e;
            sum += e;
        }
        #pragma unroll
        for (int o = 16; o; o >>= 1) sum += __shfl_xor_sync(0xffffffffu, sum, o);
        float inv = 1.0f / sum;
        for (int j = lane; j < Lk; j += 32) sS[h][j] *= inv;
    }
    __syncthreads();

    float acc[16];
    #pragma unroll
    for (int i = 0; i < 16; i++) acc[i] = 0.0f;
    for (int jt = 0; jt < Lk; jt += 8) {
        int nj = min(8, Lk - jt);
        for (int idx = tid; idx < nj*512; idx += 256) {
            int j = idx >> 9, d = idx & 511;
            krow[j][d] = SRC[(long)rows[jt + j]*512 + d];
        }
        __syncthreads();
        for (int j = 0; j < nj; j++) {
            float p = sS[h][jt + j];
            #pragma unroll
            for (int i = 0; i < 16; i++)
                acc[i] += p * krow[j][i*32 + lane];
        }
        __syncthreads();
    }
    #pragma unroll
    for (int i = 0; i < 16; i++)
        SB[(long)q*4096 + h*512 + i*32 + lane] = acc[i];
}

// ---------------- elementwise add ----------------
__global__ void add_kernel(const float* __restrict__ a, const float* __restrict__ b,
                           float* __restrict__ c, int n) {
    int i = blockIdx.x*256 + threadIdx.x;
    if (i < n) c[i] = a[i] + b[i];
}

// ---------------- host ----------------
static float* sym_f(const void* s) { void* p = nullptr; cudaGetSymbolAddress(&p, s); return (float*)p; }
static int*   sym_i(const void* s) { void* p = nullptr; cudaGetSymbolAddress(&p, s); return (int*)p; }

extern "C" void kernel_launch(void* const* d_in, const int* in_sizes, int n_in,
                              void* d_out, int out_size) {
    const float* x    = (const float*)d_in[0];
    const float* vft  = (const float*)d_in[1];
    const float* his  = (const float*)d_in[2];
    const float* cap  = (const float*)d_in[3];
    const float* qry  = (const float*)d_in[4];
    const int* trg_m  = (const int*)d_in[5];
    const int* his_m  = (const int*)d_in[6];
    const int* cap_m  = (const int*)d_in[7];
    const int* qry_m  = (const int*)d_in[8];
    const int* tmp_m  = (const int*)d_in[9];
    const float* attw = (const float*)d_in[10];
    const float* attb = (const float*)d_in[11];
    const float* ffw1 = (const float*)d_in[12];
    const float* ffb1 = (const float*)d_in[13];
    const float* ffw2 = (const float*)d_in[14];
    const float* ffb2 = (const float*)d_in[15];
    const float* lng  = (const float*)d_in[16];
    const float* lnb  = (const float*)d_in[17];
    float* out = (float*)d_out;

    float* cur   = sym_f(g_cur);
    float* lnA   = sym_f(g_lnA);
    float* lnB   = sym_f(g_lnB);
    float* qA    = sym_f(g_qA);
    float* qB    = sym_f(g_qB);
    float* ks    = sym_f(g_ks);
    float* vs    = sym_f(g_vs);
    float* abA   = sym_f(g_abA);
    float* abB   = sym_f(g_abB);
    float* ts    = sym_f(g_ts);
    float* st    = sym_f(g_st);
    float* ffhA  = sym_f(g_ffhA);
    float* ffhB  = sym_f(g_ffhB);
    float* big0  = sym_f(g_big0);
    float* big1  = sym_f(g_big1);
    float* big2  = sym_f(g_big2);
    float* big3  = sym_f(g_big3);
    float* big4  = sym_f(g_big4);
    float* big5  = sym_f(g_big5);
    float* big6  = sym_f(g_big6);
    float* big7  = sym_f(g_big7);
    int* map_perm = sym_i(g_map_perm);
    int* map_pt   = sym_i(g_map_pt);
    int* map_ps   = sym_i(g_map_ps);

    // per-chain scratch layout inside big3 (A) / big7 (B)
    const long OFF_BWK = 0;              // 512*4096  = 2M
    const long OFF_BWV = 2*1024*1024;    // 4096*512  = 2M
    const long OFF_QT  = 4*1024*1024;    // 1024*4096 = 4M
    const long OFF_SB  = 8*1024*1024;    // 1024*4096 = 4M
    const long OFF_U2  = 12*1024*1024;   // 1024*512
    const long OFF_PK  = 13*1024*1024;   // 512*512
    const long OFF_PV  = OFF_PK + 512*512;
    const long OFF_BV  = OFF_PV + 512*512;  // 512

    static cudaStream_t sA = nullptr, sB = nullptr, sC = nullptr;
    static cudaEvent_t eStart, eMaps, eVft, eCur, eC, eB, eEnd;
    if (!sA) {
        cudaStreamCreateWithFlags(&sA, cudaStreamNonBlocking);
        cudaStreamCreateWithFlags(&sB, cudaStreamNonBlocking);
        cudaStreamCreateWithFlags(&sC, cudaStreamNonBlocking);
        cudaEventCreateWithFlags(&eStart, cudaEventDisableTiming);
        cudaEventCreateWithFlags(&eMaps,  cudaEventDisableTiming);
        cudaEventCreateWithFlags(&eVft,   cudaEventDisableTiming);
        cudaEventCreateWithFlags(&eCur,   cudaEventDisableTiming);
        cudaEventCreateWithFlags(&eC,     cudaEventDisableTiming);
        cudaEventCreateWithFlags(&eB,     cudaEventDisableTiming);
        cudaEventCreateWithFlags(&eEnd,   cudaEventDisableTiming);
    }

    cudaFuncSetAttribute((const void*)attn_tc_kernel,
                         cudaFuncAttributeMaxDynamicSharedMemorySize, 120*1024);

    #define AW(i,j) (attw + ((i)*4+(j))*DD*DD)
    #define ABI(i,j) (attb + ((i)*4+(j))*DD)

    auto gemmN = [](cudaStream_t st_, const float* A, const int* amap, int nch,
                    const float* w0, const float* b0, float* c0,
                    const float* w1, const float* b1, float* c1,
                    const float* R, const int* rmap,
                    int M, int N, int K, int relu) {
        GemmChunks ch;
        ch.w[0] = w0; ch.b[0] = b0; ch.c[0] = c0;
        ch.w[1] = w1; ch.b[1] = b1; ch.c[1] = c1;
        ch.w[2] = nullptr; ch.b[2] = nullptr; ch.c[2] = nullptr;
        dim3 grid(nch * (N/128), M/128);
        sgemm_tc_kernel<<<grid, 256, 0, st_>>>(A, amap, ch, R, rmap, M, N, K, relu);
    };
    auto gemm3 = [](cudaStream_t st_, const float* A,
                    const float* w0, const float* b0, float* c0,
                    const float* w1, const float* b1, float* c1,
                    const float* w2, const float* b2, float* c2,
                    int M, int N, int K) {
        GemmChunks ch;
        ch.w[0] = w0; ch.b[0] = b0; ch.c[0] = c0;
        ch.w[1] = w1; ch.b[1] = b1; ch.c[1] = c1;
        ch.w[2] = w2; ch.b[2] = b2; ch.c[2] = c2;
        dim3 grid(3 * (N/128), M/128);
        sgemm_tc_kernel<<<grid, 256, 0, st_>>>(A, nullptr, ch, nullptr, nullptr, M, N, K, 0);
    };
    auto gemm = [&](cudaStream_t st_, const float* A, const int* amap,
                    const float* W, const float* bias,
                    const float* R, const int* rmap, float* C,
                    int M, int N, int K, int relu) {
        gemmN(st_, A, amap, 1, W, bias, C, nullptr, nullptr, nullptr, R, rmap, M, N, K, relu);
    };
    auto attn = [](cudaStream_t st_, const float* Q, const float* K, const float* V, float* O,
                   int NB, int Lk, int qg, const int* mask, int mode, int mdiv) {
        int LkPad = (Lk + 31) & ~31;
        size_t sh = (size_t)(64*68 + LkPad*68 + 64*(LkPad+4)) * sizeof(float);
        attn_tc_kernel<<<dim3(NB, HH), 256, sh, st_>>>(Q, K, V, O, Lk, LkPad, qg, mask, mode, mdiv);
    };
    auto ln = [&](cudaStream_t st_, const float* in, int li, float* o, int rows) {
        ln_kernel<<<rows, 128, 0, st_>>>(in, lng + li*DD, lnb + li*DD, o);
    };

    // ---- fork ----
    cudaEventRecord(eStart, 0);
    cudaStreamWaitEvent(sA, eStart, 0);
    cudaStreamWaitEvent(sB, eStart, 0);
    cudaStreamWaitEvent(sC, eStart, 0);

    // sC: weight-only prep for factored mha5/mha7 (off critical path)
    {
        // Pk/Pv for chain A: P = W43 @ {Wk5, Wv5}; chain B: W63 @ {Wk7, Wv7}
        gemmN(sC, AW(4,3), nullptr, 2, AW(5,1), nullptr, big3 + OFF_PK,
              AW(5,2), nullptr, big3 + OFF_PV, nullptr, nullptr, DD, DD, DD, 0);
        gemmN(sC, AW(6,3), nullptr, 2, AW(7,1), nullptr, big7 + OFF_PK,
              AW(7,2), nullptr, big7 + OFF_PV, nullptr, nullptr, DD, DD, DD, 0);
        bias_compose_kernel<<<4, 128, 0, sC>>>(ABI(4,3), AW(5,2), ABI(5,2), big3 + OFF_BV);
        bias_compose_kernel<<<4, 128, 0, sC>>>(ABI(6,3), AW(7,2), ABI(7,2), big7 + OFF_BV);
        build_bwk_kernel<<<(512*4096+255)/256, 256, 0, sC>>>(big3 + OFF_PK, big3 + OFF_BWK);
        build_bwv_kernel<<<(4096*512+255)/256, 256, 0, sC>>>(big3 + OFF_PV, big3 + OFF_BWV);
        build_bwk_kernel<<<(512*4096+255)/256, 256, 0, sC>>>(big7 + OFF_PK, big7 + OFF_BWK);
        build_bwv_kernel<<<(4096*512+255)/256, 256, 0, sC>>>(big7 + OFF_PV, big7 + OFF_BWV);
        cudaEventRecord(eC, sC);
    }

    // sA: maps
    build_maps_kernel<<<dim3(256, 3), 256, 0, sA>>>();
    cudaEventRecord(eMaps, sA);

    // sB: big vft projections, overlapped with mha0-3
    cudaStreamWaitEvent(sB, eMaps, 0);
    gemmN(sB, vft, map_perm, 2, AW(4,1), ABI(4,1), big0, AW(4,2), ABI(4,2), big1,
          nullptr, nullptr, NTOK_VFT, DD, DD, 0);
    gemmN(sB, vft, nullptr, 2, AW(6,1), ABI(6,1), big4, AW(6,2), ABI(6,2), big5,
          nullptr, nullptr, NTOK_VFT, DD, DD, 0);
    cudaEventRecord(eVft, sB);

    // sA: mha0
    ln(sA, x, 0, lnA, NTOK_X);
    gemm3(sA, lnA, AW(0,0), ABI(0,0), qA, AW(0,1), ABI(0,1), ks, AW(0,2), ABI(0,2), vs,
          NTOK_X, DD, DD);
    attn(sA, qA, ks, vs, abA, BB, TTRG, 1, trg_m, 1, 1);
    gemm(sA, abA, nullptr, AW(0,3), ABI(0,3), x, nullptr, cur, NTOK_X, DD, DD, 0);

    // sA: mha1..3
    {
        const float* kvsrc[3] = { his, cap, qry };
        const int    kvrows[3] = { BB*128, BB*64, BB*32 };
        const int    Lks[3]    = { 128, 64, 32 };
        const int*   masks[3]  = { his_m, cap_m, qry_m };
        for (int a = 0; a < 3; a++) {
            int wi = a + 1;
            ln(sA, cur, wi, lnA, NTOK_X);
            gemm(sA, lnA, nullptr, AW(wi,0), ABI(wi,0), nullptr, nullptr, qA, NTOK_X, DD, DD, 0);
            gemmN(sA, kvsrc[a], nullptr, 2,
                  AW(wi,1), ABI(wi,1), ks, AW(wi,2), ABI(wi,2), vs,
                  nullptr, nullptr, kvrows[a], DD, DD, 0);
            attn(sA, qA, ks, vs, abA, BB, Lks[a], 1, masks[a], 2, 1);
            gemm(sA, abA, nullptr, AW(wi,3), ABI(wi,3), cur, nullptr, cur, NTOK_X, DD, DD, 0);
        }
    }
    cudaEventRecord(eCur, sA);

    // ================= chain A (sA): mha4 attn -> factored mha5 -> ffn0 =================
    ln(sA, cur, 4, lnA, NTOK_X);
    gemm(sA, lnA, nullptr, AW(4,0), ABI(4,0), nullptr, nullptr, qA, NTOK_X, DD, DD, 0);
    cudaStreamWaitEvent(sA, eVft, 0);
    attn(sA, qA, big0, big1, big2, BB*SS, TT, SS, tmp_m, 2, SS);   // ao_A in big2
    // factored mha5 (no t_out materialization)
    ln(sA, cur, 5, lnA, NTOK_X);
    gemm(sA, lnA, nullptr, AW(5,0), ABI(5,0), nullptr, nullptr, qA, NTOK_X, DD, DD, 0);
    cudaStreamWaitEvent(sA, eC, 0);
    gemm(sA, cur, nullptr, AW(5,2), big3 + OFF_BV, nullptr, nullptr, big3 + OFF_U2,
         NTOK_X, DD, DD, 0);                                        // U2 = (cur+b43)@Wv5 + bv5
    gemm(sA, qA, nullptr, big3 + OFF_BWK, nullptr, nullptr, nullptr, big3 + OFF_QT,
         NTOK_X, 4096, DD, 0);                                      // QTW
    attn_wide_kernel<<<NTOK_X, 256, 0, sA>>>(big3 + OFF_QT, big2, map_pt, big3 + OFF_SB,
                                             SS, nullptr, 0, 1);
    gemm(sA, big3 + OFF_SB, nullptr, big3 + OFF_BWV, nullptr, big3 + OFF_U2, nullptr,
         abA, NTOK_X, DD, 4096, 0);
    gemm(sA, abA, nullptr, AW(5,3), ABI(5,3), cur, nullptr, ts, NTOK_X, DD, DD, 0);
    // ffn0
    ln(sA, ts, 6, lnA, NTOK_X);
    gemm(sA, lnA, nullptr, ffw1 + 0*DD*DFF, ffb1 + 0*DFF, nullptr, nullptr, ffhA, NTOK_X, DFF, DD, 1);
    gemm(sA, ffhA, nullptr, ffw2 + 0*DFF*DD, ffb2 + 0*DD, ts, nullptr, ts, NTOK_X, DD, DFF, 0);

    // ================= chain B (sB): mha6 attn -> factored mha7 -> ffn1 =================
    cudaStreamWaitEvent(sB, eCur, 0);
    ln(sB, cur, 7, lnB, NTOK_X);
    gemm(sB, lnB, nullptr, AW(6,0), ABI(6,0), nullptr, nullptr, qB, NTOK_X, DD, DD, 0);
    attn(sB, qB, big4, big5, big6, BB*TT, SS, TT, nullptr, 0, 1);   // ao_B in big6
    // factored mha7
    ln(sB, cur, 8, lnB, NTOK_X);
    gemm(sB, lnB, nullptr, AW(7,0), ABI(7,0), nullptr, nullptr, qB, NTOK_X, DD, DD, 0);
    cudaStreamWaitEvent(sB, eC, 0);
    gemm(sB, cur, nullptr, AW(7,2), big7 + OFF_BV, nullptr, nullptr, big7 + OFF_U2,
         NTOK_X, DD, DD, 0);
    gemm(sB, qB, nullptr, big7 + OFF_BWK, nullptr, nullptr, nullptr, big7 + OFF_QT,
         NTOK_X, 4096, DD, 0);
    attn_wide_kernel<<<NTOK_X, 256, 0, sB>>>(big7 + OFF_QT, big6, map_ps, big7 + OFF_SB,
                                             TT, tmp_m, 2, TTRG);
    gemm(sB, big7 + OFF_SB, nullptr, big7 + OFF_BWV, nullptr, big7 + OFF_U2, nullptr,
         abB, NTOK_X, DD, 4096, 0);
    gemm(sB, abB, nullptr, AW(7,3), ABI(7,3), cur, nullptr, st, NTOK_X, DD, DD, 0);
    // ffn1
    ln(sB, st, 9, lnB, NTOK_X);
    gemm(sB, lnB, nullptr, ffw1 + 1*DD*DFF, ffb1 + 1*DFF, nullptr, nullptr, ffhB, NTOK_X, DFF, DD, 1);
    gemm(sB, ffhB, nullptr, ffw2 + 1*DFF*DD, ffb2 + 1*DD, st, nullptr, st, NTOK_X, DD, DFF, 0);
    cudaEventRecord(eB, sB);

    // ---- join on sA ----
    cudaStreamWaitEvent(sA, eB, 0);
    add_kernel<<<(NTOK_X*DD + 255)/256, 256, 0, sA>>>(ts, st, cur, NTOK_X*DD);
    ln(sA, cur, 10, lnA, NTOK_X);
    gemm(sA, lnA, nullptr, ffw1 + 2*DD*DFF, ffb1 + 2*DFF, nullptr, nullptr, ffhA, NTOK_X, DFF, DD, 1);
    gemm(sA, ffhA, nullptr, ffw2 + 2*DFF*DD, ffb2 + 2*DD, cur, nullptr, out, NTOK_X, DD, DFF, 0);

    cudaEventRecord(eEnd, sA);
    cudaStreamWaitEvent(0, eEnd, 0);

    #undef AW
    #undef ABI
}

// round 13
// speedup vs baseline: 5.2448x; 1.0286x over previous
#include <cuda_runtime.h>
#include <math.h>
#include <stdint.h>

// ---------------- problem constants ----------------
#define BB   16
#define TTRG 64
#define TT   64
#define SS   49
#define DD   512
#define DFF  2048
#define HH   8
#define NTOK_X    (BB*TTRG)          // 1024
#define NTOK_VFT  (BB*TT*SS)         // 50176
#define NTOK_SOUT (BB*TT*TTRG)       // 65536

// ---------------- scratch ----------------
__device__ float g_cur [NTOK_X*DD];
__device__ float g_lnA [NTOK_X*DD];
__device__ float g_lnB [NTOK_X*DD];
__device__ float g_lnC [NTOK_X*DD];
__device__ float g_qA  [NTOK_X*DD];
__device__ float g_qB  [NTOK_X*DD];
__device__ float g_ks  [2048*DD];
__device__ float g_vs  [2048*DD];
__device__ float g_abA [NTOK_X*DD];
__device__ float g_abB [NTOK_X*DD];
__device__ float g_ts  [NTOK_X*DD];
__device__ float g_st  [NTOK_X*DD];
__device__ float g_ffhA[NTOK_X*DFF];
__device__ float g_ffhB[NTOK_X*DFF];
__device__ float g_big0[NTOK_SOUT*DD];   // mha4 K
__device__ float g_big1[NTOK_SOUT*DD];   // mha4 V
__device__ float g_big2[NTOK_SOUT*DD];   // head: ao_A (25.7M); tail @26M: mha1-3 KV
__device__ float g_big3[NTOK_SOUT*DD];   // chain A scratch
__device__ float g_big4[NTOK_SOUT*DD];   // mha6 K
__device__ float g_big5[NTOK_SOUT*DD];   // mha6 V
__device__ float g_big6[NTOK_SOUT*DD];   // mha6 attn out (ao_B)
__device__ float g_big7[NTOK_SOUT*DD];   // chain B scratch
__device__ int   g_map_perm[NTOK_VFT];
__device__ int   g_map_pt  [NTOK_VFT];
__device__ int   g_map_ps  [NTOK_SOUT];

// ---------------- fused map builder ----------------
__device__ __forceinline__ int swap_map(int m, int Bd, int Cd) {
    int c = m % Cd;
    int b = (m / Cd) % Bd;
    int a = m / (Cd*Bd);
    return (a*Cd + c)*Bd + b;
}
__global__ void build_maps_kernel() {
    int m = blockIdx.x*256 + threadIdx.x;
    int job = blockIdx.y;
    if (job == 0)      { if (m < NTOK_VFT)  g_map_perm[m] = swap_map(m, SS, TT); }
    else if (job == 1) { if (m < NTOK_VFT)  g_map_pt[m]   = swap_map(m, TTRG, SS); }
    else               { if (m < NTOK_SOUT) g_map_ps[m]   = swap_map(m, TTRG, TT); }
}

// ---------------- block-diagonal weight builders ----------------
__global__ void build_bwk_kernel(const float* __restrict__ W, float* __restrict__ BWK) {
    int idx = blockIdx.x*256 + threadIdx.x;
    if (idx >= 512*4096) return;
    int k = idx >> 12, n = idx & 4095;
    int hk = k >> 6, c = k & 63;
    int hn = n >> 9, d = n & 511;
    BWK[idx] = (hk == hn) ? W[d*512 + hk*64 + c] : 0.0f;
}
__global__ void build_bwv_kernel(const float* __restrict__ W, float* __restrict__ BWV) {
    int idx = blockIdx.x*256 + threadIdx.x;
    if (idx >= 4096*512) return;
    int k = idx >> 9, n = idx & 511;
    int hk = k >> 9, d = k & 511;
    int hn = n >> 6, e = n & 63;
    BWV[idx] = (hk == hn) ? W[d*512 + hn*64 + e] : 0.0f;
}
// biasv[n] = sum_d b1[d]*W[d*512+n] + b2[n]; warp-per-n
__global__ void bias_compose_kernel(const float* __restrict__ b1, const float* __restrict__ W,
                                    const float* __restrict__ b2, float* __restrict__ biasv) {
    int n = blockIdx.x*8 + (threadIdx.x >> 5);
    int lane = threadIdx.x & 31;
    if (n >= 512) return;
    float s = 0.0f;
    for (int d = lane; d < 512; d += 32) s += b1[d] * W[d*512 + n];
    #pragma unroll
    for (int o = 16; o; o >>= 1) s += __shfl_xor_sync(0xffffffffu, s, o);
    if (lane == 0) biasv[n] = s + b2[n];
}

// ---------------- layernorm (D=512) ----------------
__global__ __launch_bounds__(128) void ln_kernel(const float* __restrict__ in,
                                                 const float* __restrict__ gamma,
                                                 const float* __restrict__ beta,
                                                 float* __restrict__ out) {
    int row = blockIdx.x;
    int tid = threadIdx.x;
    const float4* p = reinterpret_cast<const float4*>(in + (long)row*DD);
    float4 v = p[tid];
    float s = v.x + v.y + v.z + v.w;
    float q = v.x*v.x + v.y*v.y + v.z*v.z + v.w*v.w;
    #pragma unroll
    for (int o = 16; o; o >>= 1) {
        s += __shfl_xor_sync(0xffffffffu, s, o);
        q += __shfl_xor_sync(0xffffffffu, q, o);
    }
    __shared__ float ssum[4], ssq[4];
    int warp = tid >> 5, lane = tid & 31;
    if (lane == 0) { ssum[warp] = s; ssq[warp] = q; }
    __syncthreads();
    __shared__ float smean, sinv;
    if (tid == 0) {
        float S = ssum[0]+ssum[1]+ssum[2]+ssum[3];
        float Q = ssq[0]+ssq[1]+ssq[2]+ssq[3];
        float mean = S * (1.0f/DD);
        float var  = Q * (1.0f/DD) - mean*mean;
        float sd   = sqrtf(fmaxf(var, 0.0f));
        smean = mean;
        sinv  = 1.0f / (sd + 1e-6f);
    }
    __syncthreads();
    float mean = smean, inv = sinv;
    float4 gv = reinterpret_cast<const float4*>(gamma)[tid];
    float4 bv = reinterpret_cast<const float4*>(beta)[tid];
    float4 o;
    o.x = gv.x*(v.x-mean)*inv + bv.x;
    o.y = gv.y*(v.y-mean)*inv + bv.y;
    o.z = gv.z*(v.z-mean)*inv + bv.z;
    o.w = gv.w*(v.w-mean)*inv + bv.w;
    reinterpret_cast<float4*>(out + (long)row*DD)[tid] = o;
}

// ---------------- tf32/cp.async/ldmatrix helpers ----------------
__device__ __forceinline__ void mma_tf32(float* c, const uint32_t* a, const uint32_t* b) {
    asm volatile("mma.sync.aligned.m16n8k8.row.col.f32.tf32.tf32.f32 "
        "{%0,%1,%2,%3}, {%4,%5,%6,%7}, {%8,%9}, {%0,%1,%2,%3};"
        : "+f"(c[0]), "+f"(c[1]), "+f"(c[2]), "+f"(c[3])
        : "r"(a[0]), "r"(a[1]), "r"(a[2]), "r"(a[3]), "r"(b[0]), "r"(b[1]));
}
__device__ __forceinline__ void cp_async16(void* smem_ptr, const void* gptr) {
    uint32_t s = (uint32_t)__cvta_generic_to_shared(smem_ptr);
    asm volatile("cp.async.cg.shared.global [%0], [%1], 16;" :: "r"(s), "l"(gptr));
}
#define CP_COMMIT() asm volatile("cp.async.commit_group;")
#define CP_WAIT0()  asm volatile("cp.async.wait_group 0;")
__device__ __forceinline__ void ldsm_x4(uint32_t* r, const void* p) {
    uint32_t a = (uint32_t)__cvta_generic_to_shared(p);
    asm volatile("ldmatrix.sync.aligned.m8n8.x4.shared.b16 {%0,%1,%2,%3}, [%4];"
        : "=r"(r[0]), "=r"(r[1]), "=r"(r[2]), "=r"(r[3]) : "r"(a));
}

// ---------------- multi-chunk tf32 GEMM (128x128 tile, Kc=32, double-buffered) ----
#define TCP 136
#define ASP 36

struct GemmChunks {
    const float* w[3];
    const float* b[3];
    float*       c[3];
};

__global__ __launch_bounds__(256, 2) void sgemm_tc_kernel(
    const float* __restrict__ A, const int* __restrict__ amap,
    GemmChunks ch,
    const float* __restrict__ R, const int* __restrict__ rmap,
    int M, int N, int K, int relu)
{
    __shared__ float As[2][128][ASP];
    __shared__ float Bs[2][32][TCP];
    __shared__ int rowm[128];
    int tid = threadIdx.x;
    int ntiles = N >> 7;
    int widx = blockIdx.x / ntiles;
    int n0 = (blockIdx.x % ntiles) << 7;
    int m0 = blockIdx.y << 7;
    const float* W    = ch.w[widx];
    const float* bias = ch.b[widx];
    float*       C    = ch.c[widx];
    if (tid < 128) rowm[tid] = amap ? amap[m0 + tid] : (m0 + tid);
    __syncthreads();

    int wid = tid >> 5, lane = tid & 31;
    int warp_m = wid >> 2, warp_n = wid & 3;
    int gr = lane >> 2, gc = lane & 3;
    int lrow = lane & 15, lkq = (lane >> 4) << 2;

    int arow = tid >> 1, ak = (tid & 1) << 4;
    const float* aptr = A + (long)rowm[arow]*K + ak;
    int bk = tid >> 5, bn = (lane) << 2;
    const float* bptr = W + (long)bk*N + n0 + bn;

    float acc[4][4][4];
    #pragma unroll
    for (int i = 0; i < 4; i++)
        #pragma unroll
        for (int j = 0; j < 4; j++)
            #pragma unroll
            for (int u = 0; u < 4; u++) acc[i][j][u] = 0.0f;

    #pragma unroll
    for (int q = 0; q < 4; q++)
        cp_async16(&As[0][arow][ak + q*4], aptr + q*4);
    #pragma unroll
    for (int q = 0; q < 4; q++)
        cp_async16(&Bs[0][bk + q*8][bn], bptr + (long)(q*8)*N);
    CP_COMMIT();
    CP_WAIT0();
    __syncthreads();

    int mbase = warp_m << 6;
    int buf = 0;
    for (int k0 = 0; k0 < K; k0 += 32) {
        bool has_next = (k0 + 32) < K;
        if (has_next) {
            #pragma unroll
            for (int q = 0; q < 4; q++)
                cp_async16(&As[buf^1][arow][ak + q*4], aptr + k0 + 32 + q*4);
            #pragma unroll
            for (int q = 0; q < 4; q++)
                cp_async16(&Bs[buf^1][bk + q*8][bn], bptr + (long)(k0 + 32 + q*8)*N);
            CP_COMMIT();
        }
        uint32_t afb[2][4][4];
        #pragma unroll
        for (int mt = 0; mt < 4; mt++)
            ldsm_x4(afb[0][mt], &As[buf][mbase + (mt << 4) + lrow][lkq]);
        #pragma unroll
        for (int ks = 0; ks < 4; ks++) {
            int cur = ks & 1;
            if (ks < 3) {
                #pragma unroll
                for (int mt = 0; mt < 4; mt++)
                    ldsm_x4(afb[cur ^ 1][mt],
                            &As[buf][mbase + (mt << 4) + lrow][((ks + 1) << 3) + lkq]);
            }
            int kb = ks << 3;
            uint32_t bf[4][2];
            #pragma unroll
            for (int nt = 0; nt < 4; nt++) {
                int nb = (warp_n << 5) + (nt << 3) + gr;
                bf[nt][0] = __float_as_uint(Bs[buf][kb+gc  ][nb]);
                bf[nt][1] = __float_as_uint(Bs[buf][kb+gc+4][nb]);
            }
            #pragma unroll
            for (int mt = 0; mt < 4; mt++)
                #pragma unroll
                for (int nt = 0; nt < 4; nt++)
                    mma_tf32(acc[mt][nt], afb[cur][mt], bf[nt]);
        }
        if (has_next) CP_WAIT0();
        __syncthreads();
        buf ^= 1;
    }

    #pragma unroll
    for (int mt = 0; mt < 4; mt++) {
        #pragma unroll
        for (int half = 0; half < 2; half++) {
            int m = m0 + (warp_m << 6) + (mt << 4) + gr + (half << 3);
            long rbase = 0;
            if (R) rbase = (long)(rmap ? rmap[m] : m) * N;
            #pragma unroll
            for (int nt = 0; nt < 4; nt++) {
                int n = n0 + (warp_n << 5) + (nt << 3) + (gc << 1);
                float v0 = acc[mt][nt][half*2 + 0];
                float v1 = acc[mt][nt][half*2 + 1];
                if (bias) { v0 += bias[n]; v1 += bias[n+1]; }
                if (relu) { v0 = fmaxf(v0, 0.0f); v1 = fmaxf(v1, 0.0f); }
                if (R) {
                    float2 rv = *reinterpret_cast<const float2*>(R + rbase + n);
                    v0 += rv.x; v1 += rv.y;
                }
                *reinterpret_cast<float2*>(C + (long)m*N + n) = make_float2(v0, v1);
            }
        }
    }
}

// ---------------- tensor-core attention, Lq=64, dk=64 ----------------
__global__ __launch_bounds__(256) void attn_tc_kernel(
    const float* __restrict__ Q, const float* __restrict__ Kg,
    const float* __restrict__ Vg, float* __restrict__ O,
    int Lk, int LkPad, int q_group,
    const int* __restrict__ mask, int mask_mode, int mask_div)
{
    extern __shared__ float sm[];
    float* sQ  = sm;
    float* sKV = sm + 64*68;
    float* sS  = sKV + LkPad*68;
    int batch = blockIdx.x, h = blockIdx.y;
    int tid = threadIdx.x;
    int qbase = (batch / q_group) * 64;
    int sp = LkPad + 4;

    int wid = tid >> 5, lane = tid & 31;
    int warp_m = wid >> 2, warp_n = wid & 3;
    int gr = lane >> 2, gc = lane & 3;
    int nw  = LkPad >> 2;
    int ntn = LkPad >> 5;

    for (int c4 = tid; c4 < 64*16; c4 += 256) {
        int i = c4 >> 4, d = (c4 & 15) << 2;
        cp_async16(&sQ[i*68 + d], &Q[(long)(qbase + i)*DD + h*64 + d]);
    }
    for (int c4 = tid; c4 < Lk*16; c4 += 256) {
        int j = c4 >> 4, d = (c4 & 15) << 2;
        cp_async16(&sKV[j*68 + d], &Kg[(long)(batch*Lk + j)*DD + h*64 + d]);
    }
    CP_COMMIT();
    for (int idx = Lk*64 + tid; idx < LkPad*64; idx += 256) {
        int j = idx >> 6, d = idx & 63;
        sKV[j*68 + d] = 0.0f;
    }
    CP_WAIT0();
    __syncthreads();

    {
        float acc[2][4][4];
        #pragma unroll
        for (int mt = 0; mt < 2; mt++)
            #pragma unroll
            for (int nt = 0; nt < 4; nt++)
                #pragma unroll
                for (int u = 0; u < 4; u++) acc[mt][nt][u] = 0.0f;

        for (int kb = 0; kb < 64; kb += 8) {
            uint32_t af[2][4];
            #pragma unroll
            for (int mt = 0; mt < 2; mt++) {
                int mr = warp_m*32 + mt*16 + gr;
                af[mt][0] = __float_as_uint(sQ[mr*68 + kb+gc]);
                af[mt][1] = __float_as_uint(sQ[(mr+8)*68 + kb+gc]);
                af[mt][2] = __float_as_uint(sQ[mr*68 + kb+gc+4]);
                af[mt][3] = __float_as_uint(sQ[(mr+8)*68 + kb+gc+4]);
            }
            for (int nt = 0; nt < ntn; nt++) {
                int nc = warp_n*nw + nt*8 + gr;
                uint32_t bf[2];
                bf[0] = __float_as_uint(sKV[nc*68 + kb+gc]);
                bf[1] = __float_as_uint(sKV[nc*68 + kb+gc+4]);
                mma_tf32(acc[0][nt], af[0], bf);
                mma_tf32(acc[1][nt], af[1], bf);
            }
        }
        #pragma unroll
        for (int mt = 0; mt < 2; mt++)
            for (int nt = 0; nt < ntn; nt++) {
                int row = warp_m*32 + mt*16 + gr;
                int col = warp_n*nw + nt*8 + (gc << 1);
                sS[row*sp + col]       = acc[mt][nt][0]*0.125f;
                sS[row*sp + col + 1]   = acc[mt][nt][1]*0.125f;
                sS[(row+8)*sp + col]   = acc[mt][nt][2]*0.125f;
                sS[(row+8)*sp + col+1] = acc[mt][nt][3]*0.125f;
            }
    }
    __syncthreads();

    for (int c4 = tid; c4 < Lk*16; c4 += 256) {
        int j = c4 >> 4, d = (c4 & 15) << 2;
        cp_async16(&sKV[j*68 + d], &Vg[(long)(batch*Lk + j)*DD + h*64 + d]);
    }
    CP_COMMIT();

    for (int i = wid; i < 64; i += 8) {
        float mx = -3.4e38f;
        for (int j = lane; j < Lk; j += 32) {
            float v = sS[i*sp + j];
            bool dead = false;
            if (mask_mode == 1) dead = (mask[(long)(batch*64 + i)*Lk + j] == 0);
            else if (mask_mode == 2) dead = (mask[(batch/mask_div)*Lk + j] == 0);
            if (dead) { v = -1e9f; sS[i*sp + j] = v; }
            mx = fmaxf(mx, v);
        }
        #pragma unroll
        for (int o = 16; o; o >>= 1) mx = fmaxf(mx, __shfl_xor_sync(0xffffffffu, mx, o));
        float sum = 0.0f;
        for (int j = lane; j < Lk; j += 32) {
            float e = __expf(sS[i*sp + j] - mx);
            sS[i*sp + j] = e;
            sum += e;
        }
        #pragma unroll
        for (int o = 16; o; o >>= 1) sum += __shfl_xor_sync(0xffffffffu, sum, o);
        float inv = 1.0f / sum;
        for (int j = lane; j < Lk; j += 32) sS[i*sp + j] *= inv;
        for (int j = Lk + lane; j < LkPad; j += 32) sS[i*sp + j] = 0.0f;
    }
    CP_WAIT0();
    __syncthreads();

    {
        float acc[2][2][4];
        #pragma unroll
        for (int mt = 0; mt < 2; mt++)
            #pragma unroll
            for (int nt = 0; nt < 2; nt++)
                #pragma unroll
                for (int u = 0; u < 4; u++) acc[mt][nt][u] = 0.0f;

        for (int kb = 0; kb < LkPad; kb += 8) {
            uint32_t af[2][4];
            #pragma unroll
            for (int mt = 0; mt < 2; mt++) {
                int mr = warp_m*32 + mt*16 + gr;
                af[mt][0] = __float_as_uint(sS[mr*sp + kb+gc]);
                af[mt][1] = __float_as_uint(sS[(mr+8)*sp + kb+gc]);
                af[mt][2] = __float_as_uint(sS[mr*sp + kb+gc+4]);
                af[mt][3] = __float_as_uint(sS[(mr+8)*sp + kb+gc+4]);
            }
            #pragma unroll
            for (int nt = 0; nt < 2; nt++) {
                int nc = warp_n*16 + nt*8 + gr;
                uint32_t bf[2];
                int k0r = kb+gc, k1r = kb+gc+4;
                bf[0] = (k0r < Lk) ? __float_as_uint(sKV[k0r*68 + nc]) : 0u;
                bf[1] = (k1r < Lk) ? __float_as_uint(sKV[k1r*68 + nc]) : 0u;
                mma_tf32(acc[0][nt], af[0], bf);
                mma_tf32(acc[1][nt], af[1], bf);
            }
        }
        #pragma unroll
        for (int mt = 0; mt < 2; mt++)
            #pragma unroll
            for (int nt = 0; nt < 2; nt++) {
                int i = warp_m*32 + mt*16 + gr;
                int d = warp_n*16 + nt*8 + (gc << 1);
                long base = (long)(batch*64 + i)*DD + h*64 + d;
                *reinterpret_cast<float2*>(O + base) =
                    make_float2(acc[mt][nt][0], acc[mt][nt][1]);
                *reinterpret_cast<float2*>(O + base + 8*DD) =
                    make_float2(acc[mt][nt][2], acc[mt][nt][3]);
            }
    }
}

// ---------------- wide Lq=1 attention over RAW rows ----------------
__global__ __launch_bounds__(256) void attn_wide_kernel(
    const float* __restrict__ QT, const float* __restrict__ SRC,
    const int* __restrict__ map, float* __restrict__ SB,
    int Lk, const int* __restrict__ mask, int mask_mode, int mask_div)
{
    __shared__ float qt8[8*512];
    __shared__ float krow[8][516];
    __shared__ float sS[8][72];
    __shared__ int   rows[64];
    int q = blockIdx.x;
    int tid = threadIdx.x;
    int h = tid >> 5, lane = tid & 31;

    for (int i = tid; i < 4096; i += 256) qt8[i] = QT[(long)q*4096 + i];
    if (tid < Lk) rows[tid] = map[q*Lk + tid];
    __syncthreads();

    for (int jt = 0; jt < Lk; jt += 8) {
        int nj = min(8, Lk - jt);
        for (int idx = tid; idx < nj*512; idx += 256) {
            int j = idx >> 9, d = idx & 511;
            krow[j][d] = SRC[(long)rows[jt + j]*512 + d];
        }
        __syncthreads();
        for (int j = 0; j < nj; j++) {
            float s = 0.0f;
            #pragma unroll
            for (int i = 0; i < 16; i++)
                s += qt8[h*512 + i*32 + lane] * krow[j][i*32 + lane];
            #pragma unroll
            for (int o = 16; o; o >>= 1) s += __shfl_xor_sync(0xffffffffu, s, o);
            if (lane == 0) sS[h][jt + j] = s * 0.125f;
        }
        __syncthreads();
    }

    {
        float mx = -3.4e38f;
        for (int j = lane; j < Lk; j += 32) {
            float v = sS[h][j];
            if (mask_mode == 2 && mask[(q/mask_div)*Lk + j] == 0) { v = -1e9f; sS[h][j] = v; }
            mx = fmaxf(mx, v);
        }
        #pragma unroll
        for (int o = 16; o; o >>= 1) mx = fmaxf(mx, __shfl_xor_sync(0xffffffffu, mx, o));
        float sum = 0.0f;
        for (int j = lane; j < Lk; j += 32) {
            float e = __expf(sS[h][j] - mx);
            sS[h][j] = e;
            sum += e;
        }
        #pragma unroll
        for (int o = 16; o; o >>= 1) sum += __shfl_xor_sync(0xffffffffu, sum, o);
        float inv = 1.0f / sum;
        for (int j = lane; j < Lk; j += 32) sS[h][j] *= inv;
    }
    __syncthreads();

    float acc[16];
    #pragma unroll
    for (int i = 0; i < 16; i++) acc[i] = 0.0f;
    for (int jt = 0; jt < Lk; jt += 8) {
        int nj = min(8, Lk - jt);
        for (int idx = tid; idx < nj*512; idx += 256) {
            int j = idx >> 9, d = idx & 511;
            krow[j][d] = SRC[(long)rows[jt + j]*512 + d];
        }
        __syncthreads();
        for (int j = 0; j < nj; j++) {
            float p = sS[h][jt + j];
            #pragma unroll
            for (int i = 0; i < 16; i++)
                acc[i] += p * krow[j][i*32 + lane];
        }
        __syncthreads();
    }
    #pragma unroll
    for (int i = 0; i < 16; i++)
        SB[(long)q*4096 + h*512 + i*32 + lane] = acc[i];
}

// ---------------- elementwise add ----------------
__global__ void add_kernel(const float* __restrict__ a, const float* __restrict__ b,
                           float* __restrict__ c, int n) {
    int i = blockIdx.x*256 + threadIdx.x;
    if (i < n) c[i] = a[i] + b[i];
}

// ---------------- host ----------------
static float* sym_f(const void* s) { void* p = nullptr; cudaGetSymbolAddress(&p, s); return (float*)p; }
static int*   sym_i(const void* s) { void* p = nullptr; cudaGetSymbolAddress(&p, s); return (int*)p; }

extern "C" void kernel_launch(void* const* d_in, const int* in_sizes, int n_in,
                              void* d_out, int out_size) {
    const float* x    = (const float*)d_in[0];
    const float* vft  = (const float*)d_in[1];
    const float* his  = (const float*)d_in[2];
    const float* cap  = (const float*)d_in[3];
    const float* qry  = (const float*)d_in[4];
    const int* trg_m  = (const int*)d_in[5];
    const int* his_m  = (const int*)d_in[6];
    const int* cap_m  = (const int*)d_in[7];
    const int* qry_m  = (const int*)d_in[8];
    const int* tmp_m  = (const int*)d_in[9];
    const float* attw = (const float*)d_in[10];
    const float* attb = (const float*)d_in[11];
    const float* ffw1 = (const float*)d_in[12];
    const float* ffb1 = (const float*)d_in[13];
    const float* ffw2 = (const float*)d_in[14];
    const float* ffb2 = (const float*)d_in[15];
    const float* lng  = (const float*)d_in[16];
    const float* lnb  = (const float*)d_in[17];
    float* out = (float*)d_out;

    float* cur   = sym_f(g_cur);
    float* lnA   = sym_f(g_lnA);
    float* lnB   = sym_f(g_lnB);
    float* lnC   = sym_f(g_lnC);
    float* qA    = sym_f(g_qA);
    float* qB    = sym_f(g_qB);
    float* ks    = sym_f(g_ks);
    float* vs    = sym_f(g_vs);
    float* abA   = sym_f(g_abA);
    float* abB   = sym_f(g_abB);
    float* ts    = sym_f(g_ts);
    float* st    = sym_f(g_st);
    float* ffhA  = sym_f(g_ffhA);
    float* ffhB  = sym_f(g_ffhB);
    float* big0  = sym_f(g_big0);
    float* big1  = sym_f(g_big1);
    float* big2  = sym_f(g_big2);
    float* big3  = sym_f(g_big3);
    float* big4  = sym_f(g_big4);
    float* big5  = sym_f(g_big5);
    float* big6  = sym_f(g_big6);
    float* big7  = sym_f(g_big7);
    int* map_perm = sym_i(g_map_perm);
    int* map_pt   = sym_i(g_map_pt);
    int* map_ps   = sym_i(g_map_ps);

    // chain scratch layout inside big3 (A) / big7 (B)
    const long OFF_BWK = 0;
    const long OFF_BWV = 2*1024*1024;
    const long OFF_QT  = 4*1024*1024;
    const long OFF_SB  = 8*1024*1024;
    const long OFF_U2  = 12*1024*1024;
    const long OFF_PK  = 13*1024*1024;
    const long OFF_PV  = OFF_PK + 512*512;
    const long OFF_BV  = OFF_PV + 512*512;
    // mha1-3 KV buffers in big2 tail (head 25.7M used later by ao_A)
    const long OFF_KV  = 26L*1024*1024;  // 6 x 1M floats

    static cudaStream_t sA = nullptr, sB = nullptr, sC = nullptr;
    static cudaEvent_t eStart, eMaps, eVft, eCur, eC, eB, eEnd, eQKV0, eKV123;
    if (!sA) {
        cudaStreamCreateWithFlags(&sA, cudaStreamNonBlocking);
        cudaStreamCreateWithFlags(&sB, cudaStreamNonBlocking);
        cudaStreamCreateWithFlags(&sC, cudaStreamNonBlocking);
        cudaEventCreateWithFlags(&eStart, cudaEventDisableTiming);
        cudaEventCreateWithFlags(&eMaps,  cudaEventDisableTiming);
        cudaEventCreateWithFlags(&eVft,   cudaEventDisableTiming);
        cudaEventCreateWithFlags(&eCur,   cudaEventDisableTiming);
        cudaEventCreateWithFlags(&eC,     cudaEventDisableTiming);
        cudaEventCreateWithFlags(&eB,     cudaEventDisableTiming);
        cudaEventCreateWithFlags(&eEnd,   cudaEventDisableTiming);
        cudaEventCreateWithFlags(&eQKV0,  cudaEventDisableTiming);
        cudaEventCreateWithFlags(&eKV123, cudaEventDisableTiming);
    }

    cudaFuncSetAttribute((const void*)attn_tc_kernel,
                         cudaFuncAttributeMaxDynamicSharedMemorySize, 120*1024);

    #define AW(i,j) (attw + ((i)*4+(j))*DD*DD)
    #define ABI(i,j) (attb + ((i)*4+(j))*DD)

    auto gemmN = [](cudaStream_t st_, const float* A, const int* amap, int nch,
                    const float* w0, const float* b0, float* c0,
                    const float* w1, const float* b1, float* c1,
                    const float* R, const int* rmap,
                    int M, int N, int K, int relu) {
        GemmChunks ch;
        ch.w[0] = w0; ch.b[0] = b0; ch.c[0] = c0;
        ch.w[1] = w1; ch.b[1] = b1; ch.c[1] = c1;
        ch.w[2] = nullptr; ch.b[2] = nullptr; ch.c[2] = nullptr;
        dim3 grid(nch * (N/128), M/128);
        sgemm_tc_kernel<<<grid, 256, 0, st_>>>(A, amap, ch, R, rmap, M, N, K, relu);
    };
    auto gemm3 = [](cudaStream_t st_, const float* A,
                    const float* w0, const float* b0, float* c0,
                    const float* w1, const float* b1, float* c1,
                    const float* w2, const float* b2, float* c2,
                    int M, int N, int K) {
        GemmChunks ch;
        ch.w[0] = w0; ch.b[0] = b0; ch.c[0] = c0;
        ch.w[1] = w1; ch.b[1] = b1; ch.c[1] = c1;
        ch.w[2] = w2; ch.b[2] = b2; ch.c[2] = c2;
        dim3 grid(3 * (N/128), M/128);
        sgemm_tc_kernel<<<grid, 256, 0, st_>>>(A, nullptr, ch, nullptr, nullptr, M, N, K, 0);
    };
    auto gemm = [&](cudaStream_t st_, const float* A, const int* amap,
                    const float* W, const float* bias,
                    const float* R, const int* rmap, float* C,
                    int M, int N, int K, int relu) {
        gemmN(st_, A, amap, 1, W, bias, C, nullptr, nullptr, nullptr, R, rmap, M, N, K, relu);
    };
    auto attn = [](cudaStream_t st_, const float* Q, const float* K, const float* V, float* O,
                   int NB, int Lk, int qg, const int* mask, int mode, int mdiv) {
        int LkPad = (Lk + 31) & ~31;
        size_t sh = (size_t)(64*68 + LkPad*68 + 64*(LkPad+4)) * sizeof(float);
        attn_tc_kernel<<<dim3(NB, HH), 256, sh, st_>>>(Q, K, V, O, Lk, LkPad, qg, mask, mode, mdiv);
    };
    auto ln = [&](cudaStream_t st_, const float* in, int li, float* o, int rows) {
        ln_kernel<<<rows, 128, 0, st_>>>(in, lng + li*DD, lnb + li*DD, o);
    };

    // ---- fork ----
    cudaEventRecord(eStart, 0);
    cudaStreamWaitEvent(sA, eStart, 0);
    cudaStreamWaitEvent(sB, eStart, 0);
    cudaStreamWaitEvent(sC, eStart, 0);

    // sC phase 1: mha0 LN+QKV (input-only)
    ln(sC, x, 0, lnC, NTOK_X);
    gemm3(sC, lnC, AW(0,0), ABI(0,0), qA, AW(0,1), ABI(0,1), ks, AW(0,2), ABI(0,2), vs,
          NTOK_X, DD, DD);
    cudaEventRecord(eQKV0, sC);
    // sC phase 2: mha1-3 K/V pairs (input-only)
    {
        const float* kvsrc[3] = { his, cap, qry };
        const int    kvrows[3] = { BB*128, BB*64, BB*32 };
        for (int a = 0; a < 3; a++) {
            gemmN(sC, kvsrc[a], nullptr, 2,
                  AW(a+1,1), ABI(a+1,1), big2 + OFF_KV + (2*a)*1024*1024,
                  AW(a+1,2), ABI(a+1,2), big2 + OFF_KV + (2*a+1)*1024*1024,
                  nullptr, nullptr, kvrows[a], DD, DD, 0);
        }
        cudaEventRecord(eKV123, sC);
    }
    // sC phase 3: weight-only prep for factored mha5/mha7
    {
        gemmN(sC, AW(4,3), nullptr, 2, AW(5,1), nullptr, big3 + OFF_PK,
              AW(5,2), nullptr, big3 + OFF_PV, nullptr, nullptr, DD, DD, DD, 0);
        gemmN(sC, AW(6,3), nullptr, 2, AW(7,1), nullptr, big7 + OFF_PK,
              AW(7,2), nullptr, big7 + OFF_PV, nullptr, nullptr, DD, DD, DD, 0);
        bias_compose_kernel<<<64, 256, 0, sC>>>(ABI(4,3), AW(5,2), ABI(5,2), big3 + OFF_BV);
        bias_compose_kernel<<<64, 256, 0, sC>>>(ABI(6,3), AW(7,2), ABI(7,2), big7 + OFF_BV);
        build_bwk_kernel<<<(512*4096+255)/256, 256, 0, sC>>>(big3 + OFF_PK, big3 + OFF_BWK);
        build_bwv_kernel<<<(4096*512+255)/256, 256, 0, sC>>>(big3 + OFF_PV, big3 + OFF_BWV);
        build_bwk_kernel<<<(512*4096+255)/256, 256, 0, sC>>>(big7 + OFF_PK, big7 + OFF_BWK);
        build_bwv_kernel<<<(4096*512+255)/256, 256, 0, sC>>>(big7 + OFF_PV, big7 + OFF_BWV);
        cudaEventRecord(eC, sC);
    }

    // sA: maps
    build_maps_kernel<<<dim3(256, 3), 256, 0, sA>>>();
    cudaEventRecord(eMaps, sA);

    // sB: big vft projections (overlapped with sA chain)
    cudaStreamWaitEvent(sB, eMaps, 0);
    gemmN(sB, vft, map_perm, 2, AW(4,1), ABI(4,1), big0, AW(4,2), ABI(4,2), big1,
          nullptr, nullptr, NTOK_VFT, DD, DD, 0);
    gemmN(sB, vft, nullptr, 2, AW(6,1), ABI(6,1), big4, AW(6,2), ABI(6,2), big5,
          nullptr, nullptr, NTOK_VFT, DD, DD, 0);
    cudaEventRecord(eVft, sB);

    // sA: mha0 (QKV precomputed on sC)
    cudaStreamWaitEvent(sA, eQKV0, 0);
    attn(sA, qA, ks, vs, abA, BB, TTRG, 1, trg_m, 1, 1);
    gemm(sA, abA, nullptr, AW(0,3), ABI(0,3), x, nullptr, cur, NTOK_X, DD, DD, 0);

    // sA: mha1..3 (KV precomputed on sC)
    cudaStreamWaitEvent(sA, eKV123, 0);
    {
        const int  Lks[3]   = { 128, 64, 32 };
        const int* masks[3] = { his_m, cap_m, qry_m };
        for (int a = 0; a < 3; a++) {
            int wi = a + 1;
            ln(sA, cur, wi, lnA, NTOK_X);
            gemm(sA, lnA, nullptr, AW(wi,0), ABI(wi,0), nullptr, nullptr, qA, NTOK_X, DD, DD, 0);
            attn(sA, qA, big2 + OFF_KV + (2*a)*1024*1024, big2 + OFF_KV + (2*a+1)*1024*1024,
                 abA, BB, Lks[a], 1, masks[a], 2, 1);
            gemm(sA, abA, nullptr, AW(wi,3), ABI(wi,3), cur, nullptr, cur, NTOK_X, DD, DD, 0);
        }
    }
    cudaEventRecord(eCur, sA);

    // ================= chain A (sA): mha4 attn -> factored mha5 -> ffn0 =================
    ln(sA, cur, 4, lnA, NTOK_X);
    gemm(sA, lnA, nullptr, AW(4,0), ABI(4,0), nullptr, nullptr, qA, NTOK_X, DD, DD, 0);
    cudaStreamWaitEvent(sA, eVft, 0);
    attn(sA, qA, big0, big1, big2, BB*SS, TT, SS, tmp_m, 2, SS);   // ao_A in big2 head
    ln(sA, cur, 5, lnA, NTOK_X);
    gemm(sA, lnA, nullptr, AW(5,0), ABI(5,0), nullptr, nullptr, qA, NTOK_X, DD, DD, 0);
    cudaStreamWaitEvent(sA, eC, 0);
    gemm(sA, cur, nullptr, AW(5,2), big3 + OFF_BV, nullptr, nullptr, big3 + OFF_U2,
         NTOK_X, DD, DD, 0);
    gemm(sA, qA, nullptr, big3 + OFF_BWK, nullptr, nullptr, nullptr, big3 + OFF_QT,
         NTOK_X, 4096, DD, 0);
    attn_wide_kernel<<<NTOK_X, 256, 0, sA>>>(big3 + OFF_QT, big2, map_pt, big3 + OFF_SB,
                                             SS, nullptr, 0, 1);
    gemm(sA, big3 + OFF_SB, nullptr, big3 + OFF_BWV, nullptr, big3 + OFF_U2, nullptr,
         abA, NTOK_X, DD, 4096, 0);
    gemm(sA, abA, nullptr, AW(5,3), ABI(5,3), cur, nullptr, ts, NTOK_X, DD, DD, 0);
    ln(sA, ts, 6, lnA, NTOK_X);
    gemm(sA, lnA, nullptr, ffw1 + 0*DD*DFF, ffb1 + 0*DFF, nullptr, nullptr, ffhA, NTOK_X, DFF, DD, 1);
    gemm(sA, ffhA, nullptr, ffw2 + 0*DFF*DD, ffb2 + 0*DD, ts, nullptr, ts, NTOK_X, DD, DFF, 0);

    // ================= chain B (sB): mha6 attn -> factored mha7 -> ffn1 =================
    cudaStreamWaitEvent(sB, eCur, 0);
    ln(sB, cur, 7, lnB, NTOK_X);
    gemm(sB, lnB, nullptr, AW(6,0), ABI(6,0), nullptr, nullptr, qB, NTOK_X, DD, DD, 0);
    attn(sB, qB, big4, big5, big6, BB*TT, SS, TT, nullptr, 0, 1);
    ln(sB, cur, 8, lnB, NTOK_X);
    gemm(sB, lnB, nullptr, AW(7,0), ABI(7,0), nullptr, nullptr, qB, NTOK_X, DD, DD, 0);
    cudaStreamWaitEvent(sB, eC, 0);
    gemm(sB, cur, nullptr, AW(7,2), big7 + OFF_BV, nullptr, nullptr, big7 + OFF_U2,
         NTOK_X, DD, DD, 0);
    gemm(sB, qB, nullptr, big7 + OFF_BWK, nullptr, nullptr, nullptr, big7 + OFF_QT,
         NTOK_X, 4096, DD, 0);
    attn_wide_kernel<<<NTOK_X, 256, 0, sB>>>(big7 + OFF_QT, big6, map_ps, big7 + OFF_SB,
                                             TT, tmp_m, 2, TTRG);
    gemm(sB, big7 + OFF_SB, nullptr, big7 + OFF_BWV, nullptr, big7 + OFF_U2, nullptr,
         abB, NTOK_X, DD, 4096, 0);
    gemm(sB, abB, nullptr, AW(7,3), ABI(7,3), cur, nullptr, st, NTOK_X, DD, DD, 0);
    ln(sB, st, 9, lnB, NTOK_X);
    gemm(sB, lnB, nullptr, ffw1 + 1*DD*DFF, ffb1 + 1*DFF, nullptr, nullptr, ffhB, NTOK_X, DFF, DD, 1);
    gemm(sB, ffhB, nullptr, ffw2 + 1*DFF*DD, ffb2 + 1*DD, st, nullptr, st, NTOK_X, DD, DFF, 0);
    cudaEventRecord(eB, sB);

    // ---- join on sA ----
    cudaStreamWaitEvent(sA, eB, 0);
    add_kernel<<<(NTOK_X*DD + 255)/256, 256, 0, sA>>>(ts, st, cur, NTOK_X*DD);
    ln(sA, cur, 10, lnA, NTOK_X);
    gemm(sA, lnA, nullptr, ffw1 + 2*DD*DFF, ffb1 + 2*DFF, nullptr, nullptr, ffhA, NTOK_X, DFF, DD, 1);
    gemm(sA, ffhA, nullptr, ffw2 + 2*DFF*DD, ffb2 + 2*DD, cur, nullptr, out, NTOK_X, DD, DFF, 0);

    cudaEventRecord(eEnd, sA);
    cudaStreamWaitEvent(0, eEnd, 0);

    #undef AW
    #undef ABI
}